// round 1
// baseline (speedup 1.0000x reference)
#include <cuda_runtime.h>

// ----------------------------------------------------------------------------
// TransMIL forward pass, fp32 SIMT baseline.
// Model constants (fixed by the problem):
//   N_TOK=8192, IN_DIM=1024, D=512, HEADS=8, DH=64, M=256, ITERS=6, KRES=33
//   Hs=Ws=91, NPIX=8281, tokens after cls = 8282, Nystrom pad=166, Np=8448, l=33
// ----------------------------------------------------------------------------

#define NP      8448
#define NTOK    8282
#define NPIX    8281
#define HSIZE   91
#define PADR    166
#define DIM     512
#define HEADS   8
#define DH      64
#define MLM     256
#define LCH     33
#define SCALE_Q 0.125f
#define EPSLN   1e-5f

// ---------------- scratch layout (single __device__ array) ------------------
constexpr long long SZ_H    = (long long)NTOK * DIM;        // 4,240,384
constexpr long long SZ_QKV  = (long long)NP * 3 * DIM;      // 12,976,128
constexpr long long SZ_S    = (long long)HEADS * NP * MLM;  // 17,301,504
constexpr long long SZ_A2   = (long long)HEADS * MLM * MLM; // 524,288
constexpr long long SZ_LM   = (long long)HEADS * MLM * DH;  // 131,072
constexpr long long SZ_ATTN = (long long)NP * DIM;          // 4,325,376

constexpr long long OFF_HA   = 0;
constexpr long long OFF_H2   = OFF_HA  + SZ_H;
constexpr long long OFF_XLN  = OFF_H2  + SZ_H;
constexpr long long OFF_QKV  = OFF_XLN + SZ_H;
constexpr long long OFF_S1   = OFF_QKV + SZ_QKV;
constexpr long long OFF_S3   = OFF_S1  + SZ_S;
constexpr long long OFF_A2   = OFF_S3  + SZ_S;
constexpr long long OFF_Z    = OFF_A2  + SZ_A2;
constexpr long long OFF_XZ   = OFF_Z   + SZ_A2;
constexpr long long OFF_T    = OFF_XZ  + SZ_A2;
constexpr long long OFF_P    = OFF_T   + SZ_A2;
constexpr long long OFF_QL   = OFF_P   + SZ_A2;
constexpr long long OFF_KL   = OFF_QL  + SZ_LM;
constexpr long long OFF_A3V  = OFF_KL  + SZ_LM;
constexpr long long OFF_W2   = OFF_A3V + SZ_LM;
constexpr long long OFF_ATTN = OFF_W2  + SZ_LM;
constexpr long long SCRATCH_TOTAL = OFF_ATTN + SZ_ATTN;

__device__ float g_scratch[SCRATCH_TOTAL];

// ---------------- generic tiled SGEMM -----------------------------------
// C[M,N] = act(alpha * A_eff @ B + bias + res)
//   A_eff row i = (i < zrows) ? 0 : A[i - zrows]   (front zero-padding)
//   flags: 1 = relu, 2 = transB (B is [N,K] row-major)
//   batch via blockIdx.z with strides sA/sB/sC.
template<int BM, int BN, int BK, int TM, int TN>
__global__ void gemm_k(const float* __restrict__ A, const float* __restrict__ B,
                       float* __restrict__ C,
                       int Mr, int N, int K,
                       int lda, int ldb, int ldc,
                       long long sA, long long sB, long long sC,
                       float alpha,
                       const float* __restrict__ bias,
                       const float* __restrict__ res, int ldres,
                       int zrows, int flags)
{
    constexpr int TX = BN / TN;
    constexpr int TY = BM / TM;
    constexpr int THREADS = TX * TY;   // 256 for both instantiations
    __shared__ float As[BK][BM + 4];
    __shared__ float Bs[BK][BN + 4];

    int bz = blockIdx.z;
    A += bz * sA; B += bz * sB; C += bz * sC;

    int tid = threadIdx.x;
    int tx = tid % TX, ty = tid / TX;
    int rowBase = blockIdx.y * BM;
    int colBase = blockIdx.x * BN;

    float acc[TM][TN];
#pragma unroll
    for (int i = 0; i < TM; i++)
#pragma unroll
        for (int j = 0; j < TN; j++) acc[i][j] = 0.f;

    for (int k0 = 0; k0 < K; k0 += BK) {
        // A tile (BM x BK)
        for (int i = tid; i < BM * BK; i += THREADS) {
            int m = i / BK, kk = i % BK;
            int gm = rowBase + m, gk = k0 + kk;
            float v = 0.f;
            if (gm < Mr && gk < K) {
                int am = gm - zrows;
                if (am >= 0) v = A[(long long)am * lda + gk];
            }
            As[kk][m] = v;
        }
        // B tile (BK x BN)
        if (flags & 2) {
            for (int i = tid; i < BK * BN; i += THREADS) {
                int n = i / BK, kk = i % BK;
                int gk = k0 + kk, gn = colBase + n;
                float v = 0.f;
                if (gk < K && gn < N) v = B[(long long)gn * ldb + gk];
                Bs[kk][n] = v;
            }
        } else {
            for (int i = tid; i < BK * BN; i += THREADS) {
                int kk = i / BN, n = i % BN;
                int gk = k0 + kk, gn = colBase + n;
                float v = 0.f;
                if (gk < K && gn < N) v = B[(long long)gk * ldb + gn];
                Bs[kk][n] = v;
            }
        }
        __syncthreads();
#pragma unroll
        for (int kk = 0; kk < BK; kk++) {
            float a[TM], bb[TN];
#pragma unroll
            for (int i = 0; i < TM; i++) a[i] = As[kk][ty * TM + i];
#pragma unroll
            for (int j = 0; j < TN; j++) bb[j] = Bs[kk][tx * TN + j];
#pragma unroll
            for (int i = 0; i < TM; i++)
#pragma unroll
                for (int j = 0; j < TN; j++) acc[i][j] += a[i] * bb[j];
        }
        __syncthreads();
    }

#pragma unroll
    for (int i = 0; i < TM; i++) {
        int gm = rowBase + ty * TM + i;
        if (gm >= Mr) continue;
#pragma unroll
        for (int j = 0; j < TN; j++) {
            int gn = colBase + tx * TN + j;
            if (gn >= N) continue;
            float v = acc[i][j] * alpha;
            if (bias) v += bias[gn];
            if (res)  v += res[(long long)gm * ldres + gn];
            if (flags & 1) v = fmaxf(v, 0.f);
            C[(long long)gm * ldc + gn] = v;
        }
    }
}

// ---------------- small kernels ------------------------------------------

// row-wise softmax in place; grid.x = rows, grid.y = batch
__global__ void softmax_k(float* __restrict__ S, int cols, int ld, long long bstride)
{
    float* row = S + (long long)blockIdx.y * bstride + (long long)blockIdx.x * ld;
    __shared__ float sm[256];
    int t = threadIdx.x;
    float m = -1e30f;
    for (int c = t; c < cols; c += 256) m = fmaxf(m, row[c]);
    sm[t] = m; __syncthreads();
    for (int s = 128; s > 0; s >>= 1) { if (t < s) sm[t] = fmaxf(sm[t], sm[t + s]); __syncthreads(); }
    m = sm[0]; __syncthreads();
    float sum = 0.f;
    for (int c = t; c < cols; c += 256) { float e = expf(row[c] - m); row[c] = e; sum += e; }
    sm[t] = sum; __syncthreads();
    for (int s = 128; s > 0; s >>= 1) { if (t < s) sm[t] += sm[t + s]; __syncthreads(); }
    float inv = 1.f / sm[0]; __syncthreads();
    for (int c = t; c < cols; c += 256) row[c] *= inv;
}

// LayerNorm over 512 cols; grid.x = rows; 256 threads
__global__ void ln_k(const float* __restrict__ x, float* __restrict__ y,
                     const float* __restrict__ g, const float* __restrict__ b)
{
    long long row = blockIdx.x;
    const float* xr = x + row * DIM;
    float* yr = y + row * DIM;
    int t = threadIdx.x;
    float v0 = xr[t], v1 = xr[t + 256];
    __shared__ float sm[256];
    sm[t] = v0 + v1; __syncthreads();
    for (int s = 128; s > 0; s >>= 1) { if (t < s) sm[t] += sm[t + s]; __syncthreads(); }
    float mu = sm[0] * (1.f / DIM); __syncthreads();
    float d0 = v0 - mu, d1 = v1 - mu;
    sm[t] = d0 * d0 + d1 * d1; __syncthreads();
    for (int s = 128; s > 0; s >>= 1) { if (t < s) sm[t] += sm[t + s]; __syncthreads(); }
    float rs = rsqrtf(sm[0] * (1.f / DIM) + EPSLN); __syncthreads();
    yr[t]       = d0 * rs * g[t]       + b[t];
    yr[t + 256] = d1 * rs * g[t + 256] + b[t + 256];
}

// scale q columns (cols 0..511 of qkv) by SCALE_Q
__global__ void scaleq_k(float* __restrict__ qkv)
{
    int idx = blockIdx.x * 256 + threadIdx.x;       // NP*DIM total
    int i = idx >> 9, c = idx & 511;
    qkv[(long long)i * (3 * DIM) + c] *= SCALE_Q;
}

// landmark means: grid (512, 2): y==0 -> q_l (from already-scaled q), y==1 -> k_l
__global__ void landmark_k(const float* __restrict__ qkv,
                           float* __restrict__ ql, float* __restrict__ kl)
{
    int idx = blockIdx.x * 256 + threadIdx.x;       // 0 .. HEADS*MLM*DH-1
    int d = idx & 63, m = (idx >> 6) & 255, h = idx >> 14;
    int off = (blockIdx.y == 0) ? 0 : DIM;
    float s = 0.f;
    const float* src = qkv + off + h * DH + d;
#pragma unroll
    for (int j = 0; j < LCH; j++)
        s += src[(long long)(m * LCH + j) * (3 * DIM)];
    float* dst = (blockIdx.y == 0) ? ql : kl;
    dst[h * (MLM * DH) + m * DH + d] = s * (1.f / LCH);
}

// pinv init: per-head Z = a2^T / (max|rowsum| * max|colsum|); one block per head
__global__ void pinv_init_k(const float* __restrict__ A2, float* __restrict__ Z)
{
    int h = blockIdx.x;
    const float* A = A2 + (long long)h * MLM * MLM;
    float* Zh = Z + (long long)h * MLM * MLM;
    int t = threadIdx.x;   // 256
    float rs = 0.f, cs = 0.f;
    for (int j = 0; j < MLM; j++) {
        rs += fabsf(A[t * MLM + j]);
        cs += fabsf(A[j * MLM + t]);
    }
    __shared__ float s1[256], s2[256];
    s1[t] = rs; s2[t] = cs; __syncthreads();
    for (int s = 128; s > 0; s >>= 1) {
        if (t < s) { s1[t] = fmaxf(s1[t], s1[t + s]); s2[t] = fmaxf(s2[t], s2[t + s]); }
        __syncthreads();
    }
    float scale = 1.f / (s1[0] * s2[0]);
    __syncthreads();
    for (int j = 0; j < MLM; j++)
        Zh[t * MLM + j] = A[j * MLM + t] * scale;
}

// T = d*I - P  (batched over heads, elementwise)
__global__ void dimin_k(const float* __restrict__ P, float* __restrict__ T, float d)
{
    int idx = blockIdx.x * 256 + threadIdx.x;       // HEADS*MLM*MLM total
    int rc = idx & (MLM * MLM - 1);
    int r = rc >> 8, c = rc & 255;
    T[idx] = ((r == c) ? d : 0.f) - P[idx];
}

// depthwise conv along sequence (KRES=33, pad 16), accumulate into attn buffer
__global__ void conv1d_add_k(float* __restrict__ attn, const float* __restrict__ qkv,
                             const float* __restrict__ w)
{
    int idx = blockIdx.x * 256 + threadIdx.x;       // NP*DIM
    int i = idx >> 9, c = idx & 511, h = c >> 6;
    float acc = 0.f;
#pragma unroll
    for (int t = 0; t < 33; t++) {
        int j = i + t - 16;
        if (j >= 0 && j < NP)
            acc += w[h * 33 + t] * qkv[(long long)j * (3 * DIM) + 2 * DIM + c];
    }
    attn[idx] += acc;
}

// seed: row0 = cls token; wrap rows 8193..8281 = rows 1..89 (post-fc1)
__global__ void seed_k(float* __restrict__ hA, const float* __restrict__ cls)
{
    int idx = blockIdx.x * 256 + threadIdx.x;
    if (idx < DIM) hA[idx] = cls[idx];
    int j = idx - DIM;
    if (j >= 0 && j < 89 * DIM) {
        int r = j >> 9, c = j & 511;
        hA[(long long)(1 + 8192 + r) * DIM + c] = hA[(long long)(1 + r) * DIM + c];
    }
}

// PPEG: y = f + dw7 + dw5 + dw3 (+biases), depthwise on 91x91 grid
__global__ void ppeg_k(const float* __restrict__ hA, float* __restrict__ h2,
                       const float* __restrict__ w7, const float* __restrict__ b7,
                       const float* __restrict__ w5, const float* __restrict__ b5,
                       const float* __restrict__ w3, const float* __restrict__ b3)
{
    int idx = blockIdx.x * 256 + threadIdx.x;
    if (idx >= NPIX * DIM) return;
    int tok = idx >> 9, ch = idx & 511;
    int r = tok / HSIZE, cc = tok % HSIZE;
    float acc = hA[(long long)(1 + tok) * DIM + ch] + b7[ch] + b5[ch] + b3[ch];
#pragma unroll
    for (int u = -3; u <= 3; u++) {
        int rr = r + u;
        if (rr < 0 || rr >= HSIZE) continue;
#pragma unroll
        for (int v = -3; v <= 3; v++) {
            int c2 = cc + v;
            if (c2 < 0 || c2 >= HSIZE) continue;
            float f = hA[(long long)(1 + rr * HSIZE + c2) * DIM + ch];
            float w = w7[ch * 49 + (u + 3) * 7 + (v + 3)];
            if (u >= -2 && u <= 2 && v >= -2 && v <= 2)
                w += w5[ch * 25 + (u + 2) * 5 + (v + 2)];
            if (u >= -1 && u <= 1 && v >= -1 && v <= 1)
                w += w3[ch * 9 + (u + 1) * 3 + (v + 1)];
            acc += w * f;
        }
    }
    h2[(long long)(1 + tok) * DIM + ch] = acc;
}

__global__ void copy_row0_k(float* __restrict__ h2, const float* __restrict__ hA)
{
    int t = threadIdx.x;
    h2[t] = hA[t];
}

// final: LN(row0) -> emb; logits = emb@fc2_w + b; softmax; argmax
// out layout: [logit0, logit1, p0, p1, yhat, emb(512)]
__global__ void final_k(const float* __restrict__ h, const float* __restrict__ g,
                        const float* __restrict__ b, const float* __restrict__ w,
                        const float* __restrict__ bias, float* __restrict__ out,
                        int out_size)
{
    int t = threadIdx.x;   // 512
    __shared__ float sm[512];
    float v = h[t];
    sm[t] = v; __syncthreads();
    for (int s = 256; s > 0; s >>= 1) { if (t < s) sm[t] += sm[t + s]; __syncthreads(); }
    float mu = sm[0] * (1.f / DIM); __syncthreads();
    float d = v - mu;
    sm[t] = d * d; __syncthreads();
    for (int s = 256; s > 0; s >>= 1) { if (t < s) sm[t] += sm[t + s]; __syncthreads(); }
    float rs = rsqrtf(sm[0] * (1.f / DIM) + EPSLN); __syncthreads();
    float e = d * rs * g[t] + b[t];
    if (5 + t < out_size) out[5 + t] = e;
    sm[t] = e * w[t * 2]; __syncthreads();
    for (int s = 256; s > 0; s >>= 1) { if (t < s) sm[t] += sm[t + s]; __syncthreads(); }
    float l0 = sm[0] + bias[0]; __syncthreads();
    sm[t] = e * w[t * 2 + 1]; __syncthreads();
    for (int s = 256; s > 0; s >>= 1) { if (t < s) sm[t] += sm[t + s]; __syncthreads(); }
    float l1 = sm[0] + bias[1]; __syncthreads();
    if (t == 0 && out_size >= 5) {
        out[0] = l0; out[1] = l1;
        float mx = fmaxf(l0, l1);
        float e0 = expf(l0 - mx), e1 = expf(l1 - mx);
        float s = e0 + e1;
        out[2] = e0 / s; out[3] = e1 / s;
        out[4] = (l1 > l0) ? 1.f : 0.f;
    }
}

// ---------------- host orchestration ----------------------------------------

static void launch_big(const float* A, const float* B, float* C,
                       int M, int N, int K, int lda, int ldb, int ldc,
                       long long sA, long long sB, long long sC, int batch,
                       float alpha, const float* bias, const float* res, int ldres,
                       int zrows, int flags)
{
    dim3 grid((N + 127) / 128, (M + 127) / 128, batch);
    gemm_k<128, 128, 8, 8, 8><<<grid, 256>>>(A, B, C, M, N, K, lda, ldb, ldc,
                                             sA, sB, sC, alpha, bias, res, ldres, zrows, flags);
}

static void launch_small(const float* A, const float* B, float* C,
                         int M, int N, int K, int lda, int ldb, int ldc,
                         long long sA, long long sB, long long sC, int batch,
                         float alpha, const float* bias, const float* res, int ldres,
                         int zrows, int flags)
{
    dim3 grid((N + 63) / 64, (M + 63) / 64, batch);
    gemm_k<64, 64, 16, 4, 4><<<grid, 256>>>(A, B, C, M, N, K, lda, ldb, ldc,
                                            sA, sB, sC, alpha, bias, res, ldres, zrows, flags);
}

static void run_attn_layer(float* base, float* hbuf,
                           const float* lng, const float* lnb,
                           const float* qkvw, const float* outw, const float* outb,
                           const float* convw)
{
    float* xln  = base + OFF_XLN;
    float* qkv  = base + OFF_QKV;
    float* S1   = base + OFF_S1;
    float* S3   = base + OFF_S3;
    float* a2   = base + OFF_A2;
    float* Zb   = base + OFF_Z;
    float* XZ   = base + OFF_XZ;
    float* Tb   = base + OFF_T;
    float* Pb   = base + OFF_P;
    float* ql   = base + OFF_QL;
    float* kl   = base + OFF_KL;
    float* a3v  = base + OFF_A3V;
    float* W2   = base + OFF_W2;
    float* attn = base + OFF_ATTN;

    const long long sS  = (long long)NP * MLM;        // 2,162,688
    const long long sA2 = (long long)MLM * MLM;       // 65,536
    const long long sLM = (long long)MLM * DH;        // 16,384

    // 1. LayerNorm
    ln_k<<<NTOK, 256>>>(hbuf, xln, lng, lnb);

    // 2. qkv = pad(xln) @ qkv_w   (front-zero rows folded via zrows)
    launch_big(xln, qkvw, qkv, NP, 3 * DIM, DIM, DIM, 3 * DIM, 3 * DIM,
               0, 0, 0, 1, 1.f, nullptr, nullptr, 0, PADR, 0);

    // 3. scale q, 4. landmarks
    scaleq_k<<<(NP * DIM) / 256, 256>>>(qkv);
    landmark_k<<<dim3(512, 2), 256>>>(qkv, ql, kl);

    // 5. S1 = q @ k_l^T  (per head), softmax
    launch_big(qkv, kl, S1, NP, MLM, DH, 3 * DIM, DH, MLM,
               DH, sLM, sS, HEADS, 1.f, nullptr, nullptr, 0, 0, 2);
    softmax_k<<<dim3(NP, HEADS), 256>>>(S1, MLM, MLM, sS);

    // 6. S3 = q_l @ k^T  (per head), softmax over 8448
    launch_big(ql, qkv + DIM, S3, MLM, NP, DH, DH, 3 * DIM, NP,
               sLM, DH, sS, HEADS, 1.f, nullptr, nullptr, 0, 0, 2);
    softmax_k<<<dim3(MLM, HEADS), 256>>>(S3, NP, NP, sS);

    // 7. a2 = softmax(q_l @ k_l^T)
    launch_small(ql, kl, a2, MLM, MLM, DH, DH, DH, MLM,
                 sLM, sLM, sA2, HEADS, 1.f, nullptr, nullptr, 0, 0, 2);
    softmax_k<<<dim3(MLM, HEADS), 256>>>(a2, MLM, MLM, sA2);

    // 8. Moore-Penrose pinv, 6 Newton iterations
    pinv_init_k<<<HEADS, 256>>>(a2, Zb);
    float* Zc = Zb;
    float* Pc = Pb;
    for (int it = 0; it < 6; it++) {
        launch_small(a2, Zc, XZ, MLM, MLM, MLM, MLM, MLM, MLM,
                     sA2, sA2, sA2, HEADS, 1.f, nullptr, nullptr, 0, 0, 0);
        dimin_k<<<(HEADS * (int)sA2) / 256, 256>>>(XZ, Tb, 7.f);
        launch_small(XZ, Tb, Pc, MLM, MLM, MLM, MLM, MLM, MLM,
                     sA2, sA2, sA2, HEADS, 1.f, nullptr, nullptr, 0, 0, 0);
        dimin_k<<<(HEADS * (int)sA2) / 256, 256>>>(Pc, Tb, 15.f);
        launch_small(XZ, Tb, Pc, MLM, MLM, MLM, MLM, MLM, MLM,
                     sA2, sA2, sA2, HEADS, 1.f, nullptr, nullptr, 0, 0, 0);
        dimin_k<<<(HEADS * (int)sA2) / 256, 256>>>(Pc, Tb, 13.f);
        launch_small(Zc, Tb, Pc, MLM, MLM, MLM, MLM, MLM, MLM,
                     sA2, sA2, sA2, HEADS, 0.25f, nullptr, nullptr, 0, 0, 0);
        float* tmp = Zc; Zc = Pc; Pc = tmp;
    }

    // 9. a3v = S3 @ v
    launch_small(S3, qkv + 2 * DIM, a3v, MLM, DH, NP, NP, 3 * DIM, DH,
                 sS, DH, sLM, HEADS, 1.f, nullptr, nullptr, 0, 0, 0);

    // 10. W2 = pinv @ a3v
    launch_small(Zc, a3v, W2, MLM, DH, MLM, MLM, DH, DH,
                 sA2, sLM, sLM, HEADS, 1.f, nullptr, nullptr, 0, 0, 0);

    // 11. attn = S1 @ W2  (written into [Np, 512] at col offset h*64)
    launch_small(S1, W2, attn, NP, DH, MLM, MLM, DH, DIM,
                 sS, sLM, DH, HEADS, 1.f, nullptr, nullptr, 0, 0, 0);

    // 12. attn += depthwise seq-conv(v)
    conv1d_add_k<<<(NP * DIM) / 256, 256>>>(attn, qkv, convw);

    // 13. h += attn[166:] @ out_w + out_b
    launch_big(attn + (long long)PADR * DIM, outw, hbuf, NTOK, DIM, DIM,
               DIM, DIM, DIM, 0, 0, 0, 1, 1.f, outb, hbuf, DIM, 0, 0);
}

extern "C" void kernel_launch(void* const* d_in, const int* in_sizes, int n_in,
                              void* d_out, int out_size)
{
    const float* x      = (const float*)d_in[0];
    const float* fc1_w  = (const float*)d_in[1];
    const float* fc1_b  = (const float*)d_in[2];
    const float* cls    = (const float*)d_in[3];
    const float* ln1_g  = (const float*)d_in[4];
    const float* ln1_b  = (const float*)d_in[5];
    const float* qkv1_w = (const float*)d_in[6];
    const float* out1_w = (const float*)d_in[7];
    const float* out1_b = (const float*)d_in[8];
    const float* conv1w = (const float*)d_in[9];
    const float* ln2_g  = (const float*)d_in[10];
    const float* ln2_b  = (const float*)d_in[11];
    const float* qkv2_w = (const float*)d_in[12];
    const float* out2_w = (const float*)d_in[13];
    const float* out2_b = (const float*)d_in[14];
    const float* conv2w = (const float*)d_in[15];
    const float* pg7_w  = (const float*)d_in[16];
    const float* pg7_b  = (const float*)d_in[17];
    const float* pg5_w  = (const float*)d_in[18];
    const float* pg5_b  = (const float*)d_in[19];
    const float* pg3_w  = (const float*)d_in[20];
    const float* pg3_b  = (const float*)d_in[21];
    const float* norm_g = (const float*)d_in[22];
    const float* norm_b = (const float*)d_in[23];
    const float* fc2_w  = (const float*)d_in[24];
    const float* fc2_b  = (const float*)d_in[25];

    float* base = nullptr;
    cudaGetSymbolAddress((void**)&base, g_scratch);
    float* hA = base + OFF_HA;
    float* h2 = base + OFF_H2;

    // fc1 + relu into rows 1..8192 of hA
    launch_big(x, fc1_w, hA + DIM, 8192, DIM, 1024, 1024, DIM, DIM,
               0, 0, 0, 1, 1.f, fc1_b, nullptr, 0, 0, 1);
    // cls token + wrap rows
    seed_k<<<(90 * DIM) / 256, 256>>>(hA, cls);

    // layer 1 attention (residual into hA)
    run_attn_layer(base, hA, ln1_g, ln1_b, qkv1_w, out1_w, out1_b, conv1w);

    // PPEG: hA -> h2
    ppeg_k<<<(NPIX * DIM + 255) / 256, 256>>>(hA, h2, pg7_w, pg7_b, pg5_w, pg5_b, pg3_w, pg3_b);
    copy_row0_k<<<1, DIM>>>(h2, hA);

    // layer 2 attention (residual into h2)
    run_attn_layer(base, h2, ln2_g, ln2_b, qkv2_w, out2_w, out2_b, conv2w);

    // final LN + fc2 + softmax + argmax + emb
    final_k<<<1, DIM>>>(h2, norm_g, norm_b, fc2_w, fc2_b, (float*)d_out, out_size);
}

// round 2
// speedup vs baseline: 2.4174x; 2.4174x over previous
#include <cuda_runtime.h>

// ----------------------------------------------------------------------------
// TransMIL forward pass, fp32, tuned SIMT GEMM (double-buffered, vectorized).
//   N_TOK=8192, IN_DIM=1024, D=512, HEADS=8, DH=64, M=256, ITERS=6, KRES=33
//   Hs=Ws=91, NPIX=8281, NTOK=8282, pad=166, Np=8448
// ----------------------------------------------------------------------------

#define NP      8448
#define NTOK    8282
#define NPIX    8281
#define HSIZE   91
#define PADR    166
#define DIM     512
#define HEADS   8
#define DH      64
#define MLM     256
#define LCH     33
#define SCALE_Q 0.125f
#define EPSLN   1e-5f

// flags
#define F_RELU  1
#define F_TRB   2
#define F_DIAG  4   // C = alpha*(dcoef*A - A@B)   (square, same layout)

// ---------------- scratch -----------------------------------------------
constexpr long long SZ_H    = (long long)NTOK * DIM;
constexpr long long SZ_QKV  = (long long)NP * 3 * DIM;
constexpr long long SZ_S    = (long long)HEADS * NP * MLM;
constexpr long long SZ_A2   = (long long)MLM * MLM * HEADS;
constexpr long long SZ_LM   = (long long)HEADS * MLM * DH;
constexpr long long SZ_ATTN = (long long)NP * DIM;

constexpr long long OFF_HA   = 0;
constexpr long long OFF_H2   = OFF_HA  + SZ_H;
constexpr long long OFF_XLN  = OFF_H2  + SZ_H;
constexpr long long OFF_QKV  = OFF_XLN + SZ_H;
constexpr long long OFF_S1   = OFF_QKV + SZ_QKV;
constexpr long long OFF_S3   = OFF_S1  + SZ_S;
constexpr long long OFF_A2   = OFF_S3  + SZ_S;
constexpr long long OFF_Z    = OFF_A2  + SZ_A2;
constexpr long long OFF_XZ   = OFF_Z   + SZ_A2;
constexpr long long OFF_T    = OFF_XZ  + SZ_A2;
constexpr long long OFF_T4   = OFF_T   + SZ_A2;
constexpr long long OFF_P    = OFF_T4  + SZ_A2;
constexpr long long OFF_QL   = OFF_P   + SZ_A2;
constexpr long long OFF_KL   = OFF_QL  + SZ_LM;
constexpr long long OFF_A3V  = OFF_KL  + SZ_LM;
constexpr long long OFF_W2   = OFF_A3V + SZ_LM;
constexpr long long OFF_A3P  = OFF_W2  + SZ_LM;                 // split-K partials
constexpr long long SZ_A3P   = 8LL * SZ_LM;
constexpr long long OFF_ATTN = OFF_A3P + SZ_A3P;
constexpr long long SCRATCH_TOTAL = OFF_ATTN + SZ_ATTN;

__device__ float g_scratch[SCRATCH_TOTAL];

// ---------------- double-buffered tiled SGEMM ----------------------------
// C[M,N] = epilogue(alpha * A_eff @ B)
//   A_eff row i = (i < zrows) ? 0 : A[i - zrows]
//   F_TRB : B is [N,K] row-major.  F_DIAG : C = alpha*(dcoef*A - acc).
// Requirements: K % BK == 0, N % BN == 0 (true for all call sites).
template<int BM, int BN, int BK, int TM, int TN, int THREADS>
__global__ void __launch_bounds__(THREADS, 2)
gemm2_k(const float* __restrict__ A, const float* __restrict__ B,
        float* __restrict__ C,
        int Mr, int K, int lda, int ldb, int ldc,
        long long sA, long long sB, long long sC,
        float alpha,
        const float* __restrict__ bias,
        const float* __restrict__ res, int ldres,
        int zrows, int flags, float dcoef)
{
    constexpr int TX = BN / TN;
    constexpr int TY = BM / TM;
    static_assert(TX * TY == THREADS, "thread shape");
    constexpr int AV = BM * BK / (4 * THREADS);
    constexpr int BV = BN * BK / (4 * THREADS);
    static_assert(AV >= 1 && BV >= 1, "vec counts");

    __shared__ float As[2][BK][BM];
    __shared__ float Bs[2][BK][BN];

    const int bz = blockIdx.z;
    A += bz * sA; B += bz * sB; C += bz * sC;

    const int tid = threadIdx.x;
    const int tx = tid % TX, ty = tid / TX;
    const int rowBase = blockIdx.y * BM;
    const int colBase = blockIdx.x * BN;

    float4 ra[AV], rb[BV];

    auto loadA = [&](int k0) {
#pragma unroll
        for (int v = 0; v < AV; v++) {
            int idx = tid + v * THREADS;
            int r = idx / (BK / 4), kq = idx % (BK / 4);
            int gm = rowBase + r, am = gm - zrows;
            if (gm < Mr && am >= 0)
                ra[v] = *reinterpret_cast<const float4*>(A + (long long)am * lda + k0 + kq * 4);
            else
                ra[v] = make_float4(0.f, 0.f, 0.f, 0.f);
        }
    };
    auto storeA = [&](int s) {
#pragma unroll
        for (int v = 0; v < AV; v++) {
            int idx = tid + v * THREADS;
            int r = idx / (BK / 4), kq = idx % (BK / 4);
            As[s][kq * 4 + 0][r] = ra[v].x;
            As[s][kq * 4 + 1][r] = ra[v].y;
            As[s][kq * 4 + 2][r] = ra[v].z;
            As[s][kq * 4 + 3][r] = ra[v].w;
        }
    };
    auto loadB = [&](int k0) {
        if (flags & F_TRB) {
#pragma unroll
            for (int v = 0; v < BV; v++) {
                int idx = tid + v * THREADS;
                int n = idx / (BK / 4), kq = idx % (BK / 4);
                rb[v] = *reinterpret_cast<const float4*>(B + (long long)(colBase + n) * ldb + k0 + kq * 4);
            }
        } else {
#pragma unroll
            for (int v = 0; v < BV; v++) {
                int idx = tid + v * THREADS;
                int kk = idx / (BN / 4), cq = idx % (BN / 4);
                rb[v] = *reinterpret_cast<const float4*>(B + (long long)(k0 + kk) * ldb + colBase + cq * 4);
            }
        }
    };
    auto storeB = [&](int s) {
        if (flags & F_TRB) {
#pragma unroll
            for (int v = 0; v < BV; v++) {
                int idx = tid + v * THREADS;
                int n = idx / (BK / 4), kq = idx % (BK / 4);
                Bs[s][kq * 4 + 0][n] = rb[v].x;
                Bs[s][kq * 4 + 1][n] = rb[v].y;
                Bs[s][kq * 4 + 2][n] = rb[v].z;
                Bs[s][kq * 4 + 3][n] = rb[v].w;
            }
        } else {
#pragma unroll
            for (int v = 0; v < BV; v++) {
                int idx = tid + v * THREADS;
                int kk = idx / (BN / 4), cq = idx % (BN / 4);
                *reinterpret_cast<float4*>(&Bs[s][kk][cq * 4]) = rb[v];
            }
        }
    };

    float acc[TM][TN];
#pragma unroll
    for (int i = 0; i < TM; i++)
#pragma unroll
        for (int j = 0; j < TN; j++) acc[i][j] = 0.f;

    loadA(0); loadB(0);
    storeA(0); storeB(0);
    __syncthreads();

    const int nk = K / BK;
    for (int t = 0; t < nk; t++) {
        const int cur = t & 1;
        if (t + 1 < nk) { loadA((t + 1) * BK); loadB((t + 1) * BK); }
#pragma unroll
        for (int kk = 0; kk < BK; kk++) {
            float a[TM], b[TN];
#pragma unroll
            for (int i = 0; i < TM; i += 4)
                *reinterpret_cast<float4*>(&a[i]) =
                    *reinterpret_cast<const float4*>(&As[cur][kk][ty * TM + i]);
#pragma unroll
            for (int j = 0; j < TN; j += 4)
                *reinterpret_cast<float4*>(&b[j]) =
                    *reinterpret_cast<const float4*>(&Bs[cur][kk][tx * TN + j]);
#pragma unroll
            for (int i = 0; i < TM; i++)
#pragma unroll
                for (int j = 0; j < TN; j++)
                    acc[i][j] = fmaf(a[i], b[j], acc[i][j]);
        }
        if (t + 1 < nk) { storeA(cur ^ 1); storeB(cur ^ 1); }
        __syncthreads();
    }

#pragma unroll
    for (int i = 0; i < TM; i++) {
        int gm = rowBase + ty * TM + i;
        if (gm >= Mr) continue;
#pragma unroll
        for (int j = 0; j < TN; j++) {
            int gn = colBase + tx * TN + j;
            float v;
            if (flags & F_DIAG) {
                v = alpha * (dcoef * A[(long long)gm * lda + gn] - acc[i][j]);
            } else {
                v = alpha * acc[i][j];
                if (bias) v += bias[gn];
                if (res)  v += res[(long long)gm * ldres + gn];
                if (flags & F_RELU) v = fmaxf(v, 0.f);
            }
            C[(long long)gm * ldc + gn] = v;
        }
    }
}

// ---------------- softmax kernels ----------------------------------------

// warp-per-row softmax, 256 contiguous cols, rows % 8 == 0
__global__ void softmax256_k(float* __restrict__ S)
{
    long long row = (long long)blockIdx.x * 8 + (threadIdx.x >> 5);
    int lane = threadIdx.x & 31;
    float* p = S + row * 256 + lane * 8;
    float4 a = *reinterpret_cast<float4*>(p);
    float4 b = *reinterpret_cast<float4*>(p + 4);
    float m = fmaxf(fmaxf(fmaxf(a.x, a.y), fmaxf(a.z, a.w)),
                    fmaxf(fmaxf(b.x, b.y), fmaxf(b.z, b.w)));
#pragma unroll
    for (int o = 16; o; o >>= 1) m = fmaxf(m, __shfl_xor_sync(0xffffffffu, m, o));
    a.x = expf(a.x - m); a.y = expf(a.y - m); a.z = expf(a.z - m); a.w = expf(a.w - m);
    b.x = expf(b.x - m); b.y = expf(b.y - m); b.z = expf(b.z - m); b.w = expf(b.w - m);
    float s = a.x + a.y + a.z + a.w + b.x + b.y + b.z + b.w;
#pragma unroll
    for (int o = 16; o; o >>= 1) s += __shfl_xor_sync(0xffffffffu, s, o);
    float inv = 1.f / s;
    a.x *= inv; a.y *= inv; a.z *= inv; a.w *= inv;
    b.x *= inv; b.y *= inv; b.z *= inv; b.w *= inv;
    *reinterpret_cast<float4*>(p) = a;
    *reinterpret_cast<float4*>(p + 4) = b;
}

// block-per-row softmax over NP=8448 cols, smem-resident
__global__ void softmax_np_k(float* __restrict__ S)
{
    float* row = S + (long long)blockIdx.x * NP;
    __shared__ float buf[NP];
    __shared__ float red[256];
    int t = threadIdx.x;
    float m = -1e30f;
#pragma unroll
    for (int j = 0; j < 33; j++) {
        float v = row[t + j * 256];
        buf[t + j * 256] = v;
        m = fmaxf(m, v);
    }
    red[t] = m; __syncthreads();
    for (int s = 128; s > 0; s >>= 1) { if (t < s) red[t] = fmaxf(red[t], red[t + s]); __syncthreads(); }
    m = red[0]; __syncthreads();
    float sum = 0.f;
#pragma unroll
    for (int j = 0; j < 33; j++) {
        float e = expf(buf[t + j * 256] - m);
        buf[t + j * 256] = e;
        sum += e;
    }
    red[t] = sum; __syncthreads();
    for (int s = 128; s > 0; s >>= 1) { if (t < s) red[t] += red[t + s]; __syncthreads(); }
    float inv = 1.f / red[0]; __syncthreads();
#pragma unroll
    for (int j = 0; j < 33; j++)
        row[t + j * 256] = buf[t + j * 256] * inv;
}

// ---------------- misc kernels --------------------------------------------

__global__ void ln_k(const float* __restrict__ x, float* __restrict__ y,
                     const float* __restrict__ g, const float* __restrict__ b)
{
    long long row = blockIdx.x;
    const float* xr = x + row * DIM;
    float* yr = y + row * DIM;
    int t = threadIdx.x;
    float v0 = xr[t], v1 = xr[t + 256];
    __shared__ float sm[256];
    sm[t] = v0 + v1; __syncthreads();
    for (int s = 128; s > 0; s >>= 1) { if (t < s) sm[t] += sm[t + s]; __syncthreads(); }
    float mu = sm[0] * (1.f / DIM); __syncthreads();
    float d0 = v0 - mu, d1 = v1 - mu;
    sm[t] = d0 * d0 + d1 * d1; __syncthreads();
    for (int s = 128; s > 0; s >>= 1) { if (t < s) sm[t] += sm[t + s]; __syncthreads(); }
    float rs = rsqrtf(sm[0] * (1.f / DIM) + EPSLN); __syncthreads();
    yr[t]       = d0 * rs * g[t]       + b[t];
    yr[t + 256] = d1 * rs * g[t + 256] + b[t + 256];
}

__global__ void landmark_k(const float* __restrict__ qkv,
                           float* __restrict__ ql, float* __restrict__ kl)
{
    int idx = blockIdx.x * 256 + threadIdx.x;
    int d = idx & 63, m = (idx >> 6) & 255, h = idx >> 14;
    int off = (blockIdx.y == 0) ? 0 : DIM;
    float s = 0.f;
    const float* src = qkv + off + h * DH + d;
#pragma unroll
    for (int j = 0; j < LCH; j++)
        s += src[(long long)(m * LCH + j) * (3 * DIM)];
    float* dst = (blockIdx.y == 0) ? ql : kl;
    dst[h * (MLM * DH) + m * DH + d] = s * (1.f / LCH);
}

__global__ void pinv_init_k(const float* __restrict__ A2, float* __restrict__ Z)
{
    int h = blockIdx.x;
    const float* A = A2 + (long long)h * MLM * MLM;
    float* Zh = Z + (long long)h * MLM * MLM;
    int t = threadIdx.x;
    float rs = 0.f, cs = 0.f;
    for (int j = 0; j < MLM; j++) {
        rs += fabsf(A[t * MLM + j]);
        cs += fabsf(A[j * MLM + t]);
    }
    __shared__ float s1[256], s2[256];
    s1[t] = rs; s2[t] = cs; __syncthreads();
    for (int s = 128; s > 0; s >>= 1) {
        if (t < s) { s1[t] = fmaxf(s1[t], s1[t + s]); s2[t] = fmaxf(s2[t], s2[t + s]); }
        __syncthreads();
    }
    float scale = 1.f / (s1[0] * s2[0]);
    __syncthreads();
    for (int j = 0; j < MLM; j++)
        Zh[t * MLM + j] = A[j * MLM + t] * scale;
}

__global__ void reduce8_k(float* __restrict__ dst, const float* __restrict__ src)
{
    int idx = blockIdx.x * 256 + threadIdx.x;   // HEADS*MLM*DH total
    float s = 0.f;
#pragma unroll
    for (int j = 0; j < 8; j++) s += src[(long long)j * (HEADS * MLM * DH) + idx];
    dst[idx] = s;
}

__global__ void conv1d_add_k(float* __restrict__ attn, const float* __restrict__ qkv,
                             const float* __restrict__ w)
{
    int idx = blockIdx.x * 256 + threadIdx.x;   // NP*DIM
    int i = idx >> 9, c = idx & 511, h = c >> 6;
    float acc = 0.f;
#pragma unroll
    for (int t = 0; t < 33; t++) {
        int j = i + t - 16;
        if (j >= 0 && j < NP)
            acc += w[h * 33 + t] * qkv[(long long)j * (3 * DIM) + 2 * DIM + c];
    }
    attn[idx] += acc;
}

__global__ void seed_k(float* __restrict__ hA, const float* __restrict__ cls)
{
    int idx = blockIdx.x * 256 + threadIdx.x;
    if (idx < DIM) hA[idx] = cls[idx];
    int j = idx - DIM;
    if (j >= 0 && j < 89 * DIM) {
        int r = j >> 9, c = j & 511;
        hA[(long long)(1 + 8192 + r) * DIM + c] = hA[(long long)(1 + r) * DIM + c];
    }
}

__global__ void ppeg_k(const float* __restrict__ hA, float* __restrict__ h2,
                       const float* __restrict__ w7, const float* __restrict__ b7,
                       const float* __restrict__ w5, const float* __restrict__ b5,
                       const float* __restrict__ w3, const float* __restrict__ b3)
{
    int idx = blockIdx.x * 256 + threadIdx.x;
    if (idx >= NPIX * DIM) return;
    int tok = idx >> 9, ch = idx & 511;
    int r = tok / HSIZE, cc = tok % HSIZE;
    float acc = hA[(long long)(1 + tok) * DIM + ch] + b7[ch] + b5[ch] + b3[ch];
#pragma unroll
    for (int u = -3; u <= 3; u++) {
        int rr = r + u;
        if (rr < 0 || rr >= HSIZE) continue;
#pragma unroll
        for (int v = -3; v <= 3; v++) {
            int c2 = cc + v;
            if (c2 < 0 || c2 >= HSIZE) continue;
            float f = hA[(long long)(1 + rr * HSIZE + c2) * DIM + ch];
            float w = w7[ch * 49 + (u + 3) * 7 + (v + 3)];
            if (u >= -2 && u <= 2 && v >= -2 && v <= 2)
                w += w5[ch * 25 + (u + 2) * 5 + (v + 2)];
            if (u >= -1 && u <= 1 && v >= -1 && v <= 1)
                w += w3[ch * 9 + (u + 1) * 3 + (v + 1)];
            acc += w * f;
        }
    }
    h2[(long long)(1 + tok) * DIM + ch] = acc;
}

__global__ void copy_row0_k(float* __restrict__ h2, const float* __restrict__ hA)
{
    h2[threadIdx.x] = hA[threadIdx.x];
}

__global__ void final_k(const float* __restrict__ h, const float* __restrict__ g,
                        const float* __restrict__ b, const float* __restrict__ w,
                        const float* __restrict__ bias, float* __restrict__ out,
                        int out_size)
{
    int t = threadIdx.x;   // 512
    __shared__ float sm[512];
    float v = h[t];
    sm[t] = v; __syncthreads();
    for (int s = 256; s > 0; s >>= 1) { if (t < s) sm[t] += sm[t + s]; __syncthreads(); }
    float mu = sm[0] * (1.f / DIM); __syncthreads();
    float d = v - mu;
    sm[t] = d * d; __syncthreads();
    for (int s = 256; s > 0; s >>= 1) { if (t < s) sm[t] += sm[t + s]; __syncthreads(); }
    float rs = rsqrtf(sm[0] * (1.f / DIM) + EPSLN); __syncthreads();
    float e = d * rs * g[t] + b[t];
    if (5 + t < out_size) out[5 + t] = e;
    sm[t] = e * w[t * 2]; __syncthreads();
    for (int s = 256; s > 0; s >>= 1) { if (t < s) sm[t] += sm[t + s]; __syncthreads(); }
    float l0 = sm[0] + bias[0]; __syncthreads();
    sm[t] = e * w[t * 2 + 1]; __syncthreads();
    for (int s = 256; s > 0; s >>= 1) { if (t < s) sm[t] += sm[t + s]; __syncthreads(); }
    float l1 = sm[0] + bias[1]; __syncthreads();
    if (t == 0 && out_size >= 5) {
        out[0] = l0; out[1] = l1;
        float mx = fmaxf(l0, l1);
        float e0 = expf(l0 - mx), e1 = expf(l1 - mx);
        float s = e0 + e1;
        out[2] = e0 / s; out[3] = e1 / s;
        out[4] = (l1 > l0) ? 1.f : 0.f;
    }
}

// ---------------- host orchestration ---------------------------------------

static void launch_big(const float* A, const float* B, float* C,
                       int M, int N, int K, int lda, int ldb, int ldc,
                       long long sA, long long sB, long long sC, int batch,
                       float alpha, const float* bias, const float* res, int ldres,
                       int zrows, int flags, float dcoef = 0.f)
{
    dim3 grid(N / 128, (M + 127) / 128, batch);
    gemm2_k<128, 128, 16, 8, 8, 256><<<grid, 256>>>(A, B, C, M, K, lda, ldb, ldc,
                                                    sA, sB, sC, alpha, bias, res, ldres,
                                                    zrows, flags, dcoef);
}

static void launch_small(const float* A, const float* B, float* C,
                         int M, int N, int K, int lda, int ldb, int ldc,
                         long long sA, long long sB, long long sC, int batch,
                         float alpha, const float* bias, const float* res, int ldres,
                         int zrows, int flags, float dcoef = 0.f)
{
    dim3 grid(N / 64, (M + 63) / 64, batch);
    gemm2_k<64, 64, 16, 4, 4, 256><<<grid, 256>>>(A, B, C, M, K, lda, ldb, ldc,
                                                  sA, sB, sC, alpha, bias, res, ldres,
                                                  zrows, flags, dcoef);
}

static void run_attn_layer(float* base, float* hbuf,
                           const float* lng, const float* lnb,
                           const float* qkvw, const float* outw, const float* outb,
                           const float* convw)
{
    float* xln  = base + OFF_XLN;
    float* qkv  = base + OFF_QKV;
    float* S1   = base + OFF_S1;
    float* S3   = base + OFF_S3;
    float* a2   = base + OFF_A2;
    float* Zb   = base + OFF_Z;
    float* XZ   = base + OFF_XZ;
    float* Tb   = base + OFF_T;
    float* T4   = base + OFF_T4;
    float* Pb   = base + OFF_P;
    float* ql   = base + OFF_QL;
    float* kl   = base + OFF_KL;
    float* a3v  = base + OFF_A3V;
    float* W2   = base + OFF_W2;
    float* a3p  = base + OFF_A3P;
    float* attn = base + OFF_ATTN;

    const long long sS  = (long long)NP * MLM;
    const long long sA2 = (long long)MLM * MLM;
    const long long sLM = (long long)MLM * DH;

    // LayerNorm
    ln_k<<<NTOK, 256>>>(hbuf, xln, lng, lnb);

    // qkv = pad(xln) @ qkv_w  (front zero rows via zrows; pad rows -> q=k=v=0)
    launch_big(xln, qkvw, qkv, NP, 3 * DIM, DIM, DIM, 3 * DIM, 3 * DIM,
               0, 0, 0, 1, 1.f, nullptr, nullptr, 0, PADR, 0);

    // landmarks (raw q; scale folded into alpha below)
    landmark_k<<<dim3(512, 2), 256>>>(qkv, ql, kl);

    // S1 = (q*scale) @ k_l^T, softmax
    launch_small(qkv, kl, S1, NP, MLM, DH, 3 * DIM, DH, MLM,
                 DH, sLM, sS, HEADS, SCALE_Q, nullptr, nullptr, 0, 0, F_TRB);
    softmax256_k<<<(HEADS * NP) / 8, 256>>>(S1);

    // S3 = (q_l*scale) @ k^T, softmax over Np
    launch_small(ql, qkv + DIM, S3, MLM, NP, DH, DH, 3 * DIM, NP,
                 sLM, DH, sS, HEADS, SCALE_Q, nullptr, nullptr, 0, 0, F_TRB);
    softmax_np_k<<<HEADS * MLM, 256>>>(S3);

    // a2 = softmax((q_l*scale) @ k_l^T)
    launch_small(ql, kl, a2, MLM, MLM, DH, DH, DH, MLM,
                 sLM, sLM, sA2, HEADS, SCALE_Q, nullptr, nullptr, 0, 0, F_TRB);
    softmax256_k<<<(HEADS * MLM) / 8, 256>>>(a2);

    // Moore-Penrose pinv: 6 Newton iterations, diag epilogues fused
    pinv_init_k<<<HEADS, 256>>>(a2, Zb);
    float* Zc = Zb;
    float* Pc = Pb;
    for (int it = 0; it < 6; it++) {
        // XZ = a2 @ Z
        launch_small(a2, Zc, XZ, MLM, MLM, MLM, MLM, MLM, MLM,
                     sA2, sA2, sA2, HEADS, 1.f, nullptr, nullptr, 0, 0, 0);
        // Tb = 7*XZ - XZ@XZ
        launch_small(XZ, XZ, Tb, MLM, MLM, MLM, MLM, MLM, MLM,
                     sA2, sA2, sA2, HEADS, 1.f, nullptr, nullptr, 0, 0, F_DIAG, 7.f);
        // T4 = 15*XZ - XZ@Tb
        launch_small(XZ, Tb, T4, MLM, MLM, MLM, MLM, MLM, MLM,
                     sA2, sA2, sA2, HEADS, 1.f, nullptr, nullptr, 0, 0, F_DIAG, 15.f);
        // Z' = 0.25*(13*Z - Z@T4)
        launch_small(Zc, T4, Pc, MLM, MLM, MLM, MLM, MLM, MLM,
                     sA2, sA2, sA2, HEADS, 0.25f, nullptr, nullptr, 0, 0, F_DIAG, 13.f);
        float* tmp = Zc; Zc = Pc; Pc = tmp;
    }

    // a3v = S3 @ v  -- deterministic split-K x8 into partials, then reduce
    for (int s = 0; s < 8; s++) {
        launch_small(S3 + s * 1056, qkv + 2 * DIM + (long long)(s * 1056) * (3 * DIM),
                     a3p + (long long)s * (HEADS * sLM),
                     MLM, DH, 1056, NP, 3 * DIM, DH,
                     sS, DH, sLM, HEADS, 1.f, nullptr, nullptr, 0, 0, 0);
    }
    reduce8_k<<<(HEADS * (int)sLM) / 256, 256>>>(a3v, a3p);

    // W2 = pinv @ a3v
    launch_small(Zc, a3v, W2, MLM, DH, MLM, MLM, DH, DH,
                 sA2, sLM, sLM, HEADS, 1.f, nullptr, nullptr, 0, 0, 0);

    // attn = S1 @ W2  (per head, into [Np,512] col block h*64)
    launch_small(S1, W2, attn, NP, DH, MLM, MLM, DH, DIM,
                 sS, sLM, DH, HEADS, 1.f, nullptr, nullptr, 0, 0, 0);

    // attn += depthwise seq-conv(v)
    conv1d_add_k<<<(NP * DIM) / 256, 256>>>(attn, qkv, convw);

    // h += attn[166:] @ out_w + out_b
    launch_big(attn + (long long)PADR * DIM, outw, hbuf, NTOK, DIM, DIM,
               DIM, DIM, DIM, 0, 0, 0, 1, 1.f, outb, hbuf, DIM, 0, 0);
}

extern "C" void kernel_launch(void* const* d_in, const int* in_sizes, int n_in,
                              void* d_out, int out_size)
{
    const float* x      = (const float*)d_in[0];
    const float* fc1_w  = (const float*)d_in[1];
    const float* fc1_b  = (const float*)d_in[2];
    const float* cls    = (const float*)d_in[3];
    const float* ln1_g  = (const float*)d_in[4];
    const float* ln1_b  = (const float*)d_in[5];
    const float* qkv1_w = (const float*)d_in[6];
    const float* out1_w = (const float*)d_in[7];
    const float* out1_b = (const float*)d_in[8];
    const float* conv1w = (const float*)d_in[9];
    const float* ln2_g  = (const float*)d_in[10];
    const float* ln2_b  = (const float*)d_in[11];
    const float* qkv2_w = (const float*)d_in[12];
    const float* out2_w = (const float*)d_in[13];
    const float* out2_b = (const float*)d_in[14];
    const float* conv2w = (const float*)d_in[15];
    const float* pg7_w  = (const float*)d_in[16];
    const float* pg7_b  = (const float*)d_in[17];
    const float* pg5_w  = (const float*)d_in[18];
    const float* pg5_b  = (const float*)d_in[19];
    const float* pg3_w  = (const float*)d_in[20];
    const float* pg3_b  = (const float*)d_in[21];
    const float* norm_g = (const float*)d_in[22];
    const float* norm_b = (const float*)d_in[23];
    const float* fc2_w  = (const float*)d_in[24];
    const float* fc2_b  = (const float*)d_in[25];

    float* base = nullptr;
    cudaGetSymbolAddress((void**)&base, g_scratch);
    float* hA = base + OFF_HA;
    float* h2 = base + OFF_H2;

    // fc1 + relu into rows 1..8192 of hA
    launch_big(x, fc1_w, hA + DIM, 8192, DIM, 1024, 1024, DIM, DIM,
               0, 0, 0, 1, 1.f, fc1_b, nullptr, 0, 0, F_RELU);
    seed_k<<<(90 * DIM) / 256, 256>>>(hA, cls);

    run_attn_layer(base, hA, ln1_g, ln1_b, qkv1_w, out1_w, out1_b, conv1w);

    ppeg_k<<<(NPIX * DIM + 255) / 256, 256>>>(hA, h2, pg7_w, pg7_b, pg5_w, pg5_b, pg3_w, pg3_b);
    copy_row0_k<<<1, DIM>>>(h2, hA);

    run_attn_layer(base, h2, ln2_g, ln2_b, qkv2_w, out2_w, out2_b, conv2w);

    final_k<<<1, DIM>>>(h2, norm_g, norm_b, fc2_w, fc2_b, (float*)d_out, out_size);
}

// round 3
// speedup vs baseline: 4.5755x; 1.8928x over previous
#include <cuda_runtime.h>
#include <cstdint>

// ----------------------------------------------------------------------------
// TransMIL forward pass. GEMMs on tensor cores (tf32 mma.sync, fp32 accum).
//   N_TOK=8192, IN_DIM=1024, D=512, HEADS=8, DH=64, M=256, ITERS=6, KRES=33
//   Hs=Ws=91, NPIX=8281, NTOK=8282, pad=166, Np=8448
// ----------------------------------------------------------------------------

#define NP      8448
#define NTOK    8282
#define NPIX    8281
#define HSIZE   91
#define PADR    166
#define DIM     512
#define HEADS   8
#define DH      64
#define MLM     256
#define LCH     33
#define SCALE_Q 0.125f
#define EPSLN   1e-5f

#define F_RELU  1
#define F_TRB   2
#define F_DIAG  4

// ---------------- scratch -----------------------------------------------
constexpr long long SZ_H    = (long long)NTOK * DIM;
constexpr long long SZ_QKV  = (long long)NP * 3 * DIM;
constexpr long long SZ_S    = (long long)HEADS * NP * MLM;
constexpr long long SZ_A2   = (long long)MLM * MLM * HEADS;
constexpr long long SZ_LM   = (long long)HEADS * MLM * DH;
constexpr long long SZ_ATTN = (long long)NP * DIM;

constexpr long long OFF_HA   = 0;
constexpr long long OFF_H2   = OFF_HA  + SZ_H;
constexpr long long OFF_XLN  = OFF_H2  + SZ_H;
constexpr long long OFF_QKV  = OFF_XLN + SZ_H;
constexpr long long OFF_S1   = OFF_QKV + SZ_QKV;
constexpr long long OFF_S3   = OFF_S1  + SZ_S;
constexpr long long OFF_A2   = OFF_S3  + SZ_S;
constexpr long long OFF_Z    = OFF_A2  + SZ_A2;
constexpr long long OFF_XZ   = OFF_Z   + SZ_A2;
constexpr long long OFF_T    = OFF_XZ  + SZ_A2;
constexpr long long OFF_T4   = OFF_T   + SZ_A2;
constexpr long long OFF_P    = OFF_T4  + SZ_A2;
constexpr long long OFF_QL   = OFF_P   + SZ_A2;
constexpr long long OFF_KL   = OFF_QL  + SZ_LM;
constexpr long long OFF_A3V  = OFF_KL  + SZ_LM;
constexpr long long OFF_W2   = OFF_A3V + SZ_LM;
constexpr long long OFF_A3P  = OFF_W2  + SZ_LM;
constexpr long long SZ_A3P   = 8LL * SZ_LM;
constexpr long long OFF_ATTN = OFF_A3P + SZ_A3P;
constexpr long long SCRATCH_TOTAL = OFF_ATTN + SZ_ATTN;

__device__ float g_scratch[SCRATCH_TOTAL];

// ---------------- tensor-core tf32 GEMM -----------------------------------

__device__ __forceinline__ void cpa16(uint32_t dst, const float* src, int validBytes)
{
    asm volatile("cp.async.cg.shared.global [%0], [%1], 16, %2;\n"
                 :: "r"(dst), "l"(src), "r"(validBytes));
}

__device__ __forceinline__ void mma_tf32(float* d, const uint32_t* a, const uint32_t* b)
{
    asm volatile(
        "mma.sync.aligned.m16n8k8.row.col.f32.tf32.tf32.f32 "
        "{%0,%1,%2,%3}, {%4,%5,%6,%7}, {%8,%9}, {%0,%1,%2,%3};"
        : "+f"(d[0]), "+f"(d[1]), "+f"(d[2]), "+f"(d[3])
        : "r"(a[0]), "r"(a[1]), "r"(a[2]), "r"(a[3]), "r"(b[0]), "r"(b[1]));
}

// C[M,N] = epilogue(alpha * A_eff @ B)
//  A_eff row i = (i < zrows) ? 0 : A[i-zrows].   TRB: B is [N,K] row-major.
//  F_DIAG: C = alpha*(dcoef*A - acc).  Requires K%BK==0, N%BN==0.
template<int BM, int BN, int BK, int WM, int WN, bool TRB, int THREADS, int MAXB>
__global__ void __launch_bounds__(THREADS, MAXB)
gemm_tc(const float* __restrict__ A, const float* __restrict__ B,
        float* __restrict__ C,
        int Mr, int K, int lda, int ldb, int ldc,
        long long sA, long long sB, long long sC,
        float alpha,
        const float* __restrict__ bias,
        const float* __restrict__ res, int ldres,
        int zrows, int flags, float dcoef)
{
    constexpr int MT = BM / (WM * 16);
    constexpr int NT = BN / (WN * 8);
    constexpr int ASTR = BK + 4;
    constexpr int ASZ  = BM * ASTR;
    constexpr int BSTR = TRB ? (BK + 4) : (BN + 8);
    constexpr int BROWS = TRB ? BN : BK;
    constexpr int BSZ  = BROWS * BSTR;
    constexpr int CA = BM * BK / (4 * THREADS);
    constexpr int CB = BN * BK / (4 * THREADS);
    static_assert(CA >= 1 && CB >= 1, "chunks");
    static_assert(WM * WN == THREADS / 32, "warps");

    __shared__ float sAr[2 * ASZ];
    __shared__ float sBr[2 * BSZ];

    const int bz = blockIdx.z;
    A += bz * sA; B += bz * sB; C += bz * sC;

    const int tid = threadIdx.x;
    const int lane = tid & 31;
    const int w = tid >> 5;
    const int wm = w / WN, wn = w % WN;
    const int m0 = wm * MT * 16;
    const int n0 = wn * NT * 8;
    const int g = lane >> 2, c = lane & 3;
    const int rowBase = blockIdx.y * BM;
    const int colBase = blockIdx.x * BN;

    const uint32_t saA = (uint32_t)__cvta_generic_to_shared(sAr);
    const uint32_t saB = (uint32_t)__cvta_generic_to_shared(sBr);

    auto loadTiles = [&](int st, int k0) {
#pragma unroll
        for (int v = 0; v < CA; v++) {
            int idx = tid + v * THREADS;
            int m = idx / (BK / 4), kq = idx % (BK / 4);
            int gm = rowBase + m, am = gm - zrows;
            bool ok = (gm < Mr) && (am >= 0);
            const float* src = A + (ok ? (long long)am * lda : 0) + k0 + kq * 4;
            cpa16(saA + (uint32_t)(st * ASZ + m * ASTR + kq * 4) * 4, src, ok ? 16 : 0);
        }
        if (TRB) {
#pragma unroll
            for (int v = 0; v < CB; v++) {
                int idx = tid + v * THREADS;
                int n = idx / (BK / 4), kq = idx % (BK / 4);
                const float* src = B + (long long)(colBase + n) * ldb + k0 + kq * 4;
                cpa16(saB + (uint32_t)(st * BSZ + n * BSTR + kq * 4) * 4, src, 16);
            }
        } else {
#pragma unroll
            for (int v = 0; v < CB; v++) {
                int idx = tid + v * THREADS;
                int kk = idx / (BN / 4), nq = idx % (BN / 4);
                const float* src = B + (long long)(k0 + kk) * ldb + colBase + nq * 4;
                cpa16(saB + (uint32_t)(st * BSZ + kk * BSTR + nq * 4) * 4, src, 16);
            }
        }
    };

    float acc[MT][NT][4];
#pragma unroll
    for (int i = 0; i < MT; i++)
#pragma unroll
        for (int j = 0; j < NT; j++)
#pragma unroll
            for (int e = 0; e < 4; e++) acc[i][j][e] = 0.f;

    loadTiles(0, 0);
    asm volatile("cp.async.commit_group;");

    const int nk = K / BK;
    for (int t = 0; t < nk; t++) {
        const int st = t & 1;
        if (t + 1 < nk) {
            loadTiles(st ^ 1, (t + 1) * BK);
            asm volatile("cp.async.commit_group;");
            asm volatile("cp.async.wait_group 1;");
        } else {
            asm volatile("cp.async.wait_group 0;");
        }
        __syncthreads();

        const float* pA = sAr + st * ASZ;
        const float* pB = sBr + st * BSZ;
#pragma unroll
        for (int kk = 0; kk < BK; kk += 8) {
            uint32_t af[MT][4], bf[NT][2];
#pragma unroll
            for (int mt = 0; mt < MT; mt++) {
                int r = m0 + mt * 16 + g;
                af[mt][0] = __float_as_uint(pA[r * ASTR + kk + c]);
                af[mt][1] = __float_as_uint(pA[(r + 8) * ASTR + kk + c]);
                af[mt][2] = __float_as_uint(pA[r * ASTR + kk + 4 + c]);
                af[mt][3] = __float_as_uint(pA[(r + 8) * ASTR + kk + 4 + c]);
            }
#pragma unroll
            for (int nt = 0; nt < NT; nt++) {
                int col = n0 + nt * 8 + g;
                if (TRB) {
                    bf[nt][0] = __float_as_uint(pB[col * BSTR + kk + c]);
                    bf[nt][1] = __float_as_uint(pB[col * BSTR + kk + 4 + c]);
                } else {
                    bf[nt][0] = __float_as_uint(pB[(kk + c) * BSTR + col]);
                    bf[nt][1] = __float_as_uint(pB[(kk + 4 + c) * BSTR + col]);
                }
            }
#pragma unroll
            for (int mt = 0; mt < MT; mt++)
#pragma unroll
                for (int nt = 0; nt < NT; nt++)
                    mma_tf32(acc[mt][nt], af[mt], bf[nt]);
        }
        __syncthreads();
    }

    // epilogue
#pragma unroll
    for (int mt = 0; mt < MT; mt++) {
#pragma unroll
        for (int nt = 0; nt < NT; nt++) {
            int gn = colBase + n0 + nt * 8 + 2 * c;
#pragma unroll
            for (int half = 0; half < 2; half++) {
                int gm = rowBase + m0 + mt * 16 + g + half * 8;
                if (gm >= Mr) continue;
#pragma unroll
                for (int e = 0; e < 2; e++) {
                    float v = acc[mt][nt][half * 2 + e];
                    int gnn = gn + e;
                    if (flags & F_DIAG) {
                        v = alpha * (dcoef * A[(long long)gm * lda + gnn] - v);
                    } else {
                        v = alpha * v;
                        if (bias) v += bias[gnn];
                        if (res)  v += res[(long long)gm * ldres + gnn];
                        if (flags & F_RELU) v = fmaxf(v, 0.f);
                    }
                    C[(long long)gm * ldc + gnn] = v;
                }
            }
        }
    }
}

// ---------------- softmax kernels ----------------------------------------

__global__ void softmax256_k(float* __restrict__ S)
{
    long long row = (long long)blockIdx.x * 8 + (threadIdx.x >> 5);
    int lane = threadIdx.x & 31;
    float* p = S + row * 256 + lane * 8;
    float4 a = *reinterpret_cast<float4*>(p);
    float4 b = *reinterpret_cast<float4*>(p + 4);
    float m = fmaxf(fmaxf(fmaxf(a.x, a.y), fmaxf(a.z, a.w)),
                    fmaxf(fmaxf(b.x, b.y), fmaxf(b.z, b.w)));
#pragma unroll
    for (int o = 16; o; o >>= 1) m = fmaxf(m, __shfl_xor_sync(0xffffffffu, m, o));
    a.x = expf(a.x - m); a.y = expf(a.y - m); a.z = expf(a.z - m); a.w = expf(a.w - m);
    b.x = expf(b.x - m); b.y = expf(b.y - m); b.z = expf(b.z - m); b.w = expf(b.w - m);
    float s = a.x + a.y + a.z + a.w + b.x + b.y + b.z + b.w;
#pragma unroll
    for (int o = 16; o; o >>= 1) s += __shfl_xor_sync(0xffffffffu, s, o);
    float inv = 1.f / s;
    a.x *= inv; a.y *= inv; a.z *= inv; a.w *= inv;
    b.x *= inv; b.y *= inv; b.z *= inv; b.w *= inv;
    *reinterpret_cast<float4*>(p) = a;
    *reinterpret_cast<float4*>(p + 4) = b;
}

__global__ void softmax_np_k(float* __restrict__ S)
{
    float* row = S + (long long)blockIdx.x * NP;
    __shared__ float buf[NP];
    __shared__ float red[256];
    int t = threadIdx.x;
    float m = -1e30f;
#pragma unroll
    for (int j = 0; j < 33; j++) {
        float v = row[t + j * 256];
        buf[t + j * 256] = v;
        m = fmaxf(m, v);
    }
    red[t] = m; __syncthreads();
    for (int s = 128; s > 0; s >>= 1) { if (t < s) red[t] = fmaxf(red[t], red[t + s]); __syncthreads(); }
    m = red[0]; __syncthreads();
    float sum = 0.f;
#pragma unroll
    for (int j = 0; j < 33; j++) {
        float e = expf(buf[t + j * 256] - m);
        buf[t + j * 256] = e;
        sum += e;
    }
    red[t] = sum; __syncthreads();
    for (int s = 128; s > 0; s >>= 1) { if (t < s) red[t] += red[t + s]; __syncthreads(); }
    float inv = 1.f / red[0]; __syncthreads();
#pragma unroll
    for (int j = 0; j < 33; j++)
        row[t + j * 256] = buf[t + j * 256] * inv;
}

// ---------------- misc kernels --------------------------------------------

__global__ void ln_k(const float* __restrict__ x, float* __restrict__ y,
                     const float* __restrict__ g, const float* __restrict__ b)
{
    long long row = blockIdx.x;
    const float* xr = x + row * DIM;
    float* yr = y + row * DIM;
    int t = threadIdx.x;
    float v0 = xr[t], v1 = xr[t + 256];
    __shared__ float sm[256];
    sm[t] = v0 + v1; __syncthreads();
    for (int s = 128; s > 0; s >>= 1) { if (t < s) sm[t] += sm[t + s]; __syncthreads(); }
    float mu = sm[0] * (1.f / DIM); __syncthreads();
    float d0 = v0 - mu, d1 = v1 - mu;
    sm[t] = d0 * d0 + d1 * d1; __syncthreads();
    for (int s = 128; s > 0; s >>= 1) { if (t < s) sm[t] += sm[t + s]; __syncthreads(); }
    float rs = rsqrtf(sm[0] * (1.f / DIM) + EPSLN); __syncthreads();
    yr[t]       = d0 * rs * g[t]       + b[t];
    yr[t + 256] = d1 * rs * g[t + 256] + b[t + 256];
}

__global__ void landmark_k(const float* __restrict__ qkv,
                           float* __restrict__ ql, float* __restrict__ kl)
{
    int idx = blockIdx.x * 256 + threadIdx.x;
    int d = idx & 63, m = (idx >> 6) & 255, h = idx >> 14;
    int off = (blockIdx.y == 0) ? 0 : DIM;
    float s = 0.f;
    const float* src = qkv + off + h * DH + d;
#pragma unroll
    for (int j = 0; j < LCH; j++)
        s += src[(long long)(m * LCH + j) * (3 * DIM)];
    float* dst = (blockIdx.y == 0) ? ql : kl;
    dst[h * (MLM * DH) + m * DH + d] = s * (1.f / LCH);
}

__global__ void pinv_init_k(const float* __restrict__ A2, float* __restrict__ Z)
{
    int h = blockIdx.x;
    const float* A = A2 + (long long)h * MLM * MLM;
    float* Zh = Z + (long long)h * MLM * MLM;
    int t = threadIdx.x;
    float rs = 0.f, cs = 0.f;
    for (int j = 0; j < MLM; j++) {
        rs += fabsf(A[t * MLM + j]);
        cs += fabsf(A[j * MLM + t]);
    }
    __shared__ float s1[256], s2[256];
    s1[t] = rs; s2[t] = cs; __syncthreads();
    for (int s = 128; s > 0; s >>= 1) {
        if (t < s) { s1[t] = fmaxf(s1[t], s1[t + s]); s2[t] = fmaxf(s2[t], s2[t + s]); }
        __syncthreads();
    }
    float scale = 1.f / (s1[0] * s2[0]);
    __syncthreads();
    for (int j = 0; j < MLM; j++)
        Zh[t * MLM + j] = A[j * MLM + t] * scale;
}

__global__ void reduce8_k(float* __restrict__ dst, const float* __restrict__ src)
{
    int idx = blockIdx.x * 256 + threadIdx.x;
    float s = 0.f;
#pragma unroll
    for (int j = 0; j < 8; j++) s += src[(long long)j * (HEADS * MLM * DH) + idx];
    dst[idx] = s;
}

__global__ void conv1d_add_k(float* __restrict__ attn, const float* __restrict__ qkv,
                             const float* __restrict__ w)
{
    int idx = blockIdx.x * 256 + threadIdx.x;
    int i = idx >> 9, c = idx & 511, h = c >> 6;
    float acc = 0.f;
#pragma unroll
    for (int t = 0; t < 33; t++) {
        int j = i + t - 16;
        if (j >= 0 && j < NP)
            acc += w[h * 33 + t] * qkv[(long long)j * (3 * DIM) + 2 * DIM + c];
    }
    attn[idx] += acc;
}

__global__ void seed_k(float* __restrict__ hA, const float* __restrict__ cls)
{
    int idx = blockIdx.x * 256 + threadIdx.x;
    if (idx < DIM) hA[idx] = cls[idx];
    int j = idx - DIM;
    if (j >= 0 && j < 89 * DIM) {
        int r = j >> 9, c = j & 511;
        hA[(long long)(1 + 8192 + r) * DIM + c] = hA[(long long)(1 + r) * DIM + c];
    }
}

__global__ void ppeg_k(const float* __restrict__ hA, float* __restrict__ h2,
                       const float* __restrict__ w7, const float* __restrict__ b7,
                       const float* __restrict__ w5, const float* __restrict__ b5,
                       const float* __restrict__ w3, const float* __restrict__ b3)
{
    int idx = blockIdx.x * 256 + threadIdx.x;
    if (idx >= NPIX * DIM) return;
    int tok = idx >> 9, ch = idx & 511;
    int r = tok / HSIZE, cc = tok % HSIZE;
    float acc = hA[(long long)(1 + tok) * DIM + ch] + b7[ch] + b5[ch] + b3[ch];
#pragma unroll
    for (int u = -3; u <= 3; u++) {
        int rr = r + u;
        if (rr < 0 || rr >= HSIZE) continue;
#pragma unroll
        for (int v = -3; v <= 3; v++) {
            int c2 = cc + v;
            if (c2 < 0 || c2 >= HSIZE) continue;
            float f = hA[(long long)(1 + rr * HSIZE + c2) * DIM + ch];
            float w = w7[ch * 49 + (u + 3) * 7 + (v + 3)];
            if (u >= -2 && u <= 2 && v >= -2 && v <= 2)
                w += w5[ch * 25 + (u + 2) * 5 + (v + 2)];
            if (u >= -1 && u <= 1 && v >= -1 && v <= 1)
                w += w3[ch * 9 + (u + 1) * 3 + (v + 1)];
            acc += w * f;
        }
    }
    h2[(long long)(1 + tok) * DIM + ch] = acc;
}

__global__ void copy_row0_k(float* __restrict__ h2, const float* __restrict__ hA)
{
    h2[threadIdx.x] = hA[threadIdx.x];
}

__global__ void final_k(const float* __restrict__ h, const float* __restrict__ g,
                        const float* __restrict__ b, const float* __restrict__ w,
                        const float* __restrict__ bias, float* __restrict__ out,
                        int out_size)
{
    int t = threadIdx.x;
    __shared__ float sm[512];
    float v = h[t];
    sm[t] = v; __syncthreads();
    for (int s = 256; s > 0; s >>= 1) { if (t < s) sm[t] += sm[t + s]; __syncthreads(); }
    float mu = sm[0] * (1.f / DIM); __syncthreads();
    float d = v - mu;
    sm[t] = d * d; __syncthreads();
    for (int s = 256; s > 0; s >>= 1) { if (t < s) sm[t] += sm[t + s]; __syncthreads(); }
    float rs = rsqrtf(sm[0] * (1.f / DIM) + EPSLN); __syncthreads();
    float e = d * rs * g[t] + b[t];
    if (5 + t < out_size) out[5 + t] = e;
    sm[t] = e * w[t * 2]; __syncthreads();
    for (int s = 256; s > 0; s >>= 1) { if (t < s) sm[t] += sm[t + s]; __syncthreads(); }
    float l0 = sm[0] + bias[0]; __syncthreads();
    sm[t] = e * w[t * 2 + 1]; __syncthreads();
    for (int s = 256; s > 0; s >>= 1) { if (t < s) sm[t] += sm[t + s]; __syncthreads(); }
    float l1 = sm[0] + bias[1]; __syncthreads();
    if (t == 0 && out_size >= 5) {
        out[0] = l0; out[1] = l1;
        float mx = fmaxf(l0, l1);
        float e0 = expf(l0 - mx), e1 = expf(l1 - mx);
        float s = e0 + e1;
        out[2] = e0 / s; out[3] = e1 / s;
        out[4] = (l1 > l0) ? 1.f : 0.f;
    }
}

// ---------------- host orchestration ---------------------------------------

static void launch_big(const float* A, const float* B, float* C,
                       int M, int N, int K, int lda, int ldb, int ldc,
                       long long sA, long long sB, long long sC, int batch,
                       float alpha, const float* bias, const float* res, int ldres,
                       int zrows, int flags, float dcoef = 0.f)
{
    dim3 grid(N / 128, (M + 127) / 128, batch);
    if (flags & F_TRB)
        gemm_tc<128, 128, 16, 2, 4, true, 256, 2><<<grid, 256>>>(A, B, C, M, K, lda, ldb, ldc,
            sA, sB, sC, alpha, bias, res, ldres, zrows, flags, dcoef);
    else
        gemm_tc<128, 128, 16, 2, 4, false, 256, 2><<<grid, 256>>>(A, B, C, M, K, lda, ldb, ldc,
            sA, sB, sC, alpha, bias, res, ldres, zrows, flags, dcoef);
}

static void launch_small(const float* A, const float* B, float* C,
                         int M, int N, int K, int lda, int ldb, int ldc,
                         long long sA, long long sB, long long sC, int batch,
                         float alpha, const float* bias, const float* res, int ldres,
                         int zrows, int flags, float dcoef = 0.f)
{
    dim3 grid(N / 64, (M + 63) / 64, batch);
    if (flags & F_TRB)
        gemm_tc<64, 64, 16, 2, 2, true, 128, 4><<<grid, 128>>>(A, B, C, M, K, lda, ldb, ldc,
            sA, sB, sC, alpha, bias, res, ldres, zrows, flags, dcoef);
    else
        gemm_tc<64, 64, 16, 2, 2, false, 128, 4><<<grid, 128>>>(A, B, C, M, K, lda, ldb, ldc,
            sA, sB, sC, alpha, bias, res, ldres, zrows, flags, dcoef);
}

static void run_attn_layer(float* base, float* hbuf,
                           const float* lng, const float* lnb,
                           const float* qkvw, const float* outw, const float* outb,
                           const float* convw)
{
    float* xln  = base + OFF_XLN;
    float* qkv  = base + OFF_QKV;
    float* S1   = base + OFF_S1;
    float* S3   = base + OFF_S3;
    float* a2   = base + OFF_A2;
    float* Zb   = base + OFF_Z;
    float* XZ   = base + OFF_XZ;
    float* Tb   = base + OFF_T;
    float* T4   = base + OFF_T4;
    float* Pb   = base + OFF_P;
    float* ql   = base + OFF_QL;
    float* kl   = base + OFF_KL;
    float* a3v  = base + OFF_A3V;
    float* W2   = base + OFF_W2;
    float* a3p  = base + OFF_A3P;
    float* attn = base + OFF_ATTN;

    const long long sS  = (long long)NP * MLM;
    const long long sA2 = (long long)MLM * MLM;
    const long long sLM = (long long)MLM * DH;

    ln_k<<<NTOK, 256>>>(hbuf, xln, lng, lnb);

    // qkv = pad(xln) @ qkv_w
    launch_big(xln, qkvw, qkv, NP, 3 * DIM, DIM, DIM, 3 * DIM, 3 * DIM,
               0, 0, 0, 1, 1.f, nullptr, nullptr, 0, PADR, 0);

    landmark_k<<<dim3(512, 2), 256>>>(qkv, ql, kl);

    // S1 = (q*scale) @ k_l^T, softmax
    launch_big(qkv, kl, S1, NP, MLM, DH, 3 * DIM, DH, MLM,
               DH, sLM, sS, HEADS, SCALE_Q, nullptr, nullptr, 0, 0, F_TRB);
    softmax256_k<<<(HEADS * NP) / 8, 256>>>(S1);

    // S3 = (q_l*scale) @ k^T, softmax over Np
    launch_big(ql, qkv + DIM, S3, MLM, NP, DH, DH, 3 * DIM, NP,
               sLM, DH, sS, HEADS, SCALE_Q, nullptr, nullptr, 0, 0, F_TRB);
    softmax_np_k<<<HEADS * MLM, 256>>>(S3);

    // a2 = softmax((q_l*scale) @ k_l^T)
    launch_small(ql, kl, a2, MLM, MLM, DH, DH, DH, MLM,
                 sLM, sLM, sA2, HEADS, SCALE_Q, nullptr, nullptr, 0, 0, F_TRB);
    softmax256_k<<<(HEADS * MLM) / 8, 256>>>(a2);

    // Moore-Penrose pinv: 6 Newton iterations, diag epilogues fused
    pinv_init_k<<<HEADS, 256>>>(a2, Zb);
    float* Zc = Zb;
    float* Pc = Pb;
    for (int it = 0; it < 6; it++) {
        launch_small(a2, Zc, XZ, MLM, MLM, MLM, MLM, MLM, MLM,
                     sA2, sA2, sA2, HEADS, 1.f, nullptr, nullptr, 0, 0, 0);
        launch_small(XZ, XZ, Tb, MLM, MLM, MLM, MLM, MLM, MLM,
                     sA2, sA2, sA2, HEADS, 1.f, nullptr, nullptr, 0, 0, F_DIAG, 7.f);
        launch_small(XZ, Tb, T4, MLM, MLM, MLM, MLM, MLM, MLM,
                     sA2, sA2, sA2, HEADS, 1.f, nullptr, nullptr, 0, 0, F_DIAG, 15.f);
        launch_small(Zc, T4, Pc, MLM, MLM, MLM, MLM, MLM, MLM,
                     sA2, sA2, sA2, HEADS, 0.25f, nullptr, nullptr, 0, 0, F_DIAG, 13.f);
        float* tmp = Zc; Zc = Pc; Pc = tmp;
    }

    // a3v = S3 @ v : deterministic split-K x8, then reduce
    for (int s = 0; s < 8; s++) {
        launch_small(S3 + s * 1056, qkv + 2 * DIM + (long long)(s * 1056) * (3 * DIM),
                     a3p + (long long)s * (HEADS * sLM),
                     MLM, DH, 1056, NP, 3 * DIM, DH,
                     sS, DH, sLM, HEADS, 1.f, nullptr, nullptr, 0, 0, 0);
    }
    reduce8_k<<<(HEADS * (int)sLM) / 256, 256>>>(a3v, a3p);

    // W2 = pinv @ a3v
    launch_small(Zc, a3v, W2, MLM, DH, MLM, MLM, DH, DH,
                 sA2, sLM, sLM, HEADS, 1.f, nullptr, nullptr, 0, 0, 0);

    // attn = S1 @ W2
    launch_small(S1, W2, attn, NP, DH, MLM, MLM, DH, DIM,
                 sS, sLM, DH, HEADS, 1.f, nullptr, nullptr, 0, 0, 0);

    // attn += depthwise seq-conv(v)
    conv1d_add_k<<<(NP * DIM) / 256, 256>>>(attn, qkv, convw);

    // h += attn[166:] @ out_w + out_b
    launch_big(attn + (long long)PADR * DIM, outw, hbuf, NTOK, DIM, DIM,
               DIM, DIM, DIM, 0, 0, 0, 1, 1.f, outb, hbuf, DIM, 0, 0);
}

extern "C" void kernel_launch(void* const* d_in, const int* in_sizes, int n_in,
                              void* d_out, int out_size)
{
    const float* x      = (const float*)d_in[0];
    const float* fc1_w  = (const float*)d_in[1];
    const float* fc1_b  = (const float*)d_in[2];
    const float* cls    = (const float*)d_in[3];
    const float* ln1_g  = (const float*)d_in[4];
    const float* ln1_b  = (const float*)d_in[5];
    const float* qkv1_w = (const float*)d_in[6];
    const float* out1_w = (const float*)d_in[7];
    const float* out1_b = (const float*)d_in[8];
    const float* conv1w = (const float*)d_in[9];
    const float* ln2_g  = (const float*)d_in[10];
    const float* ln2_b  = (const float*)d_in[11];
    const float* qkv2_w = (const float*)d_in[12];
    const float* out2_w = (const float*)d_in[13];
    const float* out2_b = (const float*)d_in[14];
    const float* conv2w = (const float*)d_in[15];
    const float* pg7_w  = (const float*)d_in[16];
    const float* pg7_b  = (const float*)d_in[17];
    const float* pg5_w  = (const float*)d_in[18];
    const float* pg5_b  = (const float*)d_in[19];
    const float* pg3_w  = (const float*)d_in[20];
    const float* pg3_b  = (const float*)d_in[21];
    const float* norm_g = (const float*)d_in[22];
    const float* norm_b = (const float*)d_in[23];
    const float* fc2_w  = (const float*)d_in[24];
    const float* fc2_b  = (const float*)d_in[25];

    float* base = nullptr;
    cudaGetSymbolAddress((void**)&base, g_scratch);
    float* hA = base + OFF_HA;
    float* h2 = base + OFF_H2;

    // fc1 + relu into rows 1..8192 of hA
    launch_big(x, fc1_w, hA + DIM, 8192, DIM, 1024, 1024, DIM, DIM,
               0, 0, 0, 1, 1.f, fc1_b, nullptr, 0, 0, F_RELU);
    seed_k<<<(90 * DIM) / 256, 256>>>(hA, cls);

    run_attn_layer(base, hA, ln1_g, ln1_b, qkv1_w, out1_w, out1_b, conv1w);

    ppeg_k<<<(NPIX * DIM + 255) / 256, 256>>>(hA, h2, pg7_w, pg7_b, pg5_w, pg5_b, pg3_w, pg3_b);
    copy_row0_k<<<1, DIM>>>(h2, hA);

    run_attn_layer(base, h2, ln2_g, ln2_b, qkv2_w, out2_w, out2_b, conv2w);

    final_k<<<1, DIM>>>(h2, norm_g, norm_b, fc2_w, fc2_b, (float*)d_out, out_size);
}

// round 4
// speedup vs baseline: 6.0337x; 1.3187x over previous
#include <cuda_runtime.h>
#include <cstdint>

// ----------------------------------------------------------------------------
// TransMIL forward pass. tf32 tensor-core GEMMs + fused flash attention paths.
//   N_TOK=8192, IN_DIM=1024, D=512, HEADS=8, DH=64, M=256, ITERS=6, KRES=33
//   Hs=Ws=91, NPIX=8281, NTOK=8282, pad=166, Np=8448
// ----------------------------------------------------------------------------

#define NP      8448
#define NTOK    8282
#define NPIX    8281
#define HSIZE   91
#define PADR    166
#define DIM     512
#define HEADS   8
#define DH      64
#define MLM     256
#define LCH     33
#define SCALE_Q 0.125f
#define EPSLN   1e-5f
#define NSL     11          // flash KV slices (11 * 768 = 8448)
#define KPS     768

#define F_RELU  1
#define F_TRB   2
#define F_DIAG  4

// ---------------- scratch -----------------------------------------------
constexpr long long SZ_H    = (long long)NTOK * DIM;
constexpr long long SZ_QKV  = (long long)NP * 3 * DIM;
constexpr long long SZ_S    = (long long)HEADS * NP * MLM;
constexpr long long SZ_A2   = (long long)MLM * MLM * HEADS;
constexpr long long SZ_LM   = (long long)HEADS * MLM * DH;
constexpr long long SZ_ATTN = (long long)NP * DIM;

constexpr long long OFF_HA   = 0;
constexpr long long OFF_H2   = OFF_HA  + SZ_H;
constexpr long long OFF_XLN  = OFF_H2  + SZ_H;
constexpr long long OFF_QKV  = OFF_XLN + SZ_H;
constexpr long long OFF_S1   = OFF_QKV + SZ_QKV;   // reused: flash O partials
constexpr long long OFF_S3   = OFF_S1  + SZ_S;     // reused: flash m/l partials
constexpr long long OFF_A2   = OFF_S3  + SZ_S;
constexpr long long OFF_Z    = OFF_A2  + SZ_A2;
constexpr long long OFF_XZ   = OFF_Z   + SZ_A2;
constexpr long long OFF_T    = OFF_XZ  + SZ_A2;
constexpr long long OFF_T4   = OFF_T   + SZ_A2;
constexpr long long OFF_P    = OFF_T4  + SZ_A2;
constexpr long long OFF_QL   = OFF_P   + SZ_A2;
constexpr long long OFF_KL   = OFF_QL  + SZ_LM;
constexpr long long OFF_A3V  = OFF_KL  + SZ_LM;
constexpr long long OFF_W2   = OFF_A3V + SZ_LM;
constexpr long long OFF_ATTN = OFF_W2  + SZ_LM;
constexpr long long SCRATCH_TOTAL = OFF_ATTN + SZ_ATTN;

__device__ float g_scratch[SCRATCH_TOTAL];

// ---------------- mma helpers ----------------------------------------------

__device__ __forceinline__ void cpa16(uint32_t dst, const float* src, int validBytes)
{
    asm volatile("cp.async.cg.shared.global [%0], [%1], 16, %2;\n"
                 :: "r"(dst), "l"(src), "r"(validBytes));
}

__device__ __forceinline__ void mma_tf32(float* d, const uint32_t* a, const uint32_t* b)
{
    asm volatile(
        "mma.sync.aligned.m16n8k8.row.col.f32.tf32.tf32.f32 "
        "{%0,%1,%2,%3}, {%4,%5,%6,%7}, {%8,%9}, {%0,%1,%2,%3};"
        : "+f"(d[0]), "+f"(d[1]), "+f"(d[2]), "+f"(d[3])
        : "r"(a[0]), "r"(a[1]), "r"(a[2]), "r"(a[3]), "r"(b[0]), "r"(b[1]));
}

// ---------------- tensor-core tf32 GEMM -----------------------------------
template<int BM, int BN, int BK, int WM, int WN, bool TRB, int THREADS, int MAXB>
__global__ void __launch_bounds__(THREADS, MAXB)
gemm_tc(const float* __restrict__ A, const float* __restrict__ B,
        float* __restrict__ C,
        int Mr, int K, int lda, int ldb, int ldc,
        long long sA, long long sB, long long sC,
        float alpha,
        const float* __restrict__ bias,
        const float* __restrict__ res, int ldres,
        int zrows, int flags, float dcoef)
{
    constexpr int MT = BM / (WM * 16);
    constexpr int NT = BN / (WN * 8);
    constexpr int ASTR = BK + 4;
    constexpr int ASZ  = BM * ASTR;
    constexpr int BSTR = TRB ? (BK + 4) : (BN + 8);
    constexpr int BROWS = TRB ? BN : BK;
    constexpr int BSZ  = BROWS * BSTR;
    constexpr int CA = BM * BK / (4 * THREADS);
    constexpr int CB = BN * BK / (4 * THREADS);
    static_assert(CA >= 1 && CB >= 1, "chunks");
    static_assert(WM * WN == THREADS / 32, "warps");

    __shared__ float sAr[2 * ASZ];
    __shared__ float sBr[2 * BSZ];

    const int bz = blockIdx.z;
    A += bz * sA; B += bz * sB; C += bz * sC;

    const int tid = threadIdx.x;
    const int lane = tid & 31;
    const int w = tid >> 5;
    const int wm = w / WN, wn = w % WN;
    const int m0 = wm * MT * 16;
    const int n0 = wn * NT * 8;
    const int g = lane >> 2, c = lane & 3;
    const int rowBase = blockIdx.y * BM;
    const int colBase = blockIdx.x * BN;

    const uint32_t saA = (uint32_t)__cvta_generic_to_shared(sAr);
    const uint32_t saB = (uint32_t)__cvta_generic_to_shared(sBr);

    auto loadTiles = [&](int st, int k0) {
#pragma unroll
        for (int v = 0; v < CA; v++) {
            int idx = tid + v * THREADS;
            int m = idx / (BK / 4), kq = idx % (BK / 4);
            int gm = rowBase + m, am = gm - zrows;
            bool ok = (gm < Mr) && (am >= 0);
            const float* src = A + (ok ? (long long)am * lda : 0) + k0 + kq * 4;
            cpa16(saA + (uint32_t)(st * ASZ + m * ASTR + kq * 4) * 4, src, ok ? 16 : 0);
        }
        if (TRB) {
#pragma unroll
            for (int v = 0; v < CB; v++) {
                int idx = tid + v * THREADS;
                int n = idx / (BK / 4), kq = idx % (BK / 4);
                const float* src = B + (long long)(colBase + n) * ldb + k0 + kq * 4;
                cpa16(saB + (uint32_t)(st * BSZ + n * BSTR + kq * 4) * 4, src, 16);
            }
        } else {
#pragma unroll
            for (int v = 0; v < CB; v++) {
                int idx = tid + v * THREADS;
                int kk = idx / (BN / 4), nq = idx % (BN / 4);
                const float* src = B + (long long)(k0 + kk) * ldb + colBase + nq * 4;
                cpa16(saB + (uint32_t)(st * BSZ + kk * BSTR + nq * 4) * 4, src, 16);
            }
        }
    };

    float acc[MT][NT][4];
#pragma unroll
    for (int i = 0; i < MT; i++)
#pragma unroll
        for (int j = 0; j < NT; j++)
#pragma unroll
            for (int e = 0; e < 4; e++) acc[i][j][e] = 0.f;

    loadTiles(0, 0);
    asm volatile("cp.async.commit_group;");

    const int nk = K / BK;
    for (int t = 0; t < nk; t++) {
        const int st = t & 1;
        if (t + 1 < nk) {
            loadTiles(st ^ 1, (t + 1) * BK);
            asm volatile("cp.async.commit_group;");
            asm volatile("cp.async.wait_group 1;");
        } else {
            asm volatile("cp.async.wait_group 0;");
        }
        __syncthreads();

        const float* pA = sAr + st * ASZ;
        const float* pB = sBr + st * BSZ;
#pragma unroll
        for (int kk = 0; kk < BK; kk += 8) {
            uint32_t af[MT][4], bf[NT][2];
#pragma unroll
            for (int mt = 0; mt < MT; mt++) {
                int r = m0 + mt * 16 + g;
                af[mt][0] = __float_as_uint(pA[r * ASTR + kk + c]);
                af[mt][1] = __float_as_uint(pA[(r + 8) * ASTR + kk + c]);
                af[mt][2] = __float_as_uint(pA[r * ASTR + kk + 4 + c]);
                af[mt][3] = __float_as_uint(pA[(r + 8) * ASTR + kk + 4 + c]);
            }
#pragma unroll
            for (int nt = 0; nt < NT; nt++) {
                int col = n0 + nt * 8 + g;
                if (TRB) {
                    bf[nt][0] = __float_as_uint(pB[col * BSTR + kk + c]);
                    bf[nt][1] = __float_as_uint(pB[col * BSTR + kk + 4 + c]);
                } else {
                    bf[nt][0] = __float_as_uint(pB[(kk + c) * BSTR + col]);
                    bf[nt][1] = __float_as_uint(pB[(kk + 4 + c) * BSTR + col]);
                }
            }
#pragma unroll
            for (int mt = 0; mt < MT; mt++)
#pragma unroll
                for (int nt = 0; nt < NT; nt++)
                    mma_tf32(acc[mt][nt], af[mt], bf[nt]);
        }
        __syncthreads();
    }

#pragma unroll
    for (int mt = 0; mt < MT; mt++) {
#pragma unroll
        for (int nt = 0; nt < NT; nt++) {
            int gn = colBase + n0 + nt * 8 + 2 * c;
#pragma unroll
            for (int half = 0; half < 2; half++) {
                int gm = rowBase + m0 + mt * 16 + g + half * 8;
                if (gm >= Mr) continue;
#pragma unroll
                for (int e = 0; e < 2; e++) {
                    float v = acc[mt][nt][half * 2 + e];
                    int gnn = gn + e;
                    if (flags & F_DIAG) {
                        v = alpha * (dcoef * A[(long long)gm * lda + gnn] - v);
                    } else {
                        v = alpha * v;
                        if (bias) v += bias[gnn];
                        if (res)  v += res[(long long)gm * ldres + gnn];
                        if (flags & F_RELU) v = fmaxf(v, 0.f);
                    }
                    C[(long long)gm * ldc + gnn] = v;
                }
            }
        }
    }
}

// ---------------- fused flash attention kernel -----------------------------
// Computes softmax(SCALE_Q * Q @ K^T) @ V for one 64-row q-tile, streaming keys
// in chunks of 64 with online softmax.  SPLIT: write unnormalized partials
// (O, m, l) per KV slice.  !SPLIT: normalize and write to out.
template<bool SPLIT>
__global__ void __launch_bounds__(128, 3)
flash_k(const float* __restrict__ Qb, int ldq, long long sQh,
        const float* __restrict__ Kb, int ldk, long long sKh,
        const float* __restrict__ Vb, int ldv, long long sVh,
        int nchunks, int keys_per_slice,
        float* __restrict__ out, int ldo, long long sOh,
        float* __restrict__ Op, float* __restrict__ mp, float* __restrict__ lp,
        int nslices, int nqt)
{
    extern __shared__ float smf[];
    float* sQ = smf;                 // 64 x 68
    float* sK = smf + 64 * 68;
    float* sV = smf + 2 * 64 * 68;
    float* sP = smf + 3 * 64 * 68;

    const int h = blockIdx.z, qt = blockIdx.x;
    const int sl = SPLIT ? blockIdx.y : 0;
    const float* Q = Qb + h * sQh + (long long)qt * 64 * ldq;
    const float* K = Kb + h * sKh + (long long)sl * keys_per_slice * ldk;
    const float* V = Vb + h * sVh + (long long)sl * keys_per_slice * ldv;

    const int tid = threadIdx.x, lane = tid & 31, w = tid >> 5;
    const int g = lane >> 2, c = lane & 3;
    const int wr = w * 16;

    // load Q tile
    for (int i = tid; i < 64 * 16; i += 128) {
        int r = i >> 4, q4 = (i & 15) * 4;
        *reinterpret_cast<float4*>(sQ + r * 68 + q4) =
            *reinterpret_cast<const float4*>(Q + (long long)r * ldq + q4);
    }

    float m0 = -1e30f, m1 = -1e30f, l0 = 0.f, l1 = 0.f;
    float Oacc[8][4];
#pragma unroll
    for (int nt = 0; nt < 8; nt++)
#pragma unroll
        for (int e = 0; e < 4; e++) Oacc[nt][e] = 0.f;

    for (int ch = 0; ch < nchunks; ch++) {
        __syncthreads();
        const float* Kc = K + (long long)ch * 64 * ldk;
        const float* Vc = V + (long long)ch * 64 * ldv;
        for (int i = tid; i < 64 * 16; i += 128) {
            int r = i >> 4, q4 = (i & 15) * 4;
            *reinterpret_cast<float4*>(sK + r * 68 + q4) =
                *reinterpret_cast<const float4*>(Kc + (long long)r * ldk + q4);
            *reinterpret_cast<float4*>(sV + r * 68 + q4) =
                *reinterpret_cast<const float4*>(Vc + (long long)r * ldv + q4);
        }
        __syncthreads();

        // logits: L = Q @ K^T  (64x64 per block, 16 rows per warp)
        float lacc[8][4];
#pragma unroll
        for (int nt = 0; nt < 8; nt++)
#pragma unroll
            for (int e = 0; e < 4; e++) lacc[nt][e] = 0.f;
#pragma unroll
        for (int kk = 0; kk < 64; kk += 8) {
            uint32_t a[4];
            a[0] = __float_as_uint(sQ[(wr + g) * 68 + kk + c]);
            a[1] = __float_as_uint(sQ[(wr + g + 8) * 68 + kk + c]);
            a[2] = __float_as_uint(sQ[(wr + g) * 68 + kk + 4 + c]);
            a[3] = __float_as_uint(sQ[(wr + g + 8) * 68 + kk + 4 + c]);
#pragma unroll
            for (int nt = 0; nt < 8; nt++) {
                uint32_t b[2];
                b[0] = __float_as_uint(sK[(nt * 8 + g) * 68 + kk + c]);
                b[1] = __float_as_uint(sK[(nt * 8 + g) * 68 + kk + 4 + c]);
                mma_tf32(lacc[nt], a, b);
            }
        }

        // online softmax update
        float cm0 = -1e30f, cm1 = -1e30f;
#pragma unroll
        for (int nt = 0; nt < 8; nt++) {
            lacc[nt][0] *= SCALE_Q; lacc[nt][1] *= SCALE_Q;
            lacc[nt][2] *= SCALE_Q; lacc[nt][3] *= SCALE_Q;
            cm0 = fmaxf(cm0, fmaxf(lacc[nt][0], lacc[nt][1]));
            cm1 = fmaxf(cm1, fmaxf(lacc[nt][2], lacc[nt][3]));
        }
        cm0 = fmaxf(cm0, __shfl_xor_sync(0xffffffffu, cm0, 1));
        cm0 = fmaxf(cm0, __shfl_xor_sync(0xffffffffu, cm0, 2));
        cm1 = fmaxf(cm1, __shfl_xor_sync(0xffffffffu, cm1, 1));
        cm1 = fmaxf(cm1, __shfl_xor_sync(0xffffffffu, cm1, 2));
        float nm0 = fmaxf(m0, cm0), nm1 = fmaxf(m1, cm1);
        float f0 = __expf(m0 - nm0), f1 = __expf(m1 - nm1);
        float rs0 = 0.f, rs1 = 0.f;
#pragma unroll
        for (int nt = 0; nt < 8; nt++) {
            float p0 = __expf(lacc[nt][0] - nm0);
            float p1 = __expf(lacc[nt][1] - nm0);
            float p2 = __expf(lacc[nt][2] - nm1);
            float p3 = __expf(lacc[nt][3] - nm1);
            rs0 += p0 + p1; rs1 += p2 + p3;
            sP[(wr + g) * 68 + nt * 8 + 2 * c]     = p0;
            sP[(wr + g) * 68 + nt * 8 + 2 * c + 1] = p1;
            sP[(wr + g + 8) * 68 + nt * 8 + 2 * c]     = p2;
            sP[(wr + g + 8) * 68 + nt * 8 + 2 * c + 1] = p3;
        }
        rs0 += __shfl_xor_sync(0xffffffffu, rs0, 1);
        rs0 += __shfl_xor_sync(0xffffffffu, rs0, 2);
        rs1 += __shfl_xor_sync(0xffffffffu, rs1, 1);
        rs1 += __shfl_xor_sync(0xffffffffu, rs1, 2);
        l0 = l0 * f0 + rs0; l1 = l1 * f1 + rs1;
        m0 = nm0; m1 = nm1;
#pragma unroll
        for (int nt = 0; nt < 8; nt++) {
            Oacc[nt][0] *= f0; Oacc[nt][1] *= f0;
            Oacc[nt][2] *= f1; Oacc[nt][3] *= f1;
        }
        __syncwarp();

        // O += P @ V
#pragma unroll
        for (int kk = 0; kk < 64; kk += 8) {
            uint32_t a[4];
            a[0] = __float_as_uint(sP[(wr + g) * 68 + kk + c]);
            a[1] = __float_as_uint(sP[(wr + g + 8) * 68 + kk + c]);
            a[2] = __float_as_uint(sP[(wr + g) * 68 + kk + 4 + c]);
            a[3] = __float_as_uint(sP[(wr + g + 8) * 68 + kk + 4 + c]);
#pragma unroll
            for (int nt = 0; nt < 8; nt++) {
                uint32_t b[2];
                b[0] = __float_as_uint(sV[(kk + c) * 68 + nt * 8 + g]);
                b[1] = __float_as_uint(sV[(kk + 4 + c) * 68 + nt * 8 + g]);
                mma_tf32(Oacc[nt], a, b);
            }
        }
    }

    if (SPLIT) {
        long long pb = ((long long)(h * nqt + qt) * nslices + sl) * 64;
#pragma unroll
        for (int nt = 0; nt < 8; nt++) {
            Op[(pb + wr + g) * 64 + nt * 8 + 2 * c]     = Oacc[nt][0];
            Op[(pb + wr + g) * 64 + nt * 8 + 2 * c + 1] = Oacc[nt][1];
            Op[(pb + wr + g + 8) * 64 + nt * 8 + 2 * c]     = Oacc[nt][2];
            Op[(pb + wr + g + 8) * 64 + nt * 8 + 2 * c + 1] = Oacc[nt][3];
        }
        if (c == 0) {
            mp[pb + wr + g] = m0; lp[pb + wr + g] = l0;
            mp[pb + wr + g + 8] = m1; lp[pb + wr + g + 8] = l1;
        }
    } else {
        float inv0 = 1.f / l0, inv1 = 1.f / l1;
        float* o0 = out + h * sOh + (long long)(qt * 64 + wr + g) * ldo;
        float* o1 = out + h * sOh + (long long)(qt * 64 + wr + g + 8) * ldo;
#pragma unroll
        for (int nt = 0; nt < 8; nt++) {
            o0[nt * 8 + 2 * c]     = Oacc[nt][0] * inv0;
            o0[nt * 8 + 2 * c + 1] = Oacc[nt][1] * inv0;
            o1[nt * 8 + 2 * c]     = Oacc[nt][2] * inv1;
            o1[nt * 8 + 2 * c + 1] = Oacc[nt][3] * inv1;
        }
    }
}

// combine flash partials: a3v[h][r][d] over NSL slices
__global__ void fcomb_k(const float* __restrict__ Op, const float* __restrict__ mp,
                        const float* __restrict__ lp, float* __restrict__ a3v)
{
    int idx = blockIdx.x * 256 + threadIdx.x;        // HEADS*MLM*DH
    int col = idx & 63, r = (idx >> 6) & 255, h = idx >> 14;
    int qt = r >> 6, rr = r & 63;
    long long hq = (long long)(h * 4 + qt) * NSL;
    float mx = -1e30f;
#pragma unroll
    for (int s = 0; s < NSL; s++) mx = fmaxf(mx, mp[(hq + s) * 64 + rr]);
    float num = 0.f, den = 0.f;
#pragma unroll
    for (int s = 0; s < NSL; s++) {
        float wgt = __expf(mp[(hq + s) * 64 + rr] - mx);
        den += wgt * lp[(hq + s) * 64 + rr];
        num += wgt * Op[((hq + s) * 64 + rr) * 64 + col];
    }
    a3v[idx] = num / den;
}

// ---------------- small kernels --------------------------------------------

__global__ void softmax256_k(float* __restrict__ S)
{
    long long row = (long long)blockIdx.x * 8 + (threadIdx.x >> 5);
    int lane = threadIdx.x & 31;
    float* p = S + row * 256 + lane * 8;
    float4 a = *reinterpret_cast<float4*>(p);
    float4 b = *reinterpret_cast<float4*>(p + 4);
    float m = fmaxf(fmaxf(fmaxf(a.x, a.y), fmaxf(a.z, a.w)),
                    fmaxf(fmaxf(b.x, b.y), fmaxf(b.z, b.w)));
#pragma unroll
    for (int o = 16; o; o >>= 1) m = fmaxf(m, __shfl_xor_sync(0xffffffffu, m, o));
    a.x = __expf(a.x - m); a.y = __expf(a.y - m); a.z = __expf(a.z - m); a.w = __expf(a.w - m);
    b.x = __expf(b.x - m); b.y = __expf(b.y - m); b.z = __expf(b.z - m); b.w = __expf(b.w - m);
    float s = a.x + a.y + a.z + a.w + b.x + b.y + b.z + b.w;
#pragma unroll
    for (int o = 16; o; o >>= 1) s += __shfl_xor_sync(0xffffffffu, s, o);
    float inv = 1.f / s;
    a.x *= inv; a.y *= inv; a.z *= inv; a.w *= inv;
    b.x *= inv; b.y *= inv; b.z *= inv; b.w *= inv;
    *reinterpret_cast<float4*>(p) = a;
    *reinterpret_cast<float4*>(p + 4) = b;
}

__global__ void ln_k(const float* __restrict__ x, float* __restrict__ y,
                     const float* __restrict__ g, const float* __restrict__ b)
{
    long long row = blockIdx.x;
    const float* xr = x + row * DIM;
    float* yr = y + row * DIM;
    int t = threadIdx.x;
    float v0 = xr[t], v1 = xr[t + 256];
    __shared__ float sm[256];
    sm[t] = v0 + v1; __syncthreads();
    for (int s = 128; s > 0; s >>= 1) { if (t < s) sm[t] += sm[t + s]; __syncthreads(); }
    float mu = sm[0] * (1.f / DIM); __syncthreads();
    float d0 = v0 - mu, d1 = v1 - mu;
    sm[t] = d0 * d0 + d1 * d1; __syncthreads();
    for (int s = 128; s > 0; s >>= 1) { if (t < s) sm[t] += sm[t + s]; __syncthreads(); }
    float rs = rsqrtf(sm[0] * (1.f / DIM) + EPSLN); __syncthreads();
    yr[t]       = d0 * rs * g[t]       + b[t];
    yr[t + 256] = d1 * rs * g[t + 256] + b[t + 256];
}

__global__ void landmark_k(const float* __restrict__ qkv,
                           float* __restrict__ ql, float* __restrict__ kl)
{
    int idx = blockIdx.x * 256 + threadIdx.x;
    int d = idx & 63, m = (idx >> 6) & 255, h = idx >> 14;
    int off = (blockIdx.y == 0) ? 0 : DIM;
    float s = 0.f;
    const float* src = qkv + off + h * DH + d;
#pragma unroll
    for (int j = 0; j < LCH; j++)
        s += src[(long long)(m * LCH + j) * (3 * DIM)];
    float* dst = (blockIdx.y == 0) ? ql : kl;
    dst[h * (MLM * DH) + m * DH + d] = s * (1.f / LCH);
}

__global__ void pinv_init_k(const float* __restrict__ A2, float* __restrict__ Z)
{
    int h = blockIdx.x;
    const float* A = A2 + (long long)h * MLM * MLM;
    float* Zh = Z + (long long)h * MLM * MLM;
    int t = threadIdx.x;
    float rs = 0.f, cs = 0.f;
    for (int j = 0; j < MLM; j++) {
        rs += fabsf(A[t * MLM + j]);
        cs += fabsf(A[j * MLM + t]);
    }
    __shared__ float s1[256], s2[256];
    s1[t] = rs; s2[t] = cs; __syncthreads();
    for (int s = 128; s > 0; s >>= 1) {
        if (t < s) { s1[t] = fmaxf(s1[t], s1[t + s]); s2[t] = fmaxf(s2[t], s2[t + s]); }
        __syncthreads();
    }
    float scale = 1.f / (s1[0] * s2[0]);
    __syncthreads();
    for (int j = 0; j < MLM; j++)
        Zh[t * MLM + j] = A[j * MLM + t] * scale;
}

__global__ void conv1d_add_k(float* __restrict__ attn, const float* __restrict__ qkv,
                             const float* __restrict__ w)
{
    int idx = blockIdx.x * 256 + threadIdx.x;
    int i = idx >> 9, c = idx & 511, h = c >> 6;
    float acc = 0.f;
#pragma unroll
    for (int t = 0; t < 33; t++) {
        int j = i + t - 16;
        if (j >= 0 && j < NP)
            acc += w[h * 33 + t] * qkv[(long long)j * (3 * DIM) + 2 * DIM + c];
    }
    attn[idx] += acc;
}

__global__ void seed_k(float* __restrict__ hA, const float* __restrict__ cls)
{
    int idx = blockIdx.x * 256 + threadIdx.x;
    if (idx < DIM) hA[idx] = cls[idx];
    int j = idx - DIM;
    if (j >= 0 && j < 89 * DIM) {
        int r = j >> 9, c = j & 511;
        hA[(long long)(1 + 8192 + r) * DIM + c] = hA[(long long)(1 + r) * DIM + c];
    }
}

__global__ void ppeg_k(const float* __restrict__ hA, float* __restrict__ h2,
                       const float* __restrict__ w7, const float* __restrict__ b7,
                       const float* __restrict__ w5, const float* __restrict__ b5,
                       const float* __restrict__ w3, const float* __restrict__ b3)
{
    int idx = blockIdx.x * 256 + threadIdx.x;
    if (idx >= NPIX * DIM) return;
    int tok = idx >> 9, ch = idx & 511;
    int r = tok / HSIZE, cc = tok % HSIZE;
    float acc = hA[(long long)(1 + tok) * DIM + ch] + b7[ch] + b5[ch] + b3[ch];
#pragma unroll
    for (int u = -3; u <= 3; u++) {
        int rr = r + u;
        if (rr < 0 || rr >= HSIZE) continue;
#pragma unroll
        for (int v = -3; v <= 3; v++) {
            int c2 = cc + v;
            if (c2 < 0 || c2 >= HSIZE) continue;
            float f = hA[(long long)(1 + rr * HSIZE + c2) * DIM + ch];
            float w = w7[ch * 49 + (u + 3) * 7 + (v + 3)];
            if (u >= -2 && u <= 2 && v >= -2 && v <= 2)
                w += w5[ch * 25 + (u + 2) * 5 + (v + 2)];
            if (u >= -1 && u <= 1 && v >= -1 && v <= 1)
                w += w3[ch * 9 + (u + 1) * 3 + (v + 1)];
            acc += w * f;
        }
    }
    h2[(long long)(1 + tok) * DIM + ch] = acc;
}

__global__ void copy_row0_k(float* __restrict__ h2, const float* __restrict__ hA)
{
    h2[threadIdx.x] = hA[threadIdx.x];
}

__global__ void final_k(const float* __restrict__ h, const float* __restrict__ g,
                        const float* __restrict__ b, const float* __restrict__ w,
                        const float* __restrict__ bias, float* __restrict__ out,
                        int out_size)
{
    int t = threadIdx.x;
    __shared__ float sm[512];
    float v = h[t];
    sm[t] = v; __syncthreads();
    for (int s = 256; s > 0; s >>= 1) { if (t < s) sm[t] += sm[t + s]; __syncthreads(); }
    float mu = sm[0] * (1.f / DIM); __syncthreads();
    float d = v - mu;
    sm[t] = d * d; __syncthreads();
    for (int s = 256; s > 0; s >>= 1) { if (t < s) sm[t] += sm[t + s]; __syncthreads(); }
    float rs = rsqrtf(sm[0] * (1.f / DIM) + EPSLN); __syncthreads();
    float e = d * rs * g[t] + b[t];
    if (5 + t < out_size) out[5 + t] = e;
    sm[t] = e * w[t * 2]; __syncthreads();
    for (int s = 256; s > 0; s >>= 1) { if (t < s) sm[t] += sm[t + s]; __syncthreads(); }
    float l0 = sm[0] + bias[0]; __syncthreads();
    sm[t] = e * w[t * 2 + 1]; __syncthreads();
    for (int s = 256; s > 0; s >>= 1) { if (t < s) sm[t] += sm[t + s]; __syncthreads(); }
    float l1 = sm[0] + bias[1]; __syncthreads();
    if (t == 0 && out_size >= 5) {
        out[0] = l0; out[1] = l1;
        float mx = fmaxf(l0, l1);
        float e0 = expf(l0 - mx), e1 = expf(l1 - mx);
        float s = e0 + e1;
        out[2] = e0 / s; out[3] = e1 / s;
        out[4] = (l1 > l0) ? 1.f : 0.f;
    }
}

// ---------------- host orchestration ---------------------------------------

constexpr int FLASH_SMEM = 4 * 64 * 68 * 4;   // 69632 bytes

static void launch_big(const float* A, const float* B, float* C,
                       int M, int N, int K, int lda, int ldb, int ldc,
                       long long sA, long long sB, long long sC, int batch,
                       float alpha, const float* bias, const float* res, int ldres,
                       int zrows, int flags, float dcoef = 0.f)
{
    dim3 grid(N / 128, (M + 127) / 128, batch);
    if (flags & F_TRB)
        gemm_tc<128, 128, 16, 2, 4, true, 256, 2><<<grid, 256>>>(A, B, C, M, K, lda, ldb, ldc,
            sA, sB, sC, alpha, bias, res, ldres, zrows, flags, dcoef);
    else
        gemm_tc<128, 128, 16, 2, 4, false, 256, 2><<<grid, 256>>>(A, B, C, M, K, lda, ldb, ldc,
            sA, sB, sC, alpha, bias, res, ldres, zrows, flags, dcoef);
}

static void launch_small(const float* A, const float* B, float* C,
                         int M, int N, int K, int lda, int ldb, int ldc,
                         long long sA, long long sB, long long sC, int batch,
                         float alpha, const float* bias, const float* res, int ldres,
                         int zrows, int flags, float dcoef = 0.f)
{
    dim3 grid(N / 64, (M + 63) / 64, batch);
    if (flags & F_TRB)
        gemm_tc<64, 64, 16, 2, 2, true, 128, 4><<<grid, 128>>>(A, B, C, M, K, lda, ldb, ldc,
            sA, sB, sC, alpha, bias, res, ldres, zrows, flags, dcoef);
    else
        gemm_tc<64, 64, 16, 2, 2, false, 128, 4><<<grid, 128>>>(A, B, C, M, K, lda, ldb, ldc,
            sA, sB, sC, alpha, bias, res, ldres, zrows, flags, dcoef);
}

static void run_attn_layer(float* base, float* hbuf,
                           const float* lng, const float* lnb,
                           const float* qkvw, const float* outw, const float* outb,
                           const float* convw)
{
    float* xln  = base + OFF_XLN;
    float* qkv  = base + OFF_QKV;
    float* Opar = base + OFF_S1;
    float* mpar = base + OFF_S3;
    float* lpar = base + OFF_S3 + 32768;
    float* a2   = base + OFF_A2;
    float* Zb   = base + OFF_Z;
    float* XZ   = base + OFF_XZ;
    float* Tb   = base + OFF_T;
    float* T4   = base + OFF_T4;
    float* Pb   = base + OFF_P;
    float* ql   = base + OFF_QL;
    float* kl   = base + OFF_KL;
    float* a3v  = base + OFF_A3V;
    float* W2   = base + OFF_W2;
    float* attn = base + OFF_ATTN;

    const long long sA2 = (long long)MLM * MLM;
    const long long sLM = (long long)MLM * DH;

    ln_k<<<NTOK, 256>>>(hbuf, xln, lng, lnb);

    // qkv = pad(xln) @ qkv_w
    launch_big(xln, qkvw, qkv, NP, 3 * DIM, DIM, DIM, 3 * DIM, 3 * DIM,
               0, 0, 0, 1, 1.f, nullptr, nullptr, 0, PADR, 0);

    landmark_k<<<dim3(512, 2), 256>>>(qkv, ql, kl);

    // flash: partials of softmax(ql @ k^T) @ v over 11 KV slices
    flash_k<true><<<dim3(4, NSL, HEADS), 128, FLASH_SMEM>>>(
        ql, DH, sLM,
        qkv + DIM, 3 * DIM, DH,
        qkv + 2 * DIM, 3 * DIM, DH,
        KPS / 64, KPS,
        nullptr, 0, 0,
        Opar, mpar, lpar, NSL, 4);
    fcomb_k<<<(HEADS * (int)sLM) / 256, 256>>>(Opar, mpar, lpar, a3v);

    // a2 = softmax((ql*scale) @ kl^T)
    launch_small(ql, kl, a2, MLM, MLM, DH, DH, DH, MLM,
                 sLM, sLM, sA2, HEADS, SCALE_Q, nullptr, nullptr, 0, 0, F_TRB);
    softmax256_k<<<(HEADS * MLM) / 8, 256>>>(a2);

    // Moore-Penrose pinv: 6 Newton iterations, diag epilogues fused
    pinv_init_k<<<HEADS, 256>>>(a2, Zb);
    float* Zc = Zb;
    float* Pc = Pb;
    for (int it = 0; it < 6; it++) {
        launch_small(a2, Zc, XZ, MLM, MLM, MLM, MLM, MLM, MLM,
                     sA2, sA2, sA2, HEADS, 1.f, nullptr, nullptr, 0, 0, 0);
        launch_small(XZ, XZ, Tb, MLM, MLM, MLM, MLM, MLM, MLM,
                     sA2, sA2, sA2, HEADS, 1.f, nullptr, nullptr, 0, 0, F_DIAG, 7.f);
        launch_small(XZ, Tb, T4, MLM, MLM, MLM, MLM, MLM, MLM,
                     sA2, sA2, sA2, HEADS, 1.f, nullptr, nullptr, 0, 0, F_DIAG, 15.f);
        launch_small(Zc, T4, Pc, MLM, MLM, MLM, MLM, MLM, MLM,
                     sA2, sA2, sA2, HEADS, 0.25f, nullptr, nullptr, 0, 0, F_DIAG, 13.f);
        float* tmp = Zc; Zc = Pc; Pc = tmp;
    }

    // W2 = pinv @ a3v
    launch_small(Zc, a3v, W2, MLM, DH, MLM, MLM, DH, DH,
                 sA2, sLM, sLM, HEADS, 1.f, nullptr, nullptr, 0, 0, 0);

    // attn = softmax(q @ kl^T) @ W2   (fused, no S1 materialization)
    flash_k<false><<<dim3(NP / 64, 1, HEADS), 128, FLASH_SMEM>>>(
        qkv, 3 * DIM, DH,
        kl, DH, sLM,
        W2, DH, sLM,
        MLM / 64, MLM,
        attn, DIM, DH,
        nullptr, nullptr, nullptr, 1, NP / 64);

    // attn += depthwise seq-conv(v)
    conv1d_add_k<<<(NP * DIM) / 256, 256>>>(attn, qkv, convw);

    // h += attn[166:] @ out_w + out_b
    launch_big(attn + (long long)PADR * DIM, outw, hbuf, NTOK, DIM, DIM,
               DIM, DIM, DIM, 0, 0, 0, 1, 1.f, outb, hbuf, DIM, 0, 0);
}

extern "C" void kernel_launch(void* const* d_in, const int* in_sizes, int n_in,
                              void* d_out, int out_size)
{
    const float* x      = (const float*)d_in[0];
    const float* fc1_w  = (const float*)d_in[1];
    const float* fc1_b  = (const float*)d_in[2];
    const float* cls    = (const float*)d_in[3];
    const float* ln1_g  = (const float*)d_in[4];
    const float* ln1_b  = (const float*)d_in[5];
    const float* qkv1_w = (const float*)d_in[6];
    const float* out1_w = (const float*)d_in[7];
    const float* out1_b = (const float*)d_in[8];
    const float* conv1w = (const float*)d_in[9];
    const float* ln2_g  = (const float*)d_in[10];
    const float* ln2_b  = (const float*)d_in[11];
    const float* qkv2_w = (const float*)d_in[12];
    const float* out2_w = (const float*)d_in[13];
    const float* out2_b = (const float*)d_in[14];
    const float* conv2w = (const float*)d_in[15];
    const float* pg7_w  = (const float*)d_in[16];
    const float* pg7_b  = (const float*)d_in[17];
    const float* pg5_w  = (const float*)d_in[18];
    const float* pg5_b  = (const float*)d_in[19];
    const float* pg3_w  = (const float*)d_in[20];
    const float* pg3_b  = (const float*)d_in[21];
    const float* norm_g = (const float*)d_in[22];
    const float* norm_b = (const float*)d_in[23];
    const float* fc2_w  = (const float*)d_in[24];
    const float* fc2_b  = (const float*)d_in[25];

    cudaFuncSetAttribute(flash_k<true>,  cudaFuncAttributeMaxDynamicSharedMemorySize, FLASH_SMEM);
    cudaFuncSetAttribute(flash_k<false>, cudaFuncAttributeMaxDynamicSharedMemorySize, FLASH_SMEM);

    float* base = nullptr;
    cudaGetSymbolAddress((void**)&base, g_scratch);
    float* hA = base + OFF_HA;
    float* h2 = base + OFF_H2;

    // fc1 + relu into rows 1..8192 of hA
    launch_big(x, fc1_w, hA + DIM, 8192, DIM, 1024, 1024, DIM, DIM,
               0, 0, 0, 1, 1.f, fc1_b, nullptr, 0, 0, F_RELU);
    seed_k<<<(90 * DIM) / 256, 256>>>(hA, cls);

    run_attn_layer(base, hA, ln1_g, ln1_b, qkv1_w, out1_w, out1_b, conv1w);

    ppeg_k<<<(NPIX * DIM + 255) / 256, 256>>>(hA, h2, pg7_w, pg7_b, pg5_w, pg5_b, pg3_w, pg3_b);
    copy_row0_k<<<1, DIM>>>(h2, hA);

    run_attn_layer(base, h2, ln2_g, ln2_b, qkv2_w, out2_w, out2_b, conv2w);

    final_k<<<1, DIM>>>(h2, norm_g, norm_b, fc2_w, fc2_b, (float*)d_out, out_size);
}

// round 5
// speedup vs baseline: 7.7907x; 1.2912x over previous
#include <cuda_runtime.h>
#include <cstdint>

// ----------------------------------------------------------------------------
// TransMIL forward pass. tf32 tensor-core GEMMs (3-stage cp.async) + fused
// flash attention + tiled depthwise convs.
// ----------------------------------------------------------------------------

#define NP      8448
#define NTOK    8282
#define NPIX    8281
#define HSIZE   91
#define PADR    166
#define DIM     512
#define HEADS   8
#define DH      64
#define MLM     256
#define LCH     33
#define SCALE_Q 0.125f
#define EPSLN   1e-5f
#define NSL     11
#define KPS     768

#define F_RELU  1
#define F_TRB   2
#define F_DIAG  4

// ---------------- scratch -----------------------------------------------
constexpr long long SZ_H    = (long long)NTOK * DIM;
constexpr long long SZ_QKV  = (long long)NP * 3 * DIM;
constexpr long long SZ_S    = (long long)HEADS * NP * MLM;
constexpr long long SZ_A2   = (long long)MLM * MLM * HEADS;
constexpr long long SZ_LM   = (long long)HEADS * MLM * DH;
constexpr long long SZ_ATTN = (long long)NP * DIM;

constexpr long long OFF_HA   = 0;
constexpr long long OFF_H2   = OFF_HA  + SZ_H;
constexpr long long OFF_XLN  = OFF_H2  + SZ_H;
constexpr long long OFF_QKV  = OFF_XLN + SZ_H;
constexpr long long OFF_S1   = OFF_QKV + SZ_QKV;   // flash O partials
constexpr long long OFF_S3   = OFF_S1  + SZ_S;     // flash m/l partials
constexpr long long OFF_A2   = OFF_S3  + SZ_S;
constexpr long long OFF_Z    = OFF_A2  + SZ_A2;
constexpr long long OFF_XZ   = OFF_Z   + SZ_A2;
constexpr long long OFF_T    = OFF_XZ  + SZ_A2;
constexpr long long OFF_T4   = OFF_T   + SZ_A2;
constexpr long long OFF_P    = OFF_T4  + SZ_A2;
constexpr long long OFF_QL   = OFF_P   + SZ_A2;
constexpr long long OFF_KL   = OFF_QL  + SZ_LM;
constexpr long long OFF_A3V  = OFF_KL  + SZ_LM;
constexpr long long OFF_W2   = OFF_A3V + SZ_LM;
constexpr long long OFF_ATTN = OFF_W2  + SZ_LM;
constexpr long long SCRATCH_TOTAL = OFF_ATTN + SZ_ATTN;

__device__ float g_scratch[SCRATCH_TOTAL];

// ---------------- mma helpers ----------------------------------------------

__device__ __forceinline__ void cpa16(uint32_t dst, const float* src, int validBytes)
{
    asm volatile("cp.async.cg.shared.global [%0], [%1], 16, %2;\n"
                 :: "r"(dst), "l"(src), "r"(validBytes));
}

__device__ __forceinline__ void mma_tf32(float* d, const uint32_t* a, const uint32_t* b)
{
    asm volatile(
        "mma.sync.aligned.m16n8k8.row.col.f32.tf32.tf32.f32 "
        "{%0,%1,%2,%3}, {%4,%5,%6,%7}, {%8,%9}, {%0,%1,%2,%3};"
        : "+f"(d[0]), "+f"(d[1]), "+f"(d[2]), "+f"(d[3])
        : "r"(a[0]), "r"(a[1]), "r"(a[2]), "r"(a[3]), "r"(b[0]), "r"(b[1]));
}

// ---------------- tensor-core tf32 GEMM, 3-stage pipeline ------------------
// C[M,N] = epilogue(alpha * A_eff @ B); A_eff row i = (i<zrows)?0:A[i-zrows].
// TRB: B is [N,K] row-major.  F_DIAG: C = alpha*(dcoef*A - acc).
// Requires K % BK == 0, N % BN == 0.
template<int BM, int BN, int BK, int WM, int WN, bool TRB, int THREADS, int MAXB>
__global__ void __launch_bounds__(THREADS, MAXB)
gemm_tc(const float* __restrict__ A, const float* __restrict__ B,
        float* __restrict__ C,
        int Mr, int K, int lda, int ldb, int ldc,
        long long sA, long long sB, long long sC,
        float alpha,
        const float* __restrict__ bias,
        const float* __restrict__ res, int ldres,
        int zrows, int flags, float dcoef)
{
    constexpr int MT = BM / (WM * 16);
    constexpr int NT = BN / (WN * 8);
    constexpr int ASTR = BK + 4;
    constexpr int ASZ  = BM * ASTR;
    constexpr int BSTR = TRB ? (BK + 4) : (BN + 8);
    constexpr int BROWS = TRB ? BN : BK;
    constexpr int BSZ  = BROWS * BSTR;
    constexpr int CA = BM * BK / (4 * THREADS);
    constexpr int CB = BN * BK / (4 * THREADS);
    static_assert(CA >= 1 && CB >= 1, "chunks");
    static_assert(WM * WN == THREADS / 32, "warps");

    extern __shared__ float dynsm[];
    float* sAr = dynsm;
    float* sBr = dynsm + 3 * ASZ;

    const int bz = blockIdx.z;
    A += bz * sA; B += bz * sB; C += bz * sC;

    const int tid = threadIdx.x;
    const int lane = tid & 31;
    const int w = tid >> 5;
    const int wm = w / WN, wn = w % WN;
    const int m0 = wm * MT * 16;
    const int n0 = wn * NT * 8;
    const int g = lane >> 2, c = lane & 3;
    const int rowBase = blockIdx.y * BM;
    const int colBase = blockIdx.x * BN;

    const uint32_t saA = (uint32_t)__cvta_generic_to_shared(sAr);
    const uint32_t saB = (uint32_t)__cvta_generic_to_shared(sBr);

    auto loadTiles = [&](int st, int k0) {
#pragma unroll
        for (int v = 0; v < CA; v++) {
            int idx = tid + v * THREADS;
            int m = idx / (BK / 4), kq = idx % (BK / 4);
            int gm = rowBase + m, am = gm - zrows;
            bool ok = (gm < Mr) && (am >= 0);
            const float* src = A + (ok ? (long long)am * lda : 0) + k0 + kq * 4;
            cpa16(saA + (uint32_t)(st * ASZ + m * ASTR + kq * 4) * 4, src, ok ? 16 : 0);
        }
        if (TRB) {
#pragma unroll
            for (int v = 0; v < CB; v++) {
                int idx = tid + v * THREADS;
                int n = idx / (BK / 4), kq = idx % (BK / 4);
                const float* src = B + (long long)(colBase + n) * ldb + k0 + kq * 4;
                cpa16(saB + (uint32_t)(st * BSZ + n * BSTR + kq * 4) * 4, src, 16);
            }
        } else {
#pragma unroll
            for (int v = 0; v < CB; v++) {
                int idx = tid + v * THREADS;
                int kk = idx / (BN / 4), nq = idx % (BN / 4);
                const float* src = B + (long long)(k0 + kk) * ldb + colBase + nq * 4;
                cpa16(saB + (uint32_t)(st * BSZ + kk * BSTR + nq * 4) * 4, src, 16);
            }
        }
    };

    float acc[MT][NT][4];
#pragma unroll
    for (int i = 0; i < MT; i++)
#pragma unroll
        for (int j = 0; j < NT; j++)
#pragma unroll
            for (int e = 0; e < 4; e++) acc[i][j][e] = 0.f;

    const int nk = K / BK;
    loadTiles(0, 0);
    asm volatile("cp.async.commit_group;");
    if (nk > 1) loadTiles(1, BK);
    asm volatile("cp.async.commit_group;");

    for (int t = 0; t < nk; t++) {
        if (t + 1 < nk) { asm volatile("cp.async.wait_group 1;"); }
        else            { asm volatile("cp.async.wait_group 0;"); }
        __syncthreads();
        if (t + 2 < nk) {
            loadTiles((t + 2) % 3, (t + 2) * BK);
            asm volatile("cp.async.commit_group;");
        }

        const int st = t % 3;
        const float* pA = sAr + st * ASZ;
        const float* pB = sBr + st * BSZ;
#pragma unroll
        for (int kk = 0; kk < BK; kk += 8) {
            uint32_t af[MT][4], bf[NT][2];
#pragma unroll
            for (int mt = 0; mt < MT; mt++) {
                int r = m0 + mt * 16 + g;
                af[mt][0] = __float_as_uint(pA[r * ASTR + kk + c]);
                af[mt][1] = __float_as_uint(pA[(r + 8) * ASTR + kk + c]);
                af[mt][2] = __float_as_uint(pA[r * ASTR + kk + 4 + c]);
                af[mt][3] = __float_as_uint(pA[(r + 8) * ASTR + kk + 4 + c]);
            }
#pragma unroll
            for (int nt = 0; nt < NT; nt++) {
                int col = n0 + nt * 8 + g;
                if (TRB) {
                    bf[nt][0] = __float_as_uint(pB[col * BSTR + kk + c]);
                    bf[nt][1] = __float_as_uint(pB[col * BSTR + kk + 4 + c]);
                } else {
                    bf[nt][0] = __float_as_uint(pB[(kk + c) * BSTR + col]);
                    bf[nt][1] = __float_as_uint(pB[(kk + 4 + c) * BSTR + col]);
                }
            }
#pragma unroll
            for (int mt = 0; mt < MT; mt++)
#pragma unroll
                for (int nt = 0; nt < NT; nt++)
                    mma_tf32(acc[mt][nt], af[mt], bf[nt]);
        }
    }

#pragma unroll
    for (int mt = 0; mt < MT; mt++) {
#pragma unroll
        for (int nt = 0; nt < NT; nt++) {
            int gn = colBase + n0 + nt * 8 + 2 * c;
#pragma unroll
            for (int half = 0; half < 2; half++) {
                int gm = rowBase + m0 + mt * 16 + g + half * 8;
                if (gm >= Mr) continue;
#pragma unroll
                for (int e = 0; e < 2; e++) {
                    float v = acc[mt][nt][half * 2 + e];
                    int gnn = gn + e;
                    if (flags & F_DIAG) {
                        v = alpha * (dcoef * A[(long long)gm * lda + gnn] - v);
                    } else {
                        v = alpha * v;
                        if (bias) v += bias[gnn];
                        if (res)  v += res[(long long)gm * ldres + gnn];
                        if (flags & F_RELU) v = fmaxf(v, 0.f);
                    }
                    C[(long long)gm * ldc + gnn] = v;
                }
            }
        }
    }
}

// ---------------- fused flash attention kernel -----------------------------
template<bool SPLIT>
__global__ void __launch_bounds__(128, 3)
flash_k(const float* __restrict__ Qb, int ldq, long long sQh,
        const float* __restrict__ Kb, int ldk, long long sKh,
        const float* __restrict__ Vb, int ldv, long long sVh,
        int nchunks, int keys_per_slice,
        float* __restrict__ out, int ldo, long long sOh,
        float* __restrict__ Op, float* __restrict__ mp, float* __restrict__ lp,
        int nslices, int nqt)
{
    extern __shared__ float smf[];
    float* sQ = smf;
    float* sK = smf + 64 * 68;
    float* sV = smf + 2 * 64 * 68;
    float* sP = smf + 3 * 64 * 68;

    const int h = blockIdx.z, qt = blockIdx.x;
    const int sl = SPLIT ? blockIdx.y : 0;
    const float* Q = Qb + h * sQh + (long long)qt * 64 * ldq;
    const float* K = Kb + h * sKh + (long long)sl * keys_per_slice * ldk;
    const float* V = Vb + h * sVh + (long long)sl * keys_per_slice * ldv;

    const int tid = threadIdx.x, lane = tid & 31, w = tid >> 5;
    const int g = lane >> 2, c = lane & 3;
    const int wr = w * 16;

    for (int i = tid; i < 64 * 16; i += 128) {
        int r = i >> 4, q4 = (i & 15) * 4;
        *reinterpret_cast<float4*>(sQ + r * 68 + q4) =
            *reinterpret_cast<const float4*>(Q + (long long)r * ldq + q4);
    }

    float m0 = -1e30f, m1 = -1e30f, l0 = 0.f, l1 = 0.f;
    float Oacc[8][4];
#pragma unroll
    for (int nt = 0; nt < 8; nt++)
#pragma unroll
        for (int e = 0; e < 4; e++) Oacc[nt][e] = 0.f;

    for (int ch = 0; ch < nchunks; ch++) {
        __syncthreads();
        const float* Kc = K + (long long)ch * 64 * ldk;
        const float* Vc = V + (long long)ch * 64 * ldv;
        for (int i = tid; i < 64 * 16; i += 128) {
            int r = i >> 4, q4 = (i & 15) * 4;
            *reinterpret_cast<float4*>(sK + r * 68 + q4) =
                *reinterpret_cast<const float4*>(Kc + (long long)r * ldk + q4);
            *reinterpret_cast<float4*>(sV + r * 68 + q4) =
                *reinterpret_cast<const float4*>(Vc + (long long)r * ldv + q4);
        }
        __syncthreads();

        float lacc[8][4];
#pragma unroll
        for (int nt = 0; nt < 8; nt++)
#pragma unroll
            for (int e = 0; e < 4; e++) lacc[nt][e] = 0.f;
#pragma unroll
        for (int kk = 0; kk < 64; kk += 8) {
            uint32_t a[4];
            a[0] = __float_as_uint(sQ[(wr + g) * 68 + kk + c]);
            a[1] = __float_as_uint(sQ[(wr + g + 8) * 68 + kk + c]);
            a[2] = __float_as_uint(sQ[(wr + g) * 68 + kk + 4 + c]);
            a[3] = __float_as_uint(sQ[(wr + g + 8) * 68 + kk + 4 + c]);
#pragma unroll
            for (int nt = 0; nt < 8; nt++) {
                uint32_t b[2];
                b[0] = __float_as_uint(sK[(nt * 8 + g) * 68 + kk + c]);
                b[1] = __float_as_uint(sK[(nt * 8 + g) * 68 + kk + 4 + c]);
                mma_tf32(lacc[nt], a, b);
            }
        }

        float cm0 = -1e30f, cm1 = -1e30f;
#pragma unroll
        for (int nt = 0; nt < 8; nt++) {
            lacc[nt][0] *= SCALE_Q; lacc[nt][1] *= SCALE_Q;
            lacc[nt][2] *= SCALE_Q; lacc[nt][3] *= SCALE_Q;
            cm0 = fmaxf(cm0, fmaxf(lacc[nt][0], lacc[nt][1]));
            cm1 = fmaxf(cm1, fmaxf(lacc[nt][2], lacc[nt][3]));
        }
        cm0 = fmaxf(cm0, __shfl_xor_sync(0xffffffffu, cm0, 1));
        cm0 = fmaxf(cm0, __shfl_xor_sync(0xffffffffu, cm0, 2));
        cm1 = fmaxf(cm1, __shfl_xor_sync(0xffffffffu, cm1, 1));
        cm1 = fmaxf(cm1, __shfl_xor_sync(0xffffffffu, cm1, 2));
        float nm0 = fmaxf(m0, cm0), nm1 = fmaxf(m1, cm1);
        float f0 = __expf(m0 - nm0), f1 = __expf(m1 - nm1);
        float rs0 = 0.f, rs1 = 0.f;
#pragma unroll
        for (int nt = 0; nt < 8; nt++) {
            float p0 = __expf(lacc[nt][0] - nm0);
            float p1 = __expf(lacc[nt][1] - nm0);
            float p2 = __expf(lacc[nt][2] - nm1);
            float p3 = __expf(lacc[nt][3] - nm1);
            rs0 += p0 + p1; rs1 += p2 + p3;
            sP[(wr + g) * 68 + nt * 8 + 2 * c]     = p0;
            sP[(wr + g) * 68 + nt * 8 + 2 * c + 1] = p1;
            sP[(wr + g + 8) * 68 + nt * 8 + 2 * c]     = p2;
            sP[(wr + g + 8) * 68 + nt * 8 + 2 * c + 1] = p3;
        }
        rs0 += __shfl_xor_sync(0xffffffffu, rs0, 1);
        rs0 += __shfl_xor_sync(0xffffffffu, rs0, 2);
        rs1 += __shfl_xor_sync(0xffffffffu, rs1, 1);
        rs1 += __shfl_xor_sync(0xffffffffu, rs1, 2);
        l0 = l0 * f0 + rs0; l1 = l1 * f1 + rs1;
        m0 = nm0; m1 = nm1;
#pragma unroll
        for (int nt = 0; nt < 8; nt++) {
            Oacc[nt][0] *= f0; Oacc[nt][1] *= f0;
            Oacc[nt][2] *= f1; Oacc[nt][3] *= f1;
        }
        __syncwarp();

#pragma unroll
        for (int kk = 0; kk < 64; kk += 8) {
            uint32_t a[4];
            a[0] = __float_as_uint(sP[(wr + g) * 68 + kk + c]);
            a[1] = __float_as_uint(sP[(wr + g + 8) * 68 + kk + c]);
            a[2] = __float_as_uint(sP[(wr + g) * 68 + kk + 4 + c]);
            a[3] = __float_as_uint(sP[(wr + g + 8) * 68 + kk + 4 + c]);
#pragma unroll
            for (int nt = 0; nt < 8; nt++) {
                uint32_t b[2];
                b[0] = __float_as_uint(sV[(kk + c) * 68 + nt * 8 + g]);
                b[1] = __float_as_uint(sV[(kk + 4 + c) * 68 + nt * 8 + g]);
                mma_tf32(Oacc[nt], a, b);
            }
        }
    }

    if (SPLIT) {
        long long pb = ((long long)(h * nqt + qt) * nslices + sl) * 64;
#pragma unroll
        for (int nt = 0; nt < 8; nt++) {
            Op[(pb + wr + g) * 64 + nt * 8 + 2 * c]     = Oacc[nt][0];
            Op[(pb + wr + g) * 64 + nt * 8 + 2 * c + 1] = Oacc[nt][1];
            Op[(pb + wr + g + 8) * 64 + nt * 8 + 2 * c]     = Oacc[nt][2];
            Op[(pb + wr + g + 8) * 64 + nt * 8 + 2 * c + 1] = Oacc[nt][3];
        }
        if (c == 0) {
            mp[pb + wr + g] = m0; lp[pb + wr + g] = l0;
            mp[pb + wr + g + 8] = m1; lp[pb + wr + g + 8] = l1;
        }
    } else {
        float inv0 = 1.f / l0, inv1 = 1.f / l1;
        float* o0 = out + h * sOh + (long long)(qt * 64 + wr + g) * ldo;
        float* o1 = out + h * sOh + (long long)(qt * 64 + wr + g + 8) * ldo;
#pragma unroll
        for (int nt = 0; nt < 8; nt++) {
            o0[nt * 8 + 2 * c]     = Oacc[nt][0] * inv0;
            o0[nt * 8 + 2 * c + 1] = Oacc[nt][1] * inv0;
            o1[nt * 8 + 2 * c]     = Oacc[nt][2] * inv1;
            o1[nt * 8 + 2 * c + 1] = Oacc[nt][3] * inv1;
        }
    }
}

__global__ void fcomb_k(const float* __restrict__ Op, const float* __restrict__ mp,
                        const float* __restrict__ lp, float* __restrict__ a3v)
{
    int idx = blockIdx.x * 256 + threadIdx.x;
    int col = idx & 63, r = (idx >> 6) & 255, h = idx >> 14;
    int qt = r >> 6, rr = r & 63;
    long long hq = (long long)(h * 4 + qt) * NSL;
    float mx = -1e30f;
#pragma unroll
    for (int s = 0; s < NSL; s++) mx = fmaxf(mx, mp[(hq + s) * 64 + rr]);
    float num = 0.f, den = 0.f;
#pragma unroll
    for (int s = 0; s < NSL; s++) {
        float wgt = __expf(mp[(hq + s) * 64 + rr] - mx);
        den += wgt * lp[(hq + s) * 64 + rr];
        num += wgt * Op[((hq + s) * 64 + rr) * 64 + col];
    }
    a3v[idx] = num / den;
}

// ---------------- small kernels --------------------------------------------

__global__ void softmax256_k(float* __restrict__ S)
{
    long long row = (long long)blockIdx.x * 8 + (threadIdx.x >> 5);
    int lane = threadIdx.x & 31;
    float* p = S + row * 256 + lane * 8;
    float4 a = *reinterpret_cast<float4*>(p);
    float4 b = *reinterpret_cast<float4*>(p + 4);
    float m = fmaxf(fmaxf(fmaxf(a.x, a.y), fmaxf(a.z, a.w)),
                    fmaxf(fmaxf(b.x, b.y), fmaxf(b.z, b.w)));
#pragma unroll
    for (int o = 16; o; o >>= 1) m = fmaxf(m, __shfl_xor_sync(0xffffffffu, m, o));
    a.x = __expf(a.x - m); a.y = __expf(a.y - m); a.z = __expf(a.z - m); a.w = __expf(a.w - m);
    b.x = __expf(b.x - m); b.y = __expf(b.y - m); b.z = __expf(b.z - m); b.w = __expf(b.w - m);
    float s = a.x + a.y + a.z + a.w + b.x + b.y + b.z + b.w;
#pragma unroll
    for (int o = 16; o; o >>= 1) s += __shfl_xor_sync(0xffffffffu, s, o);
    float inv = 1.f / s;
    a.x *= inv; a.y *= inv; a.z *= inv; a.w *= inv;
    b.x *= inv; b.y *= inv; b.z *= inv; b.w *= inv;
    *reinterpret_cast<float4*>(p) = a;
    *reinterpret_cast<float4*>(p + 4) = b;
}

__global__ void ln_k(const float* __restrict__ x, float* __restrict__ y,
                     const float* __restrict__ g, const float* __restrict__ b)
{
    long long row = blockIdx.x;
    const float* xr = x + row * DIM;
    float* yr = y + row * DIM;
    int t = threadIdx.x;
    float v0 = xr[t], v1 = xr[t + 256];
    __shared__ float sm[256];
    sm[t] = v0 + v1; __syncthreads();
    for (int s = 128; s > 0; s >>= 1) { if (t < s) sm[t] += sm[t + s]; __syncthreads(); }
    float mu = sm[0] * (1.f / DIM); __syncthreads();
    float d0 = v0 - mu, d1 = v1 - mu;
    sm[t] = d0 * d0 + d1 * d1; __syncthreads();
    for (int s = 128; s > 0; s >>= 1) { if (t < s) sm[t] += sm[t + s]; __syncthreads(); }
    float rs = rsqrtf(sm[0] * (1.f / DIM) + EPSLN); __syncthreads();
    yr[t]       = d0 * rs * g[t]       + b[t];
    yr[t + 256] = d1 * rs * g[t + 256] + b[t + 256];
}

__global__ void landmark_k(const float* __restrict__ qkv,
                           float* __restrict__ ql, float* __restrict__ kl)
{
    int idx = blockIdx.x * 256 + threadIdx.x;
    int d = idx & 63, m = (idx >> 6) & 255, h = idx >> 14;
    int off = (blockIdx.y == 0) ? 0 : DIM;
    float s = 0.f;
    const float* src = qkv + off + h * DH + d;
#pragma unroll
    for (int j = 0; j < LCH; j++)
        s += src[(long long)(m * LCH + j) * (3 * DIM)];
    float* dst = (blockIdx.y == 0) ? ql : kl;
    dst[h * (MLM * DH) + m * DH + d] = s * (1.f / LCH);
}

__global__ void pinv_init_k(const float* __restrict__ A2, float* __restrict__ Z)
{
    int h = blockIdx.x;
    const float* A = A2 + (long long)h * MLM * MLM;
    float* Zh = Z + (long long)h * MLM * MLM;
    int t = threadIdx.x;
    float rs = 0.f, cs = 0.f;
    for (int j = 0; j < MLM; j++) {
        rs += fabsf(A[t * MLM + j]);
        cs += fabsf(A[j * MLM + t]);
    }
    __shared__ float s1[256], s2[256];
    s1[t] = rs; s2[t] = cs; __syncthreads();
    for (int s = 128; s > 0; s >>= 1) {
        if (t < s) { s1[t] = fmaxf(s1[t], s1[t + s]); s2[t] = fmaxf(s2[t], s2[t + s]); }
        __syncthreads();
    }
    float scale = 1.f / (s1[0] * s2[0]);
    __syncthreads();
    for (int j = 0; j < MLM; j++)
        Zh[t * MLM + j] = A[j * MLM + t] * scale;
}

// tiled depthwise seq-conv: one 64-ch tile == one head; 128-token tiles
__global__ void __launch_bounds__(256)
conv1d_t_k(float* __restrict__ attn, const float* __restrict__ qkv,
           const float* __restrict__ w)
{
    __shared__ float sv[160 * 64];
    __shared__ float sw[33];
    const int t0 = blockIdx.x * 128;
    const int h = blockIdx.y;
    const int tid = threadIdx.x;
    if (tid < 33) sw[tid] = w[h * 33 + tid];
    for (int i = tid; i < 160 * 64; i += 256) {
        int chL = i & 63, p = i >> 6;
        int tok = t0 + p - 16;
        float v = 0.f;
        if (tok >= 0 && tok < NP)
            v = qkv[(long long)tok * (3 * DIM) + 2 * DIM + h * 64 + chL];
        sv[p * 64 + chL] = v;
    }
    __syncthreads();
    const int chL = tid & 63, lane = tid >> 6;
    for (int p = lane; p < 128; p += 4) {
        float acc = 0.f;
#pragma unroll
        for (int t = 0; t < 33; t++)
            acc += sw[t] * sv[(p + t) * 64 + chL];
        attn[(long long)(t0 + p) * DIM + h * 64 + chL] += acc;
    }
}

__global__ void seed_k(float* __restrict__ hA, const float* __restrict__ cls)
{
    int idx = blockIdx.x * 256 + threadIdx.x;
    if (idx < DIM) hA[idx] = cls[idx];
    int j = idx - DIM;
    if (j >= 0 && j < 89 * DIM) {
        int r = j >> 9, c = j & 511;
        hA[(long long)(1 + 8192 + r) * DIM + c] = hA[(long long)(1 + r) * DIM + c];
    }
}

// tiled PPEG: 8x32 pixel tile x 32 channels, 3-wide halo, combined taps
__global__ void __launch_bounds__(256)
ppeg_t_k(const float* __restrict__ hA, float* __restrict__ h2,
         const float* __restrict__ w7, const float* __restrict__ b7,
         const float* __restrict__ w5, const float* __restrict__ b5,
         const float* __restrict__ w3, const float* __restrict__ b3)
{
    extern __shared__ float psm[];
    float* sf = psm;                       // 14*38*32
    float* wc = psm + 14 * 38 * 32;        // 49*32
    float* bs = wc + 49 * 32;              // 32

    const int c0 = blockIdx.x * 32;
    const int r0 = blockIdx.y * 8;
    const int ch0 = blockIdx.z * 32;
    const int tid = threadIdx.x;

    for (int i = tid; i < 49 * 32; i += 256) {
        int tap = i >> 5, chL = i & 31;
        int u = tap / 7 - 3, v = tap % 7 - 3;
        int ch = ch0 + chL;
        float wv = w7[ch * 49 + tap];
        if (u >= -2 && u <= 2 && v >= -2 && v <= 2) wv += w5[ch * 25 + (u + 2) * 5 + (v + 2)];
        if (u >= -1 && u <= 1 && v >= -1 && v <= 1) wv += w3[ch * 9 + (u + 1) * 3 + (v + 1)];
        wc[tap * 32 + chL] = wv;
    }
    if (tid < 32) bs[tid] = b7[ch0 + tid] + b5[ch0 + tid] + b3[ch0 + tid];

    for (int i = tid; i < 14 * 38 * 32; i += 256) {
        int chL = i & 31;
        int p = i >> 5;
        int pc = p % 38, pr = p / 38;
        int rr = r0 + pr - 3, cc = c0 + pc - 3;
        float v = 0.f;
        if (rr >= 0 && rr < HSIZE && cc >= 0 && cc < HSIZE)
            v = hA[(long long)(1 + rr * HSIZE + cc) * DIM + ch0 + chL];
        sf[p * 32 + chL] = v;
    }
    __syncthreads();

    const int chL = tid & 31, lane = tid >> 5;   // 8 lanes
    for (int p = lane; p < 8 * 32; p += 8) {
        int pr = p >> 5, pc = p & 31;
        int rr = r0 + pr, cc = c0 + pc;
        if (rr >= HSIZE || cc >= HSIZE) continue;
        float acc = sf[((pr + 3) * 38 + pc + 3) * 32 + chL] + bs[chL];
#pragma unroll
        for (int u = 0; u < 7; u++)
#pragma unroll
            for (int v = 0; v < 7; v++)
                acc += wc[(u * 7 + v) * 32 + chL] * sf[((pr + u) * 38 + pc + v) * 32 + chL];
        h2[(long long)(1 + rr * HSIZE + cc) * DIM + ch0 + chL] = acc;
    }
}

__global__ void copy_row0_k(float* __restrict__ h2, const float* __restrict__ hA)
{
    h2[threadIdx.x] = hA[threadIdx.x];
}

__global__ void final_k(const float* __restrict__ h, const float* __restrict__ g,
                        const float* __restrict__ b, const float* __restrict__ w,
                        const float* __restrict__ bias, float* __restrict__ out,
                        int out_size)
{
    int t = threadIdx.x;
    __shared__ float sm[512];
    float v = h[t];
    sm[t] = v; __syncthreads();
    for (int s = 256; s > 0; s >>= 1) { if (t < s) sm[t] += sm[t + s]; __syncthreads(); }
    float mu = sm[0] * (1.f / DIM); __syncthreads();
    float d = v - mu;
    sm[t] = d * d; __syncthreads();
    for (int s = 256; s > 0; s >>= 1) { if (t < s) sm[t] += sm[t + s]; __syncthreads(); }
    float rs = rsqrtf(sm[0] * (1.f / DIM) + EPSLN); __syncthreads();
    float e = d * rs * g[t] + b[t];
    if (5 + t < out_size) out[5 + t] = e;
    sm[t] = e * w[t * 2]; __syncthreads();
    for (int s = 256; s > 0; s >>= 1) { if (t < s) sm[t] += sm[t + s]; __syncthreads(); }
    float l0 = sm[0] + bias[0]; __syncthreads();
    sm[t] = e * w[t * 2 + 1]; __syncthreads();
    for (int s = 256; s > 0; s >>= 1) { if (t < s) sm[t] += sm[t + s]; __syncthreads(); }
    float l1 = sm[0] + bias[1]; __syncthreads();
    if (t == 0 && out_size >= 5) {
        out[0] = l0; out[1] = l1;
        float mx = fmaxf(l0, l1);
        float e0 = expf(l0 - mx), e1 = expf(l1 - mx);
        float s = e0 + e1;
        out[2] = e0 / s; out[3] = e1 / s;
        out[4] = (l1 > l0) ? 1.f : 0.f;
    }
}

// ---------------- host orchestration ---------------------------------------

constexpr int FLASH_SMEM = 4 * 64 * 68 * 4;
constexpr int SMEM_BIG_D = 3 * (128 * 36 + 32 * 136) * 4;    // 107520
constexpr int SMEM_BIG_T = 3 * (128 * 36 + 128 * 36) * 4;    // 110592
constexpr int SMEM_SML   = 3 * (64 * 36 + 64 * 36) * 4;      // 55296 (covers both)
constexpr int PPEG_SMEM  = (14 * 38 * 32 + 49 * 32 + 32) * 4;

static void launch_big(const float* A, const float* B, float* C,
                       int M, int N, int K, int lda, int ldb, int ldc,
                       long long sA, long long sB, long long sC, int batch,
                       float alpha, const float* bias, const float* res, int ldres,
                       int zrows, int flags, float dcoef = 0.f)
{
    dim3 grid(N / 128, (M + 127) / 128, batch);
    if (flags & F_TRB)
        gemm_tc<128, 128, 32, 2, 4, true, 256, 2><<<grid, 256, SMEM_BIG_T>>>(
            A, B, C, M, K, lda, ldb, ldc, sA, sB, sC, alpha, bias, res, ldres, zrows, flags, dcoef);
    else
        gemm_tc<128, 128, 32, 2, 4, false, 256, 2><<<grid, 256, SMEM_BIG_D>>>(
            A, B, C, M, K, lda, ldb, ldc, sA, sB, sC, alpha, bias, res, ldres, zrows, flags, dcoef);
}

static void launch_small(const float* A, const float* B, float* C,
                         int M, int N, int K, int lda, int ldb, int ldc,
                         long long sA, long long sB, long long sC, int batch,
                         float alpha, const float* bias, const float* res, int ldres,
                         int zrows, int flags, float dcoef = 0.f)
{
    dim3 grid(N / 64, (M + 63) / 64, batch);
    if (flags & F_TRB)
        gemm_tc<64, 64, 32, 2, 2, true, 128, 4><<<grid, 128, SMEM_SML>>>(
            A, B, C, M, K, lda, ldb, ldc, sA, sB, sC, alpha, bias, res, ldres, zrows, flags, dcoef);
    else
        gemm_tc<64, 64, 32, 2, 2, false, 128, 4><<<grid, 128, SMEM_SML>>>(
            A, B, C, M, K, lda, ldb, ldc, sA, sB, sC, alpha, bias, res, ldres, zrows, flags, dcoef);
}

static void run_attn_layer(float* base, float* hbuf,
                           const float* lng, const float* lnb,
                           const float* qkvw, const float* outw, const float* outb,
                           const float* convw)
{
    float* xln  = base + OFF_XLN;
    float* qkv  = base + OFF_QKV;
    float* Opar = base + OFF_S1;
    float* mpar = base + OFF_S3;
    float* lpar = base + OFF_S3 + 32768;
    float* a2   = base + OFF_A2;
    float* Zb   = base + OFF_Z;
    float* XZ   = base + OFF_XZ;
    float* Tb   = base + OFF_T;
    float* T4   = base + OFF_T4;
    float* Pb   = base + OFF_P;
    float* ql   = base + OFF_QL;
    float* kl   = base + OFF_KL;
    float* a3v  = base + OFF_A3V;
    float* W2   = base + OFF_W2;
    float* attn = base + OFF_ATTN;

    const long long sA2 = (long long)MLM * MLM;
    const long long sLM = (long long)MLM * DH;

    ln_k<<<NTOK, 256>>>(hbuf, xln, lng, lnb);

    launch_big(xln, qkvw, qkv, NP, 3 * DIM, DIM, DIM, 3 * DIM, 3 * DIM,
               0, 0, 0, 1, 1.f, nullptr, nullptr, 0, PADR, 0);

    landmark_k<<<dim3(512, 2), 256>>>(qkv, ql, kl);

    flash_k<true><<<dim3(4, NSL, HEADS), 128, FLASH_SMEM>>>(
        ql, DH, sLM,
        qkv + DIM, 3 * DIM, DH,
        qkv + 2 * DIM, 3 * DIM, DH,
        KPS / 64, KPS,
        nullptr, 0, 0,
        Opar, mpar, lpar, NSL, 4);
    fcomb_k<<<(HEADS * (int)sLM) / 256, 256>>>(Opar, mpar, lpar, a3v);

    launch_small(ql, kl, a2, MLM, MLM, DH, DH, DH, MLM,
                 sLM, sLM, sA2, HEADS, SCALE_Q, nullptr, nullptr, 0, 0, F_TRB);
    softmax256_k<<<(HEADS * MLM) / 8, 256>>>(a2);

    pinv_init_k<<<HEADS, 256>>>(a2, Zb);
    float* Zc = Zb;
    float* Pc = Pb;
    for (int it = 0; it < 6; it++) {
        launch_small(a2, Zc, XZ, MLM, MLM, MLM, MLM, MLM, MLM,
                     sA2, sA2, sA2, HEADS, 1.f, nullptr, nullptr, 0, 0, 0);
        launch_small(XZ, XZ, Tb, MLM, MLM, MLM, MLM, MLM, MLM,
                     sA2, sA2, sA2, HEADS, 1.f, nullptr, nullptr, 0, 0, F_DIAG, 7.f);
        launch_small(XZ, Tb, T4, MLM, MLM, MLM, MLM, MLM, MLM,
                     sA2, sA2, sA2, HEADS, 1.f, nullptr, nullptr, 0, 0, F_DIAG, 15.f);
        launch_small(Zc, T4, Pc, MLM, MLM, MLM, MLM, MLM, MLM,
                     sA2, sA2, sA2, HEADS, 0.25f, nullptr, nullptr, 0, 0, F_DIAG, 13.f);
        float* tmp = Zc; Zc = Pc; Pc = tmp;
    }

    launch_small(Zc, a3v, W2, MLM, DH, MLM, MLM, DH, DH,
                 sA2, sLM, sLM, HEADS, 1.f, nullptr, nullptr, 0, 0, 0);

    flash_k<false><<<dim3(NP / 64, 1, HEADS), 128, FLASH_SMEM>>>(
        qkv, 3 * DIM, DH,
        kl, DH, sLM,
        W2, DH, sLM,
        MLM / 64, MLM,
        attn, DIM, DH,
        nullptr, nullptr, nullptr, 1, NP / 64);

    conv1d_t_k<<<dim3(NP / 128, HEADS), 256>>>(attn, qkv, convw);

    launch_big(attn + (long long)PADR * DIM, outw, hbuf, NTOK, DIM, DIM,
               DIM, DIM, DIM, 0, 0, 0, 1, 1.f, outb, hbuf, DIM, 0, 0);
}

extern "C" void kernel_launch(void* const* d_in, const int* in_sizes, int n_in,
                              void* d_out, int out_size)
{
    const float* x      = (const float*)d_in[0];
    const float* fc1_w  = (const float*)d_in[1];
    const float* fc1_b  = (const float*)d_in[2];
    const float* cls    = (const float*)d_in[3];
    const float* ln1_g  = (const float*)d_in[4];
    const float* ln1_b  = (const float*)d_in[5];
    const float* qkv1_w = (const float*)d_in[6];
    const float* out1_w = (const float*)d_in[7];
    const float* out1_b = (const float*)d_in[8];
    const float* conv1w = (const float*)d_in[9];
    const float* ln2_g  = (const float*)d_in[10];
    const float* ln2_b  = (const float*)d_in[11];
    const float* qkv2_w = (const float*)d_in[12];
    const float* out2_w = (const float*)d_in[13];
    const float* out2_b = (const float*)d_in[14];
    const float* conv2w = (const float*)d_in[15];
    const float* pg7_w  = (const float*)d_in[16];
    const float* pg7_b  = (const float*)d_in[17];
    const float* pg5_w  = (const float*)d_in[18];
    const float* pg5_b  = (const float*)d_in[19];
    const float* pg3_w  = (const float*)d_in[20];
    const float* pg3_b  = (const float*)d_in[21];
    const float* norm_g = (const float*)d_in[22];
    const float* norm_b = (const float*)d_in[23];
    const float* fc2_w  = (const float*)d_in[24];
    const float* fc2_b  = (const float*)d_in[25];

    cudaFuncSetAttribute(flash_k<true>,  cudaFuncAttributeMaxDynamicSharedMemorySize, FLASH_SMEM);
    cudaFuncSetAttribute(flash_k<false>, cudaFuncAttributeMaxDynamicSharedMemorySize, FLASH_SMEM);
    cudaFuncSetAttribute((const void*)gemm_tc<128, 128, 32, 2, 4, true, 256, 2>,
                         cudaFuncAttributeMaxDynamicSharedMemorySize, SMEM_BIG_T);
    cudaFuncSetAttribute((const void*)gemm_tc<128, 128, 32, 2, 4, false, 256, 2>,
                         cudaFuncAttributeMaxDynamicSharedMemorySize, SMEM_BIG_D);
    cudaFuncSetAttribute((const void*)gemm_tc<64, 64, 32, 2, 2, true, 128, 4>,
                         cudaFuncAttributeMaxDynamicSharedMemorySize, SMEM_SML);
    cudaFuncSetAttribute((const void*)gemm_tc<64, 64, 32, 2, 2, false, 128, 4>,
                         cudaFuncAttributeMaxDynamicSharedMemorySize, SMEM_SML);
    cudaFuncSetAttribute(ppeg_t_k, cudaFuncAttributeMaxDynamicSharedMemorySize, PPEG_SMEM);

    float* base = nullptr;
    cudaGetSymbolAddress((void**)&base, g_scratch);
    float* hA = base + OFF_HA;
    float* h2 = base + OFF_H2;

    launch_big(x, fc1_w, hA + DIM, 8192, DIM, 1024, 1024, DIM, DIM,
               0, 0, 0, 1, 1.f, fc1_b, nullptr, 0, 0, F_RELU);
    seed_k<<<(90 * DIM) / 256, 256>>>(hA, cls);

    run_attn_layer(base, hA, ln1_g, ln1_b, qkv1_w, out1_w, out1_b, conv1w);

    ppeg_t_k<<<dim3(3, 12, 16), 256, PPEG_SMEM>>>(hA, h2, pg7_w, pg7_b, pg5_w, pg5_b, pg3_w, pg3_b);
    copy_row0_k<<<1, DIM>>>(h2, hA);

    run_attn_layer(base, h2, ln2_g, ln2_b, qkv2_w, out2_w, out2_b, conv2w);

    final_k<<<1, DIM>>>(h2, norm_g, norm_b, fc2_w, fc2_b, (float*)d_out, out_size);
}

// round 6
// speedup vs baseline: 8.0186x; 1.0293x over previous
#include <cuda_runtime.h>
#include <cstdint>

// ----------------------------------------------------------------------------
// TransMIL forward pass. tf32 tensor-core GEMMs (3-stage cp.async) + fused
// flash attention + tiled depthwise convs + persistent fused pinv kernel.
// ----------------------------------------------------------------------------

#define NP      8448
#define NTOK    8282
#define NPIX    8281
#define HSIZE   91
#define PADR    166
#define DIM     512
#define HEADS   8
#define DH      64
#define MLM     256
#define LCH     33
#define SCALE_Q 0.125f
#define EPSLN   1e-5f
#define NSL     11
#define KPS     768

#define F_RELU  1
#define F_TRB   2
#define F_DIAG  4

// ---------------- scratch -----------------------------------------------
constexpr long long SZ_H    = (long long)NTOK * DIM;
constexpr long long SZ_QKV  = (long long)NP * 3 * DIM;
constexpr long long SZ_S    = (long long)HEADS * NP * MLM;
constexpr long long SZ_A2   = (long long)MLM * MLM * HEADS;
constexpr long long SZ_LM   = (long long)HEADS * MLM * DH;
constexpr long long SZ_ATTN = (long long)NP * DIM;

constexpr long long OFF_HA   = 0;
constexpr long long OFF_H2   = OFF_HA  + SZ_H;
constexpr long long OFF_XLN  = OFF_H2  + SZ_H;
constexpr long long OFF_QKV  = OFF_XLN + SZ_H;
constexpr long long OFF_S1   = OFF_QKV + SZ_QKV;   // flash O partials
constexpr long long OFF_S3   = OFF_S1  + SZ_S;     // flash m/l partials
constexpr long long OFF_A2   = OFF_S3  + SZ_S;
constexpr long long OFF_Z    = OFF_A2  + SZ_A2;
constexpr long long OFF_XZ   = OFF_Z   + SZ_A2;
constexpr long long OFF_T    = OFF_XZ  + SZ_A2;
constexpr long long OFF_T4   = OFF_T   + SZ_A2;
constexpr long long OFF_P    = OFF_T4  + SZ_A2;
constexpr long long OFF_QL   = OFF_P   + SZ_A2;
constexpr long long OFF_KL   = OFF_QL  + SZ_LM;
constexpr long long OFF_A3V  = OFF_KL  + SZ_LM;
constexpr long long OFF_W2   = OFF_A3V + SZ_LM;
constexpr long long OFF_ATTN = OFF_W2  + SZ_LM;
constexpr long long SCRATCH_TOTAL = OFF_ATTN + SZ_ATTN;

__device__ float g_scratch[SCRATCH_TOTAL];
__device__ unsigned g_bar_cnt;

// ---------------- mma helpers ----------------------------------------------

__device__ __forceinline__ void cpa16(uint32_t dst, const float* src, int validBytes)
{
    asm volatile("cp.async.cg.shared.global [%0], [%1], 16, %2;\n"
                 :: "r"(dst), "l"(src), "r"(validBytes));
}

__device__ __forceinline__ void mma_tf32(float* d, const uint32_t* a, const uint32_t* b)
{
    asm volatile(
        "mma.sync.aligned.m16n8k8.row.col.f32.tf32.tf32.f32 "
        "{%0,%1,%2,%3}, {%4,%5,%6,%7}, {%8,%9}, {%0,%1,%2,%3};"
        : "+f"(d[0]), "+f"(d[1]), "+f"(d[2]), "+f"(d[3])
        : "r"(a[0]), "r"(a[1]), "r"(a[2]), "r"(a[3]), "r"(b[0]), "r"(b[1]));
}

// ---------------- tensor-core tf32 GEMM, 3-stage pipeline ------------------
template<int BM, int BN, int BK, int WM, int WN, bool TRB, int THREADS, int MAXB>
__global__ void __launch_bounds__(THREADS, MAXB)
gemm_tc(const float* __restrict__ A, const float* __restrict__ B,
        float* __restrict__ C,
        int Mr, int K, int lda, int ldb, int ldc,
        long long sA, long long sB, long long sC,
        float alpha,
        const float* __restrict__ bias,
        const float* __restrict__ res, int ldres,
        int zrows, int flags, float dcoef)
{
    constexpr int MT = BM / (WM * 16);
    constexpr int NT = BN / (WN * 8);
    constexpr int ASTR = BK + 4;
    constexpr int ASZ  = BM * ASTR;
    constexpr int BSTR = TRB ? (BK + 4) : (BN + 8);
    constexpr int BROWS = TRB ? BN : BK;
    constexpr int BSZ  = BROWS * BSTR;
    constexpr int CA = BM * BK / (4 * THREADS);
    constexpr int CB = BN * BK / (4 * THREADS);
    static_assert(CA >= 1 && CB >= 1, "chunks");
    static_assert(WM * WN == THREADS / 32, "warps");

    extern __shared__ float dynsm[];
    float* sAr = dynsm;
    float* sBr = dynsm + 3 * ASZ;

    const int bz = blockIdx.z;
    A += bz * sA; B += bz * sB; C += bz * sC;

    const int tid = threadIdx.x;
    const int lane = tid & 31;
    const int w = tid >> 5;
    const int wm = w / WN, wn = w % WN;
    const int m0 = wm * MT * 16;
    const int n0 = wn * NT * 8;
    const int g = lane >> 2, c = lane & 3;
    const int rowBase = blockIdx.y * BM;
    const int colBase = blockIdx.x * BN;

    const uint32_t saA = (uint32_t)__cvta_generic_to_shared(sAr);
    const uint32_t saB = (uint32_t)__cvta_generic_to_shared(sBr);

    auto loadTiles = [&](int st, int k0) {
#pragma unroll
        for (int v = 0; v < CA; v++) {
            int idx = tid + v * THREADS;
            int m = idx / (BK / 4), kq = idx % (BK / 4);
            int gm = rowBase + m, am = gm - zrows;
            bool ok = (gm < Mr) && (am >= 0);
            const float* src = A + (ok ? (long long)am * lda : 0) + k0 + kq * 4;
            cpa16(saA + (uint32_t)(st * ASZ + m * ASTR + kq * 4) * 4, src, ok ? 16 : 0);
        }
        if (TRB) {
#pragma unroll
            for (int v = 0; v < CB; v++) {
                int idx = tid + v * THREADS;
                int n = idx / (BK / 4), kq = idx % (BK / 4);
                const float* src = B + (long long)(colBase + n) * ldb + k0 + kq * 4;
                cpa16(saB + (uint32_t)(st * BSZ + n * BSTR + kq * 4) * 4, src, 16);
            }
        } else {
#pragma unroll
            for (int v = 0; v < CB; v++) {
                int idx = tid + v * THREADS;
                int kk = idx / (BN / 4), nq = idx % (BN / 4);
                const float* src = B + (long long)(k0 + kk) * ldb + colBase + nq * 4;
                cpa16(saB + (uint32_t)(st * BSZ + kk * BSTR + nq * 4) * 4, src, 16);
            }
        }
    };

    float acc[MT][NT][4];
#pragma unroll
    for (int i = 0; i < MT; i++)
#pragma unroll
        for (int j = 0; j < NT; j++)
#pragma unroll
            for (int e = 0; e < 4; e++) acc[i][j][e] = 0.f;

    const int nk = K / BK;
    loadTiles(0, 0);
    asm volatile("cp.async.commit_group;");
    if (nk > 1) loadTiles(1, BK);
    asm volatile("cp.async.commit_group;");

    for (int t = 0; t < nk; t++) {
        if (t + 1 < nk) { asm volatile("cp.async.wait_group 1;"); }
        else            { asm volatile("cp.async.wait_group 0;"); }
        __syncthreads();
        if (t + 2 < nk) {
            loadTiles((t + 2) % 3, (t + 2) * BK);
            asm volatile("cp.async.commit_group;");
        }

        const int st = t % 3;
        const float* pA = sAr + st * ASZ;
        const float* pB = sBr + st * BSZ;
#pragma unroll
        for (int kk = 0; kk < BK; kk += 8) {
            uint32_t af[MT][4], bf[NT][2];
#pragma unroll
            for (int mt = 0; mt < MT; mt++) {
                int r = m0 + mt * 16 + g;
                af[mt][0] = __float_as_uint(pA[r * ASTR + kk + c]);
                af[mt][1] = __float_as_uint(pA[(r + 8) * ASTR + kk + c]);
                af[mt][2] = __float_as_uint(pA[r * ASTR + kk + 4 + c]);
                af[mt][3] = __float_as_uint(pA[(r + 8) * ASTR + kk + 4 + c]);
            }
#pragma unroll
            for (int nt = 0; nt < NT; nt++) {
                int col = n0 + nt * 8 + g;
                if (TRB) {
                    bf[nt][0] = __float_as_uint(pB[col * BSTR + kk + c]);
                    bf[nt][1] = __float_as_uint(pB[col * BSTR + kk + 4 + c]);
                } else {
                    bf[nt][0] = __float_as_uint(pB[(kk + c) * BSTR + col]);
                    bf[nt][1] = __float_as_uint(pB[(kk + 4 + c) * BSTR + col]);
                }
            }
#pragma unroll
            for (int mt = 0; mt < MT; mt++)
#pragma unroll
                for (int nt = 0; nt < NT; nt++)
                    mma_tf32(acc[mt][nt], af[mt], bf[nt]);
        }
    }

#pragma unroll
    for (int mt = 0; mt < MT; mt++) {
#pragma unroll
        for (int nt = 0; nt < NT; nt++) {
            int gn = colBase + n0 + nt * 8 + 2 * c;
#pragma unroll
            for (int half = 0; half < 2; half++) {
                int gm = rowBase + m0 + mt * 16 + g + half * 8;
                if (gm >= Mr) continue;
#pragma unroll
                for (int e = 0; e < 2; e++) {
                    float v = acc[mt][nt][half * 2 + e];
                    int gnn = gn + e;
                    if (flags & F_DIAG) {
                        v = alpha * (dcoef * A[(long long)gm * lda + gnn] - v);
                    } else {
                        v = alpha * v;
                        if (bias) v += bias[gnn];
                        if (res)  v += res[(long long)gm * ldres + gnn];
                        if (flags & F_RELU) v = fmaxf(v, 0.f);
                    }
                    C[(long long)gm * ldc + gnn] = v;
                }
            }
        }
    }
}

// ---------------- persistent fused pinv kernel -----------------------------
// 128 blocks (8 heads x 16 tiles of 64x64), 128 threads. 25 phases:
// 6 Newton iterations x 4 GEMMs, then W2 = Z @ a3v. Software grid barrier.
__device__ __forceinline__ void grid_bar(int gen)
{
    __syncthreads();
    if (threadIdx.x == 0) {
        __threadfence();
        atomicAdd(&g_bar_cnt, 1u);
        unsigned target = (unsigned)(gen + 1) * 128u;
        while (*(volatile unsigned*)&g_bar_cnt < target) __nanosleep(32);
        __threadfence();
    }
    __syncthreads();
}

__global__ void __launch_bounds__(128, 1)
pinv_fused_k(float* __restrict__ base)
{
    __shared__ float sA2[2][64 * 36];    // A tile [m][k], ASTR 36
    __shared__ float sB2[2][32 * 72];    // B tile [k][n], BSTR 72

    const int bid = blockIdx.x;
    const int h = bid >> 4;
    const int t = bid & 15;
    const int rowBase = (t >> 2) * 64;
    const int colBase = (t & 3) * 64;

    const long long hA2 = (long long)h * (MLM * MLM);
    const long long hLM = (long long)h * (MLM * DH);
    float* a2  = base + OFF_A2  + hA2;
    float* Zb  = base + OFF_Z   + hA2;
    float* XZ  = base + OFF_XZ  + hA2;
    float* Tb  = base + OFF_T   + hA2;
    float* T4  = base + OFF_T4  + hA2;
    float* Pb  = base + OFF_P   + hA2;
    float* a3v = base + OFF_A3V + hLM;
    float* W2  = base + OFF_W2  + hLM;

    const int tid = threadIdx.x;
    const int lane = tid & 31;
    const int w = tid >> 5;
    const int wm = w >> 1, wn = w & 1;          // WM=2, WN=2
    const int m0 = wm * 32;                     // MT=2 (2x16 rows)
    const int n0 = wn * 32;                     // NT=4 (4x8 cols)
    const int g = lane >> 2, c = lane & 3;

    const uint32_t saA = (uint32_t)__cvta_generic_to_shared(&sA2[0][0]);
    const uint32_t saB = (uint32_t)__cvta_generic_to_shared(&sB2[0][0]);

    for (int ph = 0; ph < 25; ph++) {
        const float *Ao, *Bo;
        float* Co;
        float alpha = 1.f, dcoef = 0.f;
        bool diag = false;
        int N = 256, ldb = 256, ldc = 256;

        if (ph < 24) {
            int it = ph >> 2, sub = ph & 3;
            float* Zc = (it & 1) ? Pb : Zb;
            float* Pc = (it & 1) ? Zb : Pb;
            switch (sub) {
                case 0: Ao = a2; Bo = Zc; Co = XZ; break;
                case 1: Ao = XZ; Bo = XZ; Co = Tb; diag = true; dcoef = 7.f; break;
                case 2: Ao = XZ; Bo = Tb; Co = T4; diag = true; dcoef = 15.f; break;
                default: Ao = Zc; Bo = T4; Co = Pc; diag = true; dcoef = 13.f; alpha = 0.25f; break;
            }
        } else {
            Ao = Zb; Bo = a3v; Co = W2; N = 64; ldb = 64; ldc = 64;
        }

        if (colBase < N) {
            auto loadT = [&](int st, int k0) {
#pragma unroll
                for (int v = 0; v < 4; v++) {
                    int idx = tid + v * 128;
                    int m = idx >> 3, kq = idx & 7;
                    cpa16(saA + (uint32_t)(st * 2304 + m * 36 + kq * 4) * 4,
                          Ao + (long long)(rowBase + m) * 256 + k0 + kq * 4, 16);
                }
#pragma unroll
                for (int v = 0; v < 4; v++) {
                    int idx = tid + v * 128;
                    int kk = idx >> 4, nq = idx & 15;
                    cpa16(saB + (uint32_t)(st * 2304 + kk * 72 + nq * 4) * 4,
                          Bo + (long long)(k0 + kk) * ldb + colBase + nq * 4, 16);
                }
            };

            float acc[2][4][4];
#pragma unroll
            for (int i = 0; i < 2; i++)
#pragma unroll
                for (int j = 0; j < 4; j++)
#pragma unroll
                    for (int e = 0; e < 4; e++) acc[i][j][e] = 0.f;

            loadT(0, 0);
            asm volatile("cp.async.commit_group;");

            for (int kt = 0; kt < 8; kt++) {
                if (kt + 1 < 8) {
                    loadT((kt + 1) & 1, (kt + 1) * 32);
                    asm volatile("cp.async.commit_group;");
                    asm volatile("cp.async.wait_group 1;");
                } else {
                    asm volatile("cp.async.wait_group 0;");
                }
                __syncthreads();

                const float* pA = &sA2[kt & 1][0];
                const float* pB = &sB2[kt & 1][0];
#pragma unroll
                for (int kk = 0; kk < 32; kk += 8) {
                    uint32_t af[2][4], bf[4][2];
#pragma unroll
                    for (int mt = 0; mt < 2; mt++) {
                        int r = m0 + mt * 16 + g;
                        af[mt][0] = __float_as_uint(pA[r * 36 + kk + c]);
                        af[mt][1] = __float_as_uint(pA[(r + 8) * 36 + kk + c]);
                        af[mt][2] = __float_as_uint(pA[r * 36 + kk + 4 + c]);
                        af[mt][3] = __float_as_uint(pA[(r + 8) * 36 + kk + 4 + c]);
                    }
#pragma unroll
                    for (int nt = 0; nt < 4; nt++) {
                        int col = n0 + nt * 8 + g;
                        bf[nt][0] = __float_as_uint(pB[(kk + c) * 72 + col]);
                        bf[nt][1] = __float_as_uint(pB[(kk + 4 + c) * 72 + col]);
                    }
#pragma unroll
                    for (int mt = 0; mt < 2; mt++)
#pragma unroll
                        for (int nt = 0; nt < 4; nt++)
                            mma_tf32(acc[mt][nt], af[mt], bf[nt]);
                }
                __syncthreads();
            }

#pragma unroll
            for (int mt = 0; mt < 2; mt++) {
#pragma unroll
                for (int nt = 0; nt < 4; nt++) {
                    int gn = colBase + n0 + nt * 8 + 2 * c;
#pragma unroll
                    for (int half = 0; half < 2; half++) {
                        int gm = rowBase + m0 + mt * 16 + g + half * 8;
#pragma unroll
                        for (int e = 0; e < 2; e++) {
                            float v = acc[mt][nt][half * 2 + e];
                            int gnn = gn + e;
                            if (diag)
                                v = alpha * (dcoef * Ao[(long long)gm * 256 + gnn] - v);
                            else
                                v = alpha * v;
                            Co[(long long)gm * ldc + gnn] = v;
                        }
                    }
                }
            }
        }
        grid_bar(ph);
    }
}

// ---------------- fused flash attention kernel -----------------------------
template<bool SPLIT>
__global__ void __launch_bounds__(128, 3)
flash_k(const float* __restrict__ Qb, int ldq, long long sQh,
        const float* __restrict__ Kb, int ldk, long long sKh,
        const float* __restrict__ Vb, int ldv, long long sVh,
        int nchunks, int keys_per_slice,
        float* __restrict__ out, int ldo, long long sOh,
        float* __restrict__ Op, float* __restrict__ mp, float* __restrict__ lp,
        int nslices, int nqt)
{
    extern __shared__ float smf[];
    float* sQ = smf;
    float* sK = smf + 64 * 68;
    float* sV = smf + 2 * 64 * 68;
    float* sP = smf + 3 * 64 * 68;

    const int h = blockIdx.z, qt = blockIdx.x;
    const int sl = SPLIT ? blockIdx.y : 0;
    const float* Q = Qb + h * sQh + (long long)qt * 64 * ldq;
    const float* K = Kb + h * sKh + (long long)sl * keys_per_slice * ldk;
    const float* V = Vb + h * sVh + (long long)sl * keys_per_slice * ldv;

    const int tid = threadIdx.x, lane = tid & 31, w = tid >> 5;
    const int g = lane >> 2, c = lane & 3;
    const int wr = w * 16;

    for (int i = tid; i < 64 * 16; i += 128) {
        int r = i >> 4, q4 = (i & 15) * 4;
        *reinterpret_cast<float4*>(sQ + r * 68 + q4) =
            *reinterpret_cast<const float4*>(Q + (long long)r * ldq + q4);
    }

    float m0 = -1e30f, m1 = -1e30f, l0 = 0.f, l1 = 0.f;
    float Oacc[8][4];
#pragma unroll
    for (int nt = 0; nt < 8; nt++)
#pragma unroll
        for (int e = 0; e < 4; e++) Oacc[nt][e] = 0.f;

    for (int ch = 0; ch < nchunks; ch++) {
        __syncthreads();
        const float* Kc = K + (long long)ch * 64 * ldk;
        const float* Vc = V + (long long)ch * 64 * ldv;
        for (int i = tid; i < 64 * 16; i += 128) {
            int r = i >> 4, q4 = (i & 15) * 4;
            *reinterpret_cast<float4*>(sK + r * 68 + q4) =
                *reinterpret_cast<const float4*>(Kc + (long long)r * ldk + q4);
            *reinterpret_cast<float4*>(sV + r * 68 + q4) =
                *reinterpret_cast<const float4*>(Vc + (long long)r * ldv + q4);
        }
        __syncthreads();

        float lacc[8][4];
#pragma unroll
        for (int nt = 0; nt < 8; nt++)
#pragma unroll
            for (int e = 0; e < 4; e++) lacc[nt][e] = 0.f;
#pragma unroll
        for (int kk = 0; kk < 64; kk += 8) {
            uint32_t a[4];
            a[0] = __float_as_uint(sQ[(wr + g) * 68 + kk + c]);
            a[1] = __float_as_uint(sQ[(wr + g + 8) * 68 + kk + c]);
            a[2] = __float_as_uint(sQ[(wr + g) * 68 + kk + 4 + c]);
            a[3] = __float_as_uint(sQ[(wr + g + 8) * 68 + kk + 4 + c]);
#pragma unroll
            for (int nt = 0; nt < 8; nt++) {
                uint32_t b[2];
                b[0] = __float_as_uint(sK[(nt * 8 + g) * 68 + kk + c]);
                b[1] = __float_as_uint(sK[(nt * 8 + g) * 68 + kk + 4 + c]);
                mma_tf32(lacc[nt], a, b);
            }
        }

        float cm0 = -1e30f, cm1 = -1e30f;
#pragma unroll
        for (int nt = 0; nt < 8; nt++) {
            lacc[nt][0] *= SCALE_Q; lacc[nt][1] *= SCALE_Q;
            lacc[nt][2] *= SCALE_Q; lacc[nt][3] *= SCALE_Q;
            cm0 = fmaxf(cm0, fmaxf(lacc[nt][0], lacc[nt][1]));
            cm1 = fmaxf(cm1, fmaxf(lacc[nt][2], lacc[nt][3]));
        }
        cm0 = fmaxf(cm0, __shfl_xor_sync(0xffffffffu, cm0, 1));
        cm0 = fmaxf(cm0, __shfl_xor_sync(0xffffffffu, cm0, 2));
        cm1 = fmaxf(cm1, __shfl_xor_sync(0xffffffffu, cm1, 1));
        cm1 = fmaxf(cm1, __shfl_xor_sync(0xffffffffu, cm1, 2));
        float nm0 = fmaxf(m0, cm0), nm1 = fmaxf(m1, cm1);
        float f0 = __expf(m0 - nm0), f1 = __expf(m1 - nm1);
        float rs0 = 0.f, rs1 = 0.f;
#pragma unroll
        for (int nt = 0; nt < 8; nt++) {
            float p0 = __expf(lacc[nt][0] - nm0);
            float p1 = __expf(lacc[nt][1] - nm0);
            float p2 = __expf(lacc[nt][2] - nm1);
            float p3 = __expf(lacc[nt][3] - nm1);
            rs0 += p0 + p1; rs1 += p2 + p3;
            sP[(wr + g) * 68 + nt * 8 + 2 * c]     = p0;
            sP[(wr + g) * 68 + nt * 8 + 2 * c + 1] = p1;
            sP[(wr + g + 8) * 68 + nt * 8 + 2 * c]     = p2;
            sP[(wr + g + 8) * 68 + nt * 8 + 2 * c + 1] = p3;
        }
        rs0 += __shfl_xor_sync(0xffffffffu, rs0, 1);
        rs0 += __shfl_xor_sync(0xffffffffu, rs0, 2);
        rs1 += __shfl_xor_sync(0xffffffffu, rs1, 1);
        rs1 += __shfl_xor_sync(0xffffffffu, rs1, 2);
        l0 = l0 * f0 + rs0; l1 = l1 * f1 + rs1;
        m0 = nm0; m1 = nm1;
#pragma unroll
        for (int nt = 0; nt < 8; nt++) {
            Oacc[nt][0] *= f0; Oacc[nt][1] *= f0;
            Oacc[nt][2] *= f1; Oacc[nt][3] *= f1;
        }
        __syncwarp();

#pragma unroll
        for (int kk = 0; kk < 64; kk += 8) {
            uint32_t a[4];
            a[0] = __float_as_uint(sP[(wr + g) * 68 + kk + c]);
            a[1] = __float_as_uint(sP[(wr + g + 8) * 68 + kk + c]);
            a[2] = __float_as_uint(sP[(wr + g) * 68 + kk + 4 + c]);
            a[3] = __float_as_uint(sP[(wr + g + 8) * 68 + kk + 4 + c]);
#pragma unroll
            for (int nt = 0; nt < 8; nt++) {
                uint32_t b[2];
                b[0] = __float_as_uint(sV[(kk + c) * 68 + nt * 8 + g]);
                b[1] = __float_as_uint(sV[(kk + 4 + c) * 68 + nt * 8 + g]);
                mma_tf32(Oacc[nt], a, b);
            }
        }
    }

    if (SPLIT) {
        long long pb = ((long long)(h * nqt + qt) * nslices + sl) * 64;
#pragma unroll
        for (int nt = 0; nt < 8; nt++) {
            Op[(pb + wr + g) * 64 + nt * 8 + 2 * c]     = Oacc[nt][0];
            Op[(pb + wr + g) * 64 + nt * 8 + 2 * c + 1] = Oacc[nt][1];
            Op[(pb + wr + g + 8) * 64 + nt * 8 + 2 * c]     = Oacc[nt][2];
            Op[(pb + wr + g + 8) * 64 + nt * 8 + 2 * c + 1] = Oacc[nt][3];
        }
        if (c == 0) {
            mp[pb + wr + g] = m0; lp[pb + wr + g] = l0;
            mp[pb + wr + g + 8] = m1; lp[pb + wr + g + 8] = l1;
        }
    } else {
        float inv0 = 1.f / l0, inv1 = 1.f / l1;
        float* o0 = out + h * sOh + (long long)(qt * 64 + wr + g) * ldo;
        float* o1 = out + h * sOh + (long long)(qt * 64 + wr + g + 8) * ldo;
#pragma unroll
        for (int nt = 0; nt < 8; nt++) {
            o0[nt * 8 + 2 * c]     = Oacc[nt][0] * inv0;
            o0[nt * 8 + 2 * c + 1] = Oacc[nt][1] * inv0;
            o1[nt * 8 + 2 * c]     = Oacc[nt][2] * inv1;
            o1[nt * 8 + 2 * c + 1] = Oacc[nt][3] * inv1;
        }
    }
}

__global__ void fcomb_k(const float* __restrict__ Op, const float* __restrict__ mp,
                        const float* __restrict__ lp, float* __restrict__ a3v)
{
    int idx = blockIdx.x * 256 + threadIdx.x;
    int col = idx & 63, r = (idx >> 6) & 255, h = idx >> 14;
    int qt = r >> 6, rr = r & 63;
    long long hq = (long long)(h * 4 + qt) * NSL;
    float mx = -1e30f;
#pragma unroll
    for (int s = 0; s < NSL; s++) mx = fmaxf(mx, mp[(hq + s) * 64 + rr]);
    float num = 0.f, den = 0.f;
#pragma unroll
    for (int s = 0; s < NSL; s++) {
        float wgt = __expf(mp[(hq + s) * 64 + rr] - mx);
        den += wgt * lp[(hq + s) * 64 + rr];
        num += wgt * Op[((hq + s) * 64 + rr) * 64 + col];
    }
    a3v[idx] = num / den;
}

// ---------------- small kernels --------------------------------------------

__global__ void softmax256_k(float* __restrict__ S)
{
    long long row = (long long)blockIdx.x * 8 + (threadIdx.x >> 5);
    int lane = threadIdx.x & 31;
    float* p = S + row * 256 + lane * 8;
    float4 a = *reinterpret_cast<float4*>(p);
    float4 b = *reinterpret_cast<float4*>(p + 4);
    float m = fmaxf(fmaxf(fmaxf(a.x, a.y), fmaxf(a.z, a.w)),
                    fmaxf(fmaxf(b.x, b.y), fmaxf(b.z, b.w)));
#pragma unroll
    for (int o = 16; o; o >>= 1) m = fmaxf(m, __shfl_xor_sync(0xffffffffu, m, o));
    a.x = __expf(a.x - m); a.y = __expf(a.y - m); a.z = __expf(a.z - m); a.w = __expf(a.w - m);
    b.x = __expf(b.x - m); b.y = __expf(b.y - m); b.z = __expf(b.z - m); b.w = __expf(b.w - m);
    float s = a.x + a.y + a.z + a.w + b.x + b.y + b.z + b.w;
#pragma unroll
    for (int o = 16; o; o >>= 1) s += __shfl_xor_sync(0xffffffffu, s, o);
    float inv = 1.f / s;
    a.x *= inv; a.y *= inv; a.z *= inv; a.w *= inv;
    b.x *= inv; b.y *= inv; b.z *= inv; b.w *= inv;
    *reinterpret_cast<float4*>(p) = a;
    *reinterpret_cast<float4*>(p + 4) = b;
}

__global__ void ln_k(const float* __restrict__ x, float* __restrict__ y,
                     const float* __restrict__ g, const float* __restrict__ b)
{
    long long row = blockIdx.x;
    const float* xr = x + row * DIM;
    float* yr = y + row * DIM;
    int t = threadIdx.x;
    float v0 = xr[t], v1 = xr[t + 256];
    __shared__ float sm[256];
    sm[t] = v0 + v1; __syncthreads();
    for (int s = 128; s > 0; s >>= 1) { if (t < s) sm[t] += sm[t + s]; __syncthreads(); }
    float mu = sm[0] * (1.f / DIM); __syncthreads();
    float d0 = v0 - mu, d1 = v1 - mu;
    sm[t] = d0 * d0 + d1 * d1; __syncthreads();
    for (int s = 128; s > 0; s >>= 1) { if (t < s) sm[t] += sm[t + s]; __syncthreads(); }
    float rs = rsqrtf(sm[0] * (1.f / DIM) + EPSLN); __syncthreads();
    yr[t]       = d0 * rs * g[t]       + b[t];
    yr[t + 256] = d1 * rs * g[t + 256] + b[t + 256];
}

__global__ void landmark_k(const float* __restrict__ qkv,
                           float* __restrict__ ql, float* __restrict__ kl)
{
    int idx = blockIdx.x * 256 + threadIdx.x;
    int d = idx & 63, m = (idx >> 6) & 255, h = idx >> 14;
    int off = (blockIdx.y == 0) ? 0 : DIM;
    float s = 0.f;
    const float* src = qkv + off + h * DH + d;
#pragma unroll
    for (int j = 0; j < LCH; j++)
        s += src[(long long)(m * LCH + j) * (3 * DIM)];
    float* dst = (blockIdx.y == 0) ? ql : kl;
    dst[h * (MLM * DH) + m * DH + d] = s * (1.f / LCH);
}

__global__ void pinv_init_k(const float* __restrict__ A2, float* __restrict__ Z)
{
    if (blockIdx.x == 0 && threadIdx.x == 0) g_bar_cnt = 0;
    int h = blockIdx.x;
    const float* A = A2 + (long long)h * MLM * MLM;
    float* Zh = Z + (long long)h * MLM * MLM;
    int t = threadIdx.x;
    float rs = 0.f, cs = 0.f;
    for (int j = 0; j < MLM; j++) {
        rs += fabsf(A[t * MLM + j]);
        cs += fabsf(A[j * MLM + t]);
    }
    __shared__ float s1[256], s2[256];
    s1[t] = rs; s2[t] = cs; __syncthreads();
    for (int s = 128; s > 0; s >>= 1) {
        if (t < s) { s1[t] = fmaxf(s1[t], s1[t + s]); s2[t] = fmaxf(s2[t], s2[t + s]); }
        __syncthreads();
    }
    float scale = 1.f / (s1[0] * s2[0]);
    __syncthreads();
    for (int j = 0; j < MLM; j++)
        Zh[t * MLM + j] = A[j * MLM + t] * scale;
}

// tiled depthwise seq-conv
__global__ void __launch_bounds__(256)
conv1d_t_k(float* __restrict__ attn, const float* __restrict__ qkv,
           const float* __restrict__ w)
{
    __shared__ float sv[160 * 64];
    __shared__ float sw[33];
    const int t0 = blockIdx.x * 128;
    const int h = blockIdx.y;
    const int tid = threadIdx.x;
    if (tid < 33) sw[tid] = w[h * 33 + tid];
    for (int i = tid; i < 160 * 64; i += 256) {
        int chL = i & 63, p = i >> 6;
        int tok = t0 + p - 16;
        float v = 0.f;
        if (tok >= 0 && tok < NP)
            v = qkv[(long long)tok * (3 * DIM) + 2 * DIM + h * 64 + chL];
        sv[p * 64 + chL] = v;
    }
    __syncthreads();
    const int chL = tid & 63, lane = tid >> 6;
    for (int p = lane; p < 128; p += 4) {
        float acc = 0.f;
#pragma unroll
        for (int t = 0; t < 33; t++)
            acc += sw[t] * sv[(p + t) * 64 + chL];
        attn[(long long)(t0 + p) * DIM + h * 64 + chL] += acc;
    }
}

__global__ void seed_k(float* __restrict__ hA, const float* __restrict__ cls)
{
    int idx = blockIdx.x * 256 + threadIdx.x;
    if (idx < DIM) hA[idx] = cls[idx];
    int j = idx - DIM;
    if (j >= 0 && j < 89 * DIM) {
        int r = j >> 9, c = j & 511;
        hA[(long long)(1 + 8192 + r) * DIM + c] = hA[(long long)(1 + r) * DIM + c];
    }
}

// tiled PPEG
__global__ void __launch_bounds__(256)
ppeg_t_k(const float* __restrict__ hA, float* __restrict__ h2,
         const float* __restrict__ w7, const float* __restrict__ b7,
         const float* __restrict__ w5, const float* __restrict__ b5,
         const float* __restrict__ w3, const float* __restrict__ b3)
{
    extern __shared__ float psm[];
    float* sf = psm;
    float* wc = psm + 14 * 38 * 32;
    float* bs = wc + 49 * 32;

    const int c0 = blockIdx.x * 32;
    const int r0 = blockIdx.y * 8;
    const int ch0 = blockIdx.z * 32;
    const int tid = threadIdx.x;

    for (int i = tid; i < 49 * 32; i += 256) {
        int tap = i >> 5, chL = i & 31;
        int u = tap / 7 - 3, v = tap % 7 - 3;
        int ch = ch0 + chL;
        float wv = w7[ch * 49 + tap];
        if (u >= -2 && u <= 2 && v >= -2 && v <= 2) wv += w5[ch * 25 + (u + 2) * 5 + (v + 2)];
        if (u >= -1 && u <= 1 && v >= -1 && v <= 1) wv += w3[ch * 9 + (u + 1) * 3 + (v + 1)];
        wc[tap * 32 + chL] = wv;
    }
    if (tid < 32) bs[tid] = b7[ch0 + tid] + b5[ch0 + tid] + b3[ch0 + tid];

    for (int i = tid; i < 14 * 38 * 32; i += 256) {
        int chL = i & 31;
        int p = i >> 5;
        int pc = p % 38, pr = p / 38;
        int rr = r0 + pr - 3, cc = c0 + pc - 3;
        float v = 0.f;
        if (rr >= 0 && rr < HSIZE && cc >= 0 && cc < HSIZE)
            v = hA[(long long)(1 + rr * HSIZE + cc) * DIM + ch0 + chL];
        sf[p * 32 + chL] = v;
    }
    __syncthreads();

    const int chL = tid & 31, lane = tid >> 5;
    for (int p = lane; p < 8 * 32; p += 8) {
        int pr = p >> 5, pc = p & 31;
        int rr = r0 + pr, cc = c0 + pc;
        if (rr >= HSIZE || cc >= HSIZE) continue;
        float acc = sf[((pr + 3) * 38 + pc + 3) * 32 + chL] + bs[chL];
#pragma unroll
        for (int u = 0; u < 7; u++)
#pragma unroll
            for (int v = 0; v < 7; v++)
                acc += wc[(u * 7 + v) * 32 + chL] * sf[((pr + u) * 38 + pc + v) * 32 + chL];
        h2[(long long)(1 + rr * HSIZE + cc) * DIM + ch0 + chL] = acc;
    }
}

__global__ void copy_row0_k(float* __restrict__ h2, const float* __restrict__ hA)
{
    h2[threadIdx.x] = hA[threadIdx.x];
}

__global__ void final_k(const float* __restrict__ h, const float* __restrict__ g,
                        const float* __restrict__ b, const float* __restrict__ w,
                        const float* __restrict__ bias, float* __restrict__ out,
                        int out_size)
{
    int t = threadIdx.x;
    __shared__ float sm[512];
    float v = h[t];
    sm[t] = v; __syncthreads();
    for (int s = 256; s > 0; s >>= 1) { if (t < s) sm[t] += sm[t + s]; __syncthreads(); }
    float mu = sm[0] * (1.f / DIM); __syncthreads();
    float d = v - mu;
    sm[t] = d * d; __syncthreads();
    for (int s = 256; s > 0; s >>= 1) { if (t < s) sm[t] += sm[t + s]; __syncthreads(); }
    float rs = rsqrtf(sm[0] * (1.f / DIM) + EPSLN); __syncthreads();
    float e = d * rs * g[t] + b[t];
    if (5 + t < out_size) out[5 + t] = e;
    sm[t] = e * w[t * 2]; __syncthreads();
    for (int s = 256; s > 0; s >>= 1) { if (t < s) sm[t] += sm[t + s]; __syncthreads(); }
    float l0 = sm[0] + bias[0]; __syncthreads();
    sm[t] = e * w[t * 2 + 1]; __syncthreads();
    for (int s = 256; s > 0; s >>= 1) { if (t < s) sm[t] += sm[t + s]; __syncthreads(); }
    float l1 = sm[0] + bias[1]; __syncthreads();
    if (t == 0 && out_size >= 5) {
        out[0] = l0; out[1] = l1;
        float mx = fmaxf(l0, l1);
        float e0 = expf(l0 - mx), e1 = expf(l1 - mx);
        float s = e0 + e1;
        out[2] = e0 / s; out[3] = e1 / s;
        out[4] = (l1 > l0) ? 1.f : 0.f;
    }
}

// ---------------- host orchestration ---------------------------------------

constexpr int FLASH_SMEM = 4 * 64 * 68 * 4;
constexpr int SMEM_BIG_D = 3 * (128 * 36 + 32 * 136) * 4;
constexpr int SMEM_BIG_T = 3 * (128 * 36 + 128 * 36) * 4;
constexpr int SMEM_SML   = 3 * (64 * 36 + 64 * 36) * 4;
constexpr int PPEG_SMEM  = (14 * 38 * 32 + 49 * 32 + 32) * 4;

static void launch_big(const float* A, const float* B, float* C,
                       int M, int N, int K, int lda, int ldb, int ldc,
                       long long sA, long long sB, long long sC, int batch,
                       float alpha, const float* bias, const float* res, int ldres,
                       int zrows, int flags, float dcoef = 0.f)
{
    dim3 grid(N / 128, (M + 127) / 128, batch);
    if (flags & F_TRB)
        gemm_tc<128, 128, 32, 2, 4, true, 256, 2><<<grid, 256, SMEM_BIG_T>>>(
            A, B, C, M, K, lda, ldb, ldc, sA, sB, sC, alpha, bias, res, ldres, zrows, flags, dcoef);
    else
        gemm_tc<128, 128, 32, 2, 4, false, 256, 2><<<grid, 256, SMEM_BIG_D>>>(
            A, B, C, M, K, lda, ldb, ldc, sA, sB, sC, alpha, bias, res, ldres, zrows, flags, dcoef);
}

static void launch_small(const float* A, const float* B, float* C,
                         int M, int N, int K, int lda, int ldb, int ldc,
                         long long sA, long long sB, long long sC, int batch,
                         float alpha, const float* bias, const float* res, int ldres,
                         int zrows, int flags, float dcoef = 0.f)
{
    dim3 grid(N / 64, (M + 63) / 64, batch);
    if (flags & F_TRB)
        gemm_tc<64, 64, 32, 2, 2, true, 128, 4><<<grid, 128, SMEM_SML>>>(
            A, B, C, M, K, lda, ldb, ldc, sA, sB, sC, alpha, bias, res, ldres, zrows, flags, dcoef);
    else
        gemm_tc<64, 64, 32, 2, 2, false, 128, 4><<<grid, 128, SMEM_SML>>>(
            A, B, C, M, K, lda, ldb, ldc, sA, sB, sC, alpha, bias, res, ldres, zrows, flags, dcoef);
}

static void run_attn_layer(float* base, float* hbuf,
                           const float* lng, const float* lnb,
                           const float* qkvw, const float* outw, const float* outb,
                           const float* convw)
{
    float* xln  = base + OFF_XLN;
    float* qkv  = base + OFF_QKV;
    float* Opar = base + OFF_S1;
    float* mpar = base + OFF_S3;
    float* lpar = base + OFF_S3 + 32768;
    float* a2   = base + OFF_A2;
    float* Zb   = base + OFF_Z;
    float* ql   = base + OFF_QL;
    float* kl   = base + OFF_KL;
    float* a3v  = base + OFF_A3V;
    float* W2   = base + OFF_W2;
    float* attn = base + OFF_ATTN;

    const long long sA2 = (long long)MLM * MLM;
    const long long sLM = (long long)MLM * DH;

    ln_k<<<NTOK, 256>>>(hbuf, xln, lng, lnb);

    launch_big(xln, qkvw, qkv, NP, 3 * DIM, DIM, DIM, 3 * DIM, 3 * DIM,
               0, 0, 0, 1, 1.f, nullptr, nullptr, 0, PADR, 0);

    landmark_k<<<dim3(512, 2), 256>>>(qkv, ql, kl);

    flash_k<true><<<dim3(4, NSL, HEADS), 128, FLASH_SMEM>>>(
        ql, DH, sLM,
        qkv + DIM, 3 * DIM, DH,
        qkv + 2 * DIM, 3 * DIM, DH,
        KPS / 64, KPS,
        nullptr, 0, 0,
        Opar, mpar, lpar, NSL, 4);
    fcomb_k<<<(HEADS * (int)sLM) / 256, 256>>>(Opar, mpar, lpar, a3v);

    launch_small(ql, kl, a2, MLM, MLM, DH, DH, DH, MLM,
                 sLM, sLM, sA2, HEADS, SCALE_Q, nullptr, nullptr, 0, 0, F_TRB);
    softmax256_k<<<(HEADS * MLM) / 8, 256>>>(a2);

    // fused pinv: init (also resets grid barrier), then one persistent kernel
    pinv_init_k<<<HEADS, 256>>>(a2, Zb);
    pinv_fused_k<<<128, 128>>>(base);

    flash_k<false><<<dim3(NP / 64, 1, HEADS), 128, FLASH_SMEM>>>(
        qkv, 3 * DIM, DH,
        kl, DH, sLM,
        W2, DH, sLM,
        MLM / 64, MLM,
        attn, DIM, DH,
        nullptr, nullptr, nullptr, 1, NP / 64);

    conv1d_t_k<<<dim3(NP / 128, HEADS), 256>>>(attn, qkv, convw);

    launch_big(attn + (long long)PADR * DIM, outw, hbuf, NTOK, DIM, DIM,
               DIM, DIM, DIM, 0, 0, 0, 1, 1.f, outb, hbuf, DIM, 0, 0);
}

extern "C" void kernel_launch(void* const* d_in, const int* in_sizes, int n_in,
                              void* d_out, int out_size)
{
    const float* x      = (const float*)d_in[0];
    const float* fc1_w  = (const float*)d_in[1];
    const float* fc1_b  = (const float*)d_in[2];
    const float* cls    = (const float*)d_in[3];
    const float* ln1_g  = (const float*)d_in[4];
    const float* ln1_b  = (const float*)d_in[5];
    const float* qkv1_w = (const float*)d_in[6];
    const float* out1_w = (const float*)d_in[7];
    const float* out1_b = (const float*)d_in[8];
    const float* conv1w = (const float*)d_in[9];
    const float* ln2_g  = (const float*)d_in[10];
    const float* ln2_b  = (const float*)d_in[11];
    const float* qkv2_w = (const float*)d_in[12];
    const float* out2_w = (const float*)d_in[13];
    const float* out2_b = (const float*)d_in[14];
    const float* conv2w = (const float*)d_in[15];
    const float* pg7_w  = (const float*)d_in[16];
    const float* pg7_b  = (const float*)d_in[17];
    const float* pg5_w  = (const float*)d_in[18];
    const float* pg5_b  = (const float*)d_in[19];
    const float* pg3_w  = (const float*)d_in[20];
    const float* pg3_b  = (const float*)d_in[21];
    const float* norm_g = (const float*)d_in[22];
    const float* norm_b = (const float*)d_in[23];
    const float* fc2_w  = (const float*)d_in[24];
    const float* fc2_b  = (const float*)d_in[25];

    cudaFuncSetAttribute(flash_k<true>,  cudaFuncAttributeMaxDynamicSharedMemorySize, FLASH_SMEM);
    cudaFuncSetAttribute(flash_k<false>, cudaFuncAttributeMaxDynamicSharedMemorySize, FLASH_SMEM);
    cudaFuncSetAttribute((const void*)gemm_tc<128, 128, 32, 2, 4, true, 256, 2>,
                         cudaFuncAttributeMaxDynamicSharedMemorySize, SMEM_BIG_T);
    cudaFuncSetAttribute((const void*)gemm_tc<128, 128, 32, 2, 4, false, 256, 2>,
                         cudaFuncAttributeMaxDynamicSharedMemorySize, SMEM_BIG_D);
    cudaFuncSetAttribute((const void*)gemm_tc<64, 64, 32, 2, 2, true, 128, 4>,
                         cudaFuncAttributeMaxDynamicSharedMemorySize, SMEM_SML);
    cudaFuncSetAttribute((const void*)gemm_tc<64, 64, 32, 2, 2, false, 128, 4>,
                         cudaFuncAttributeMaxDynamicSharedMemorySize, SMEM_SML);
    cudaFuncSetAttribute(ppeg_t_k, cudaFuncAttributeMaxDynamicSharedMemorySize, PPEG_SMEM);

    float* base = nullptr;
    cudaGetSymbolAddress((void**)&base, g_scratch);
    float* hA = base + OFF_HA;
    float* h2 = base + OFF_H2;

    launch_big(x, fc1_w, hA + DIM, 8192, DIM, 1024, 1024, DIM, DIM,
               0, 0, 0, 1, 1.f, fc1_b, nullptr, 0, 0, F_RELU);
    seed_k<<<(90 * DIM) / 256, 256>>>(hA, cls);

    run_attn_layer(base, hA, ln1_g, ln1_b, qkv1_w, out1_w, out1_b, conv1w);

    ppeg_t_k<<<dim3(3, 12, 16), 256, PPEG_SMEM>>>(hA, h2, pg7_w, pg7_b, pg5_w, pg5_b, pg3_w, pg3_b);
    copy_row0_k<<<1, DIM>>>(h2, hA);

    run_attn_layer(base, h2, ln2_g, ln2_b, qkv2_w, out2_w, out2_b, conv2w);

    final_k<<<1, DIM>>>(h2, norm_g, norm_b, fc2_w, fc2_b, (float*)d_out, out_size);
}

// round 7
// speedup vs baseline: 8.6877x; 1.0834x over previous
#include <cuda_runtime.h>
#include <cuda_fp16.h>
#include <cstdint>

// ----------------------------------------------------------------------------
// TransMIL forward pass. fp16 tensor-core GEMMs (m16n8k16, fp32 accum) + fp16
// flash attention + tf32 persistent pinv + tiled depthwise convs.
// ----------------------------------------------------------------------------

#define NP      8448
#define NTOK    8282
#define NPIX    8281
#define HSIZE   91
#define PADR    166
#define DIM     512
#define HEADS   8
#define DH      64
#define MLM     256
#define SCALE_Q 0.125f
#define EPSLN   1e-5f
#define NSL     11
#define KPS     768

#define F_RELU  1

// ---------------- fp32 scratch ---------------------------------------------
constexpr long long SZ_H    = (long long)NTOK * DIM;
constexpr long long SZ_S    = (long long)HEADS * NP * MLM;
constexpr long long SZ_A2   = (long long)MLM * MLM * HEADS;
constexpr long long SZ_LM   = (long long)HEADS * MLM * DH;

constexpr long long OFF_HA   = 0;
constexpr long long OFF_H2   = OFF_HA  + SZ_H;
constexpr long long OFF_S1   = OFF_H2  + SZ_H;     // flash O partials
constexpr long long OFF_S3   = OFF_S1  + SZ_S;     // flash m/l partials
constexpr long long OFF_A2   = OFF_S3  + SZ_S;
constexpr long long OFF_Z    = OFF_A2  + SZ_A2;
constexpr long long OFF_XZ   = OFF_Z   + SZ_A2;
constexpr long long OFF_T    = OFF_XZ  + SZ_A2;
constexpr long long OFF_T4   = OFF_T   + SZ_A2;
constexpr long long OFF_P    = OFF_T4  + SZ_A2;
constexpr long long OFF_A3V  = OFF_P   + SZ_A2;
constexpr long long OFF_W2   = OFF_A3V + SZ_LM;
constexpr long long SCRATCH_TOTAL = OFF_W2 + SZ_LM;

__device__ float g_scratch[SCRATCH_TOTAL];
__device__ unsigned g_bar_cnt;

// ---------------- fp16 scratch ---------------------------------------------
constexpr long long HOFF_X    = 0;                              // 8192x1024
constexpr long long HOFF_WF   = HOFF_X    + 8388608;            // fc1_w^T 512x1024
constexpr long long HOFF_WQ1  = HOFF_WF   + 524288;             // qkv1_w^T 1536x512
constexpr long long HOFF_WQ2  = HOFF_WQ1  + 786432;
constexpr long long HOFF_WO1  = HOFF_WQ2  + 786432;             // out1_w^T 512x512
constexpr long long HOFF_WO2  = HOFF_WO1  + 262144;
constexpr long long HOFF_XLN  = HOFF_WO2  + 262144;             // NTOK x 512
constexpr long long HOFF_QKV  = HOFF_XLN  + SZ_H;               // NP x 1536
constexpr long long HOFF_QL   = HOFF_QKV  + (long long)NP * 1536;
constexpr long long HOFF_KL   = HOFF_QL   + SZ_LM;
constexpr long long HOFF_W2   = HOFF_KL   + SZ_LM;
constexpr long long HOFF_ATTN = HOFF_W2   + SZ_LM;              // NP x 512
constexpr long long HSCR_TOTAL = HOFF_ATTN + (long long)NP * DIM;

__device__ __half g_hscr[HSCR_TOTAL];

// ---------------- mma helpers ----------------------------------------------

__device__ __forceinline__ void cpa16(uint32_t dst, const void* src, int validBytes)
{
    asm volatile("cp.async.cg.shared.global [%0], [%1], 16, %2;\n"
                 :: "r"(dst), "l"(src), "r"(validBytes));
}

__device__ __forceinline__ void mma_tf32(float* d, const uint32_t* a, const uint32_t* b)
{
    asm volatile(
        "mma.sync.aligned.m16n8k8.row.col.f32.tf32.tf32.f32 "
        "{%0,%1,%2,%3}, {%4,%5,%6,%7}, {%8,%9}, {%0,%1,%2,%3};"
        : "+f"(d[0]), "+f"(d[1]), "+f"(d[2]), "+f"(d[3])
        : "r"(a[0]), "r"(a[1]), "r"(a[2]), "r"(a[3]), "r"(b[0]), "r"(b[1]));
}

__device__ __forceinline__ void mma_f16(float* d, const uint32_t* a, const uint32_t* b)
{
    asm volatile(
        "mma.sync.aligned.m16n8k16.row.col.f32.f16.f16.f32 "
        "{%0,%1,%2,%3}, {%4,%5,%6,%7}, {%8,%9}, {%0,%1,%2,%3};"
        : "+f"(d[0]), "+f"(d[1]), "+f"(d[2]), "+f"(d[3])
        : "r"(a[0]), "r"(a[1]), "r"(a[2]), "r"(a[3]), "r"(b[0]), "r"(b[1]));
}

// ---------------- fp16 tensor-core GEMM, 3-stage pipeline -------------------
// C[M,N] = epilogue(alpha * A_eff @ B^T); A fp16 [m][k], B fp16 [N][K] row-major.
// A_eff row i = (i < zrows) ? 0 : A[i - zrows].  OUT16: C half, else float
// with optional bias/res/relu.  Requires K % BK == 0, N % BN == 0.
template<int BM, int BN, int BK, int WM, int WN, bool OUT16, int THREADS, int MAXB>
__global__ void __launch_bounds__(THREADS, MAXB)
gemm_hc(const __half* __restrict__ A, const __half* __restrict__ B,
        void* __restrict__ Cv,
        int Mr, int K, int lda, int ldb, int ldc,
        long long sA, long long sB, long long sC,
        float alpha,
        const float* __restrict__ bias,
        const float* __restrict__ res, int ldres,
        int zrows, int flags)
{
    constexpr int MT = BM / (WM * 16);
    constexpr int NT = BN / (WN * 8);
    constexpr int SK  = BK + 8;
    constexpr int ASZ = BM * SK;
    constexpr int BSZ = BN * SK;
    constexpr int CA = BM * BK / (8 * THREADS);
    constexpr int CB = BN * BK / (8 * THREADS);
    static_assert(CA >= 1 && CB >= 1, "chunks");
    static_assert(WM * WN == THREADS / 32, "warps");

    extern __shared__ __half hsm[];
    __half* sAr = hsm;
    __half* sBr = hsm + 3 * ASZ;

    const int bz = blockIdx.z;
    A += bz * sA; B += bz * sB;
    __half* C16 = OUT16 ? ((__half*)Cv + bz * sC) : nullptr;
    float*  C32 = OUT16 ? nullptr : ((float*)Cv + bz * sC);

    const int tid = threadIdx.x;
    const int lane = tid & 31;
    const int w = tid >> 5;
    const int wm = w / WN, wn = w % WN;
    const int m0 = wm * MT * 16;
    const int n0 = wn * NT * 8;
    const int g = lane >> 2, c = lane & 3;
    const int rowBase = blockIdx.y * BM;
    const int colBase = blockIdx.x * BN;

    const uint32_t saA = (uint32_t)__cvta_generic_to_shared(sAr);
    const uint32_t saB = (uint32_t)__cvta_generic_to_shared(sBr);

    auto loadTiles = [&](int st, int k0) {
#pragma unroll
        for (int v = 0; v < CA; v++) {
            int idx = tid + v * THREADS;
            int m = idx / (BK / 8), kq = idx % (BK / 8);
            int gm = rowBase + m, am = gm - zrows;
            bool ok = (gm < Mr) && (am >= 0);
            const __half* src = A + (ok ? (long long)am * lda : 0) + k0 + kq * 8;
            cpa16(saA + (uint32_t)(st * ASZ + m * SK + kq * 8) * 2, src, ok ? 16 : 0);
        }
#pragma unroll
        for (int v = 0; v < CB; v++) {
            int idx = tid + v * THREADS;
            int n = idx / (BK / 8), kq = idx % (BK / 8);
            const __half* src = B + (long long)(colBase + n) * ldb + k0 + kq * 8;
            cpa16(saB + (uint32_t)(st * BSZ + n * SK + kq * 8) * 2, src, 16);
        }
    };

    float acc[MT][NT][4];
#pragma unroll
    for (int i = 0; i < MT; i++)
#pragma unroll
        for (int j = 0; j < NT; j++)
#pragma unroll
            for (int e = 0; e < 4; e++) acc[i][j][e] = 0.f;

    const int nk = K / BK;
    loadTiles(0, 0);
    asm volatile("cp.async.commit_group;");
    if (nk > 1) loadTiles(1, BK);
    asm volatile("cp.async.commit_group;");

    for (int t = 0; t < nk; t++) {
        if (t + 1 < nk) { asm volatile("cp.async.wait_group 1;"); }
        else            { asm volatile("cp.async.wait_group 0;"); }
        __syncthreads();
        if (t + 2 < nk) {
            loadTiles((t + 2) % 3, (t + 2) * BK);
            asm volatile("cp.async.commit_group;");
        }

        const int st = t % 3;
        const __half* pA = sAr + st * ASZ;
        const __half* pB = sBr + st * BSZ;
#pragma unroll
        for (int kk = 0; kk < BK; kk += 16) {
            uint32_t af[MT][4], bf[NT][2];
#pragma unroll
            for (int mt = 0; mt < MT; mt++) {
                int r = m0 + mt * 16 + g;
                af[mt][0] = *(const uint32_t*)&pA[r * SK + kk + 2 * c];
                af[mt][1] = *(const uint32_t*)&pA[(r + 8) * SK + kk + 2 * c];
                af[mt][2] = *(const uint32_t*)&pA[r * SK + kk + 8 + 2 * c];
                af[mt][3] = *(const uint32_t*)&pA[(r + 8) * SK + kk + 8 + 2 * c];
            }
#pragma unroll
            for (int nt = 0; nt < NT; nt++) {
                int col = n0 + nt * 8 + g;
                bf[nt][0] = *(const uint32_t*)&pB[col * SK + kk + 2 * c];
                bf[nt][1] = *(const uint32_t*)&pB[col * SK + kk + 8 + 2 * c];
            }
#pragma unroll
            for (int mt = 0; mt < MT; mt++)
#pragma unroll
                for (int nt = 0; nt < NT; nt++)
                    mma_f16(acc[mt][nt], af[mt], bf[nt]);
        }
    }

#pragma unroll
    for (int mt = 0; mt < MT; mt++) {
#pragma unroll
        for (int nt = 0; nt < NT; nt++) {
            int gn = colBase + n0 + nt * 8 + 2 * c;
#pragma unroll
            for (int half = 0; half < 2; half++) {
                int gm = rowBase + m0 + mt * 16 + g + half * 8;
                if (gm >= Mr) continue;
#pragma unroll
                for (int e = 0; e < 2; e++) {
                    float v = alpha * acc[mt][nt][half * 2 + e];
                    int gnn = gn + e;
                    if (OUT16) {
                        C16[(long long)gm * ldc + gnn] = __float2half(v);
                    } else {
                        if (bias) v += bias[gnn];
                        if (res)  v += res[(long long)gm * ldres + gnn];
                        if (flags & F_RELU) v = fmaxf(v, 0.f);
                        C32[(long long)gm * ldc + gnn] = v;
                    }
                }
            }
        }
    }
}

// ---------------- persistent fused pinv kernel (tf32, unchanged) ------------
__device__ __forceinline__ void grid_bar(int gen)
{
    __syncthreads();
    if (threadIdx.x == 0) {
        __threadfence();
        atomicAdd(&g_bar_cnt, 1u);
        unsigned target = (unsigned)(gen + 1) * 128u;
        while (*(volatile unsigned*)&g_bar_cnt < target) __nanosleep(32);
        __threadfence();
    }
    __syncthreads();
}

__global__ void __launch_bounds__(128, 1)
pinv_fused_k(float* __restrict__ base)
{
    __shared__ float sA2[2][64 * 36];
    __shared__ float sB2[2][32 * 72];

    const int bid = blockIdx.x;
    const int h = bid >> 4;
    const int t = bid & 15;
    const int rowBase = (t >> 2) * 64;
    const int colBase = (t & 3) * 64;

    const long long hA2 = (long long)h * (MLM * MLM);
    const long long hLM = (long long)h * (MLM * DH);
    float* a2  = base + OFF_A2  + hA2;
    float* Zb  = base + OFF_Z   + hA2;
    float* XZ  = base + OFF_XZ  + hA2;
    float* Tb  = base + OFF_T   + hA2;
    float* T4  = base + OFF_T4  + hA2;
    float* Pb  = base + OFF_P   + hA2;
    float* a3v = base + OFF_A3V + hLM;
    float* W2  = base + OFF_W2  + hLM;

    const int tid = threadIdx.x;
    const int lane = tid & 31;
    const int w = tid >> 5;
    const int wm = w >> 1, wn = w & 1;
    const int m0 = wm * 32;
    const int n0 = wn * 32;
    const int g = lane >> 2, c = lane & 3;

    const uint32_t saA = (uint32_t)__cvta_generic_to_shared(&sA2[0][0]);
    const uint32_t saB = (uint32_t)__cvta_generic_to_shared(&sB2[0][0]);

    for (int ph = 0; ph < 25; ph++) {
        const float *Ao, *Bo;
        float* Co;
        float alpha = 1.f, dcoef = 0.f;
        bool diag = false;
        int N = 256, ldb = 256, ldc = 256;

        if (ph < 24) {
            int it = ph >> 2, sub = ph & 3;
            float* Zc = (it & 1) ? Pb : Zb;
            float* Pc = (it & 1) ? Zb : Pb;
            switch (sub) {
                case 0: Ao = a2; Bo = Zc; Co = XZ; break;
                case 1: Ao = XZ; Bo = XZ; Co = Tb; diag = true; dcoef = 7.f; break;
                case 2: Ao = XZ; Bo = Tb; Co = T4; diag = true; dcoef = 15.f; break;
                default: Ao = Zc; Bo = T4; Co = Pc; diag = true; dcoef = 13.f; alpha = 0.25f; break;
            }
        } else {
            Ao = Zb; Bo = a3v; Co = W2; N = 64; ldb = 64; ldc = 64;
        }

        if (colBase < N) {
            auto loadT = [&](int st, int k0) {
#pragma unroll
                for (int v = 0; v < 4; v++) {
                    int idx = tid + v * 128;
                    int m = idx >> 3, kq = idx & 7;
                    cpa16(saA + (uint32_t)(st * 2304 + m * 36 + kq * 4) * 4,
                          Ao + (long long)(rowBase + m) * 256 + k0 + kq * 4, 16);
                }
#pragma unroll
                for (int v = 0; v < 4; v++) {
                    int idx = tid + v * 128;
                    int kk = idx >> 4, nq = idx & 15;
                    cpa16(saB + (uint32_t)(st * 2304 + kk * 72 + nq * 4) * 4,
                          Bo + (long long)(k0 + kk) * ldb + colBase + nq * 4, 16);
                }
            };

            float acc[2][4][4];
#pragma unroll
            for (int i = 0; i < 2; i++)
#pragma unroll
                for (int j = 0; j < 4; j++)
#pragma unroll
                    for (int e = 0; e < 4; e++) acc[i][j][e] = 0.f;

            loadT(0, 0);
            asm volatile("cp.async.commit_group;");

            for (int kt = 0; kt < 8; kt++) {
                if (kt + 1 < 8) {
                    loadT((kt + 1) & 1, (kt + 1) * 32);
                    asm volatile("cp.async.commit_group;");
                    asm volatile("cp.async.wait_group 1;");
                } else {
                    asm volatile("cp.async.wait_group 0;");
                }
                __syncthreads();

                const float* pA = &sA2[kt & 1][0];
                const float* pB = &sB2[kt & 1][0];
#pragma unroll
                for (int kk = 0; kk < 32; kk += 8) {
                    uint32_t af[2][4], bf[4][2];
#pragma unroll
                    for (int mt = 0; mt < 2; mt++) {
                        int r = m0 + mt * 16 + g;
                        af[mt][0] = __float_as_uint(pA[r * 36 + kk + c]);
                        af[mt][1] = __float_as_uint(pA[(r + 8) * 36 + kk + c]);
                        af[mt][2] = __float_as_uint(pA[r * 36 + kk + 4 + c]);
                        af[mt][3] = __float_as_uint(pA[(r + 8) * 36 + kk + 4 + c]);
                    }
#pragma unroll
                    for (int nt = 0; nt < 4; nt++) {
                        int col = n0 + nt * 8 + g;
                        bf[nt][0] = __float_as_uint(pB[(kk + c) * 72 + col]);
                        bf[nt][1] = __float_as_uint(pB[(kk + 4 + c) * 72 + col]);
                    }
#pragma unroll
                    for (int mt = 0; mt < 2; mt++)
#pragma unroll
                        for (int nt = 0; nt < 4; nt++)
                            mma_tf32(acc[mt][nt], af[mt], bf[nt]);
                }
                __syncthreads();
            }

#pragma unroll
            for (int mt = 0; mt < 2; mt++) {
#pragma unroll
                for (int nt = 0; nt < 4; nt++) {
                    int gn = colBase + n0 + nt * 8 + 2 * c;
#pragma unroll
                    for (int half = 0; half < 2; half++) {
                        int gm = rowBase + m0 + mt * 16 + g + half * 8;
#pragma unroll
                        for (int e = 0; e < 2; e++) {
                            float v = acc[mt][nt][half * 2 + e];
                            int gnn = gn + e;
                            if (diag)
                                v = alpha * (dcoef * Ao[(long long)gm * 256 + gnn] - v);
                            else
                                v = alpha * v;
                            Co[(long long)gm * ldc + gnn] = v;
                        }
                    }
                }
            }
        }
        grid_bar(ph);
    }
}

// ---------------- fp16 flash attention kernel -------------------------------
// softmax(SCALE_Q * Q @ K^T) @ V, 64-row q-tiles, key chunks of 64.
// SPLIT: unnormalized partials (fp32 O, m, l). !SPLIT: fp16 out.
template<bool SPLIT>
__global__ void __launch_bounds__(128, 4)
flash_h(const __half* __restrict__ Qb, int ldq, long long sQh,
        const __half* __restrict__ Kb, int ldk, long long sKh,
        const __half* __restrict__ Vb, int ldv, long long sVh,
        int nchunks, int keys_per_slice,
        __half* __restrict__ out, int ldo, long long sOh,
        float* __restrict__ Op, float* __restrict__ mp, float* __restrict__ lp,
        int nslices, int nqt)
{
    __shared__ __half sQ[64 * 72];
    __shared__ __half sK[64 * 72];
    __shared__ __half sVt[64 * 72];   // transposed: [d][key]
    __shared__ __half sP[64 * 72];

    const int h = blockIdx.z, qt = blockIdx.x;
    const int sl = SPLIT ? blockIdx.y : 0;
    const __half* Q = Qb + h * sQh + (long long)qt * 64 * ldq;
    const __half* K = Kb + h * sKh + (long long)sl * keys_per_slice * ldk;
    const __half* V = Vb + h * sVh + (long long)sl * keys_per_slice * ldv;

    const int tid = threadIdx.x, lane = tid & 31, w = tid >> 5;
    const int g = lane >> 2, c = lane & 3;
    const int wr = w * 16;

    // load Q tile (64 rows x 64 halves)
    for (int i = tid; i < 64 * 8; i += 128) {
        int r = i >> 3, q8 = (i & 7) * 8;
        *reinterpret_cast<float4*>(&sQ[r * 72 + q8]) =
            *reinterpret_cast<const float4*>(Q + (long long)r * ldq + q8);
    }

    float m0 = -1e30f, m1 = -1e30f, l0 = 0.f, l1 = 0.f;
    float Oacc[8][4];
#pragma unroll
    for (int nt = 0; nt < 8; nt++)
#pragma unroll
        for (int e = 0; e < 4; e++) Oacc[nt][e] = 0.f;

    for (int ch = 0; ch < nchunks; ch++) {
        __syncthreads();
        const __half* Kc = K + (long long)ch * 64 * ldk;
        const __half* Vc = V + (long long)ch * 64 * ldv;
        for (int i = tid; i < 64 * 8; i += 128) {
            int r = i >> 3, q8 = (i & 7) * 8;
            *reinterpret_cast<float4*>(&sK[r * 72 + q8]) =
                *reinterpret_cast<const float4*>(Kc + (long long)r * ldk + q8);
            float4 v4 = *reinterpret_cast<const float4*>(Vc + (long long)r * ldv + q8);
            const __half* vh = reinterpret_cast<const __half*>(&v4);
#pragma unroll
            for (int j = 0; j < 8; j++)
                sVt[(q8 + j) * 72 + r] = vh[j];
        }
        __syncthreads();

        // logits L = Q @ K^T
        float lacc[8][4];
#pragma unroll
        for (int nt = 0; nt < 8; nt++)
#pragma unroll
            for (int e = 0; e < 4; e++) lacc[nt][e] = 0.f;
#pragma unroll
        for (int kk = 0; kk < 64; kk += 16) {
            uint32_t a[4];
            a[0] = *(const uint32_t*)&sQ[(wr + g) * 72 + kk + 2 * c];
            a[1] = *(const uint32_t*)&sQ[(wr + g + 8) * 72 + kk + 2 * c];
            a[2] = *(const uint32_t*)&sQ[(wr + g) * 72 + kk + 8 + 2 * c];
            a[3] = *(const uint32_t*)&sQ[(wr + g + 8) * 72 + kk + 8 + 2 * c];
#pragma unroll
            for (int nt = 0; nt < 8; nt++) {
                uint32_t b[2];
                b[0] = *(const uint32_t*)&sK[(nt * 8 + g) * 72 + kk + 2 * c];
                b[1] = *(const uint32_t*)&sK[(nt * 8 + g) * 72 + kk + 8 + 2 * c];
                mma_f16(lacc[nt], a, b);
            }
        }

        // online softmax update
        float cm0 = -1e30f, cm1 = -1e30f;
#pragma unroll
        for (int nt = 0; nt < 8; nt++) {
            lacc[nt][0] *= SCALE_Q; lacc[nt][1] *= SCALE_Q;
            lacc[nt][2] *= SCALE_Q; lacc[nt][3] *= SCALE_Q;
            cm0 = fmaxf(cm0, fmaxf(lacc[nt][0], lacc[nt][1]));
            cm1 = fmaxf(cm1, fmaxf(lacc[nt][2], lacc[nt][3]));
        }
        cm0 = fmaxf(cm0, __shfl_xor_sync(0xffffffffu, cm0, 1));
        cm0 = fmaxf(cm0, __shfl_xor_sync(0xffffffffu, cm0, 2));
        cm1 = fmaxf(cm1, __shfl_xor_sync(0xffffffffu, cm1, 1));
        cm1 = fmaxf(cm1, __shfl_xor_sync(0xffffffffu, cm1, 2));
        float nm0 = fmaxf(m0, cm0), nm1 = fmaxf(m1, cm1);
        float f0 = __expf(m0 - nm0), f1 = __expf(m1 - nm1);
        float rs0 = 0.f, rs1 = 0.f;
#pragma unroll
        for (int nt = 0; nt < 8; nt++) {
            float p0 = __expf(lacc[nt][0] - nm0);
            float p1 = __expf(lacc[nt][1] - nm0);
            float p2 = __expf(lacc[nt][2] - nm1);
            float p3 = __expf(lacc[nt][3] - nm1);
            rs0 += p0 + p1; rs1 += p2 + p3;
            *reinterpret_cast<__half2*>(&sP[(wr + g) * 72 + nt * 8 + 2 * c]) =
                __floats2half2_rn(p0, p1);
            *reinterpret_cast<__half2*>(&sP[(wr + g + 8) * 72 + nt * 8 + 2 * c]) =
                __floats2half2_rn(p2, p3);
        }
        rs0 += __shfl_xor_sync(0xffffffffu, rs0, 1);
        rs0 += __shfl_xor_sync(0xffffffffu, rs0, 2);
        rs1 += __shfl_xor_sync(0xffffffffu, rs1, 1);
        rs1 += __shfl_xor_sync(0xffffffffu, rs1, 2);
        l0 = l0 * f0 + rs0; l1 = l1 * f1 + rs1;
        m0 = nm0; m1 = nm1;
#pragma unroll
        for (int nt = 0; nt < 8; nt++) {
            Oacc[nt][0] *= f0; Oacc[nt][1] *= f0;
            Oacc[nt][2] *= f1; Oacc[nt][3] *= f1;
        }
        __syncwarp();

        // O += P @ V  (A = sP [q][key], B = sVt [d][key])
#pragma unroll
        for (int kk = 0; kk < 64; kk += 16) {
            uint32_t a[4];
            a[0] = *(const uint32_t*)&sP[(wr + g) * 72 + kk + 2 * c];
            a[1] = *(const uint32_t*)&sP[(wr + g + 8) * 72 + kk + 2 * c];
            a[2] = *(const uint32_t*)&sP[(wr + g) * 72 + kk + 8 + 2 * c];
            a[3] = *(const uint32_t*)&sP[(wr + g + 8) * 72 + kk + 8 + 2 * c];
#pragma unroll
            for (int nt = 0; nt < 8; nt++) {
                uint32_t b[2];
                b[0] = *(const uint32_t*)&sVt[(nt * 8 + g) * 72 + kk + 2 * c];
                b[1] = *(const uint32_t*)&sVt[(nt * 8 + g) * 72 + kk + 8 + 2 * c];
                mma_f16(Oacc[nt], a, b);
            }
        }
    }

    if (SPLIT) {
        long long pb = ((long long)(h * nqt + qt) * nslices + sl) * 64;
#pragma unroll
        for (int nt = 0; nt < 8; nt++) {
            Op[(pb + wr + g) * 64 + nt * 8 + 2 * c]     = Oacc[nt][0];
            Op[(pb + wr + g) * 64 + nt * 8 + 2 * c + 1] = Oacc[nt][1];
            Op[(pb + wr + g + 8) * 64 + nt * 8 + 2 * c]     = Oacc[nt][2];
            Op[(pb + wr + g + 8) * 64 + nt * 8 + 2 * c + 1] = Oacc[nt][3];
        }
        if (c == 0) {
            mp[pb + wr + g] = m0; lp[pb + wr + g] = l0;
            mp[pb + wr + g + 8] = m1; lp[pb + wr + g + 8] = l1;
        }
    } else {
        float inv0 = 1.f / l0, inv1 = 1.f / l1;
        __half* o0 = out + h * sOh + (long long)(qt * 64 + wr + g) * ldo;
        __half* o1 = out + h * sOh + (long long)(qt * 64 + wr + g + 8) * ldo;
#pragma unroll
        for (int nt = 0; nt < 8; nt++) {
            o0[nt * 8 + 2 * c]     = __float2half(Oacc[nt][0] * inv0);
            o0[nt * 8 + 2 * c + 1] = __float2half(Oacc[nt][1] * inv0);
            o1[nt * 8 + 2 * c]     = __float2half(Oacc[nt][2] * inv1);
            o1[nt * 8 + 2 * c + 1] = __float2half(Oacc[nt][3] * inv1);
        }
    }
}

__global__ void fcomb_k(const float* __restrict__ Op, const float* __restrict__ mp,
                        const float* __restrict__ lp, float* __restrict__ a3v)
{
    int idx = blockIdx.x * 256 + threadIdx.x;
    int col = idx & 63, r = (idx >> 6) & 255, h = idx >> 14;
    int qt = r >> 6, rr = r & 63;
    long long hq = (long long)(h * 4 + qt) * NSL;
    float mx = -1e30f;
#pragma unroll
    for (int s = 0; s < NSL; s++) mx = fmaxf(mx, mp[(hq + s) * 64 + rr]);
    float num = 0.f, den = 0.f;
#pragma unroll
    for (int s = 0; s < NSL; s++) {
        float wgt = __expf(mp[(hq + s) * 64 + rr] - mx);
        den += wgt * lp[(hq + s) * 64 + rr];
        num += wgt * Op[((hq + s) * 64 + rr) * 64 + col];
    }
    a3v[idx] = num / den;
}

// ---------------- conversion + small kernels --------------------------------

__global__ void cvt_k(__half* __restrict__ dst, const float* __restrict__ src, int n)
{
    int idx = blockIdx.x * 256 + threadIdx.x;
    if (idx < n) dst[idx] = __float2half(src[idx]);
}

// fp32 [K][N] -> fp16 [N][K]
__global__ void cvtT_k(__half* __restrict__ dst, const float* __restrict__ src,
                       int K, int N)
{
    int idx = blockIdx.x * 256 + threadIdx.x;
    if (idx >= N * K) return;
    int n = idx / K, k = idx % K;
    dst[idx] = __float2half(src[(long long)k * N + n]);
}

__global__ void softmax256_k(float* __restrict__ S)
{
    long long row = (long long)blockIdx.x * 8 + (threadIdx.x >> 5);
    int lane = threadIdx.x & 31;
    float* p = S + row * 256 + lane * 8;
    float4 a = *reinterpret_cast<float4*>(p);
    float4 b = *reinterpret_cast<float4*>(p + 4);
    float m = fmaxf(fmaxf(fmaxf(a.x, a.y), fmaxf(a.z, a.w)),
                    fmaxf(fmaxf(b.x, b.y), fmaxf(b.z, b.w)));
#pragma unroll
    for (int o = 16; o; o >>= 1) m = fmaxf(m, __shfl_xor_sync(0xffffffffu, m, o));
    a.x = __expf(a.x - m); a.y = __expf(a.y - m); a.z = __expf(a.z - m); a.w = __expf(a.w - m);
    b.x = __expf(b.x - m); b.y = __expf(b.y - m); b.z = __expf(b.z - m); b.w = __expf(b.w - m);
    float s = a.x + a.y + a.z + a.w + b.x + b.y + b.z + b.w;
#pragma unroll
    for (int o = 16; o; o >>= 1) s += __shfl_xor_sync(0xffffffffu, s, o);
    float inv = 1.f / s;
    a.x *= inv; a.y *= inv; a.z *= inv; a.w *= inv;
    b.x *= inv; b.y *= inv; b.z *= inv; b.w *= inv;
    *reinterpret_cast<float4*>(p) = a;
    *reinterpret_cast<float4*>(p + 4) = b;
}

// LayerNorm: fp32 in, fp16 out
__global__ void ln_k(const float* __restrict__ x, __half* __restrict__ y,
                     const float* __restrict__ g, const float* __restrict__ b)
{
    long long row = blockIdx.x;
    const float* xr = x + row * DIM;
    __half* yr = y + row * DIM;
    int t = threadIdx.x;
    float v0 = xr[t], v1 = xr[t + 256];
    __shared__ float sm[256];
    sm[t] = v0 + v1; __syncthreads();
    for (int s = 128; s > 0; s >>= 1) { if (t < s) sm[t] += sm[t + s]; __syncthreads(); }
    float mu = sm[0] * (1.f / DIM); __syncthreads();
    float d0 = v0 - mu, d1 = v1 - mu;
    sm[t] = d0 * d0 + d1 * d1; __syncthreads();
    for (int s = 128; s > 0; s >>= 1) { if (t < s) sm[t] += sm[t + s]; __syncthreads(); }
    float rs = rsqrtf(sm[0] * (1.f / DIM) + EPSLN); __syncthreads();
    yr[t]       = __float2half(d0 * rs * g[t]       + b[t]);
    yr[t + 256] = __float2half(d1 * rs * g[t + 256] + b[t + 256]);
}

__global__ void landmark_k(const __half* __restrict__ qkv,
                           __half* __restrict__ ql, __half* __restrict__ kl)
{
    int idx = blockIdx.x * 256 + threadIdx.x;
    int d = idx & 63, m = (idx >> 6) & 255, h = idx >> 14;
    int off = (blockIdx.y == 0) ? 0 : DIM;
    float s = 0.f;
    const __half* src = qkv + off + h * DH + d;
#pragma unroll
    for (int j = 0; j < 33; j++)
        s += __half2float(src[(long long)(m * 33 + j) * 1536]);
    __half* dst = (blockIdx.y == 0) ? ql : kl;
    dst[h * (MLM * DH) + m * DH + d] = __float2half(s * (1.f / 33.f));
}

__global__ void pinv_init_k(const float* __restrict__ A2, float* __restrict__ Z)
{
    if (blockIdx.x == 0 && threadIdx.x == 0) g_bar_cnt = 0;
    int h = blockIdx.x;
    const float* A = A2 + (long long)h * MLM * MLM;
    float* Zh = Z + (long long)h * MLM * MLM;
    int t = threadIdx.x;
    float rs = 0.f, cs = 0.f;
    for (int j = 0; j < MLM; j++) {
        rs += fabsf(A[t * MLM + j]);
        cs += fabsf(A[j * MLM + t]);
    }
    __shared__ float s1[256], s2[256];
    s1[t] = rs; s2[t] = cs; __syncthreads();
    for (int s = 128; s > 0; s >>= 1) {
        if (t < s) { s1[t] = fmaxf(s1[t], s1[t + s]); s2[t] = fmaxf(s2[t], s2[t + s]); }
        __syncthreads();
    }
    float scale = 1.f / (s1[0] * s2[0]);
    __syncthreads();
    for (int j = 0; j < MLM; j++)
        Zh[t * MLM + j] = A[j * MLM + t] * scale;
}

// tiled depthwise seq-conv on fp16 v, accumulating into fp16 attn
__global__ void __launch_bounds__(256)
conv1d_t_k(__half* __restrict__ attn, const __half* __restrict__ qkv,
           const float* __restrict__ w)
{
    __shared__ float sv[160 * 64];
    __shared__ float sw[33];
    const int t0 = blockIdx.x * 128;
    const int h = blockIdx.y;
    const int tid = threadIdx.x;
    if (tid < 33) sw[tid] = w[h * 33 + tid];
    for (int i = tid; i < 160 * 64; i += 256) {
        int chL = i & 63, p = i >> 6;
        int tok = t0 + p - 16;
        float v = 0.f;
        if (tok >= 0 && tok < NP)
            v = __half2float(qkv[(long long)tok * 1536 + 1024 + h * 64 + chL]);
        sv[p * 64 + chL] = v;
    }
    __syncthreads();
    const int chL = tid & 63, lane = tid >> 6;
    for (int p = lane; p < 128; p += 4) {
        float acc = 0.f;
#pragma unroll
        for (int t = 0; t < 33; t++)
            acc += sw[t] * sv[(p + t) * 64 + chL];
        long long o = (long long)(t0 + p) * DIM + h * 64 + chL;
        attn[o] = __float2half(__half2float(attn[o]) + acc);
    }
}

__global__ void seed_k(float* __restrict__ hA, const float* __restrict__ cls)
{
    int idx = blockIdx.x * 256 + threadIdx.x;
    if (idx < DIM) hA[idx] = cls[idx];
    int j = idx - DIM;
    if (j >= 0 && j < 89 * DIM) {
        int r = j >> 9, c = j & 511;
        hA[(long long)(1 + 8192 + r) * DIM + c] = hA[(long long)(1 + r) * DIM + c];
    }
}

// tiled PPEG (fp32)
__global__ void __launch_bounds__(256)
ppeg_t_k(const float* __restrict__ hA, float* __restrict__ h2,
         const float* __restrict__ w7, const float* __restrict__ b7,
         const float* __restrict__ w5, const float* __restrict__ b5,
         const float* __restrict__ w3, const float* __restrict__ b3)
{
    extern __shared__ float psm[];
    float* sf = psm;
    float* wc = psm + 14 * 38 * 32;
    float* bs = wc + 49 * 32;

    const int c0 = blockIdx.x * 32;
    const int r0 = blockIdx.y * 8;
    const int ch0 = blockIdx.z * 32;
    const int tid = threadIdx.x;

    for (int i = tid; i < 49 * 32; i += 256) {
        int tap = i >> 5, chL = i & 31;
        int u = tap / 7 - 3, v = tap % 7 - 3;
        int ch = ch0 + chL;
        float wv = w7[ch * 49 + tap];
        if (u >= -2 && u <= 2 && v >= -2 && v <= 2) wv += w5[ch * 25 + (u + 2) * 5 + (v + 2)];
        if (u >= -1 && u <= 1 && v >= -1 && v <= 1) wv += w3[ch * 9 + (u + 1) * 3 + (v + 1)];
        wc[tap * 32 + chL] = wv;
    }
    if (tid < 32) bs[tid] = b7[ch0 + tid] + b5[ch0 + tid] + b3[ch0 + tid];

    for (int i = tid; i < 14 * 38 * 32; i += 256) {
        int chL = i & 31;
        int p = i >> 5;
        int pc = p % 38, pr = p / 38;
        int rr = r0 + pr - 3, cc = c0 + pc - 3;
        float v = 0.f;
        if (rr >= 0 && rr < HSIZE && cc >= 0 && cc < HSIZE)
            v = hA[(long long)(1 + rr * HSIZE + cc) * DIM + ch0 + chL];
        sf[p * 32 + chL] = v;
    }
    __syncthreads();

    const int chL = tid & 31, lane = tid >> 5;
    for (int p = lane; p < 8 * 32; p += 8) {
        int pr = p >> 5, pc = p & 31;
        int rr = r0 + pr, cc = c0 + pc;
        if (rr >= HSIZE || cc >= HSIZE) continue;
        float acc = sf[((pr + 3) * 38 + pc + 3) * 32 + chL] + bs[chL];
#pragma unroll
        for (int u = 0; u < 7; u++)
#pragma unroll
            for (int v = 0; v < 7; v++)
                acc += wc[(u * 7 + v) * 32 + chL] * sf[((pr + u) * 38 + pc + v) * 32 + chL];
        h2[(long long)(1 + rr * HSIZE + cc) * DIM + ch0 + chL] = acc;
    }
}

__global__ void copy_row0_k(float* __restrict__ h2, const float* __restrict__ hA)
{
    h2[threadIdx.x] = hA[threadIdx.x];
}

__global__ void final_k(const float* __restrict__ h, const float* __restrict__ g,
                        const float* __restrict__ b, const float* __restrict__ w,
                        const float* __restrict__ bias, float* __restrict__ out,
                        int out_size)
{
    int t = threadIdx.x;
    __shared__ float sm[512];
    float v = h[t];
    sm[t] = v; __syncthreads();
    for (int s = 256; s > 0; s >>= 1) { if (t < s) sm[t] += sm[t + s]; __syncthreads(); }
    float mu = sm[0] * (1.f / DIM); __syncthreads();
    float d = v - mu;
    sm[t] = d * d; __syncthreads();
    for (int s = 256; s > 0; s >>= 1) { if (t < s) sm[t] += sm[t + s]; __syncthreads(); }
    float rs = rsqrtf(sm[0] * (1.f / DIM) + EPSLN); __syncthreads();
    float e = d * rs * g[t] + b[t];
    if (5 + t < out_size) out[5 + t] = e;
    sm[t] = e * w[t * 2]; __syncthreads();
    for (int s = 256; s > 0; s >>= 1) { if (t < s) sm[t] += sm[t + s]; __syncthreads(); }
    float l0 = sm[0] + bias[0]; __syncthreads();
    sm[t] = e * w[t * 2 + 1]; __syncthreads();
    for (int s = 256; s > 0; s >>= 1) { if (t < s) sm[t] += sm[t + s]; __syncthreads(); }
    float l1 = sm[0] + bias[1]; __syncthreads();
    if (t == 0 && out_size >= 5) {
        out[0] = l0; out[1] = l1;
        float mx = fmaxf(l0, l1);
        float e0 = expf(l0 - mx), e1 = expf(l1 - mx);
        float s = e0 + e1;
        out[2] = e0 / s; out[3] = e1 / s;
        out[4] = (l1 > l0) ? 1.f : 0.f;
    }
}

// ---------------- host orchestration ---------------------------------------

constexpr int HSMEM_BIG = 3 * (128 * 72 + 128 * 72) * 2;   // 110592 B
constexpr int HSMEM_SML = 3 * (64 * 72 + 64 * 72) * 2;     // 55296 B
constexpr int PPEG_SMEM = (14 * 38 * 32 + 49 * 32 + 32) * 4;

static void launch_hbig(const __half* A, const __half* B, void* C, bool out16,
                        int M, int N, int K, int lda, int ldb, int ldc,
                        long long sA, long long sB, long long sC, int batch,
                        float alpha, const float* bias, const float* res, int ldres,
                        int zrows, int flags)
{
    dim3 grid(N / 128, (M + 127) / 128, batch);
    if (out16)
        gemm_hc<128, 128, 64, 2, 4, true, 256, 2><<<grid, 256, HSMEM_BIG>>>(
            A, B, C, M, K, lda, ldb, ldc, sA, sB, sC, alpha, bias, res, ldres, zrows, flags);
    else
        gemm_hc<128, 128, 64, 2, 4, false, 256, 2><<<grid, 256, HSMEM_BIG>>>(
            A, B, C, M, K, lda, ldb, ldc, sA, sB, sC, alpha, bias, res, ldres, zrows, flags);
}

static void run_attn_layer(float* base, __half* hb, float* hbuf,
                           const float* lng, const float* lnb,
                           const __half* wqkvT, const __half* woutT,
                           const float* outb, const float* convw)
{
    __half* xln16  = hb + HOFF_XLN;
    __half* qkv16  = hb + HOFF_QKV;
    __half* ql16   = hb + HOFF_QL;
    __half* kl16   = hb + HOFF_KL;
    __half* W216   = hb + HOFF_W2;
    __half* attn16 = hb + HOFF_ATTN;

    float* Opar = base + OFF_S1;
    float* mpar = base + OFF_S3;
    float* lpar = base + OFF_S3 + 32768;
    float* a2   = base + OFF_A2;
    float* Zb   = base + OFF_Z;
    float* a3v  = base + OFF_A3V;
    float* W2   = base + OFF_W2;

    const long long sA2 = (long long)MLM * MLM;
    const long long sLM = (long long)MLM * DH;

    ln_k<<<NTOK, 256>>>(hbuf, xln16, lng, lnb);

    // qkv = pad(xln) @ qkv_w   -> fp16
    launch_hbig(xln16, wqkvT, qkv16, true, NP, 1536, DIM, DIM, DIM, 1536,
                0, 0, 0, 1, 1.f, nullptr, nullptr, 0, PADR, 0);

    landmark_k<<<dim3(512, 2), 256>>>(qkv16, ql16, kl16);

    // flash split: partials of softmax(ql @ k^T) @ v over 11 KV slices
    flash_h<true><<<dim3(4, NSL, HEADS), 128>>>(
        ql16, DH, sLM,
        qkv16 + DIM, 1536, DH,
        qkv16 + 2 * DIM, 1536, DH,
        KPS / 64, KPS,
        nullptr, 0, 0,
        Opar, mpar, lpar, NSL, 4);
    fcomb_k<<<(HEADS * (int)sLM) / 256, 256>>>(Opar, mpar, lpar, a3v);

    // a2 = softmax((ql*scale) @ kl^T)  -> fp32
    {
        dim3 grid(MLM / 64, MLM / 64, HEADS);
        gemm_hc<64, 64, 64, 2, 2, false, 128, 4><<<grid, 128, HSMEM_SML>>>(
            ql16, kl16, a2, MLM, DH, DH, DH, MLM,
            sLM, sLM, sA2, SCALE_Q, nullptr, nullptr, 0, 0, 0);
    }
    softmax256_k<<<(HEADS * MLM) / 8, 256>>>(a2);

    // fused pinv (tf32, persistent)
    pinv_init_k<<<HEADS, 256>>>(a2, Zb);
    pinv_fused_k<<<128, 128>>>(base);
    cvt_k<<<(HEADS * (int)sLM) / 256, 256>>>(W216, W2, HEADS * (int)sLM);

    // attn = softmax(q @ kl^T) @ W2   -> fp16
    flash_h<false><<<dim3(NP / 64, 1, HEADS), 128>>>(
        qkv16, 1536, DH,
        kl16, DH, sLM,
        W216, DH, sLM,
        MLM / 64, MLM,
        attn16, DIM, DH,
        nullptr, nullptr, nullptr, 1, NP / 64);

    conv1d_t_k<<<dim3(NP / 128, HEADS), 256>>>(attn16, qkv16, convw);

    // h += attn[166:] @ out_w + out_b
    launch_hbig(attn16 + (long long)PADR * DIM, woutT, hbuf, false,
                NTOK, DIM, DIM, DIM, DIM, DIM,
                0, 0, 0, 1, 1.f, outb, hbuf, DIM, 0, 0);
}

extern "C" void kernel_launch(void* const* d_in, const int* in_sizes, int n_in,
                              void* d_out, int out_size)
{
    const float* x      = (const float*)d_in[0];
    const float* fc1_w  = (const float*)d_in[1];
    const float* fc1_b  = (const float*)d_in[2];
    const float* cls    = (const float*)d_in[3];
    const float* ln1_g  = (const float*)d_in[4];
    const float* ln1_b  = (const float*)d_in[5];
    const float* qkv1_w = (const float*)d_in[6];
    const float* out1_w = (const float*)d_in[7];
    const float* out1_b = (const float*)d_in[8];
    const float* conv1w = (const float*)d_in[9];
    const float* ln2_g  = (const float*)d_in[10];
    const float* ln2_b  = (const float*)d_in[11];
    const float* qkv2_w = (const float*)d_in[12];
    const float* out2_w = (const float*)d_in[13];
    const float* out2_b = (const float*)d_in[14];
    const float* conv2w = (const float*)d_in[15];
    const float* pg7_w  = (const float*)d_in[16];
    const float* pg7_b  = (const float*)d_in[17];
    const float* pg5_w  = (const float*)d_in[18];
    const float* pg5_b  = (const float*)d_in[19];
    const float* pg3_w  = (const float*)d_in[20];
    const float* pg3_b  = (const float*)d_in[21];
    const float* norm_g = (const float*)d_in[22];
    const float* norm_b = (const float*)d_in[23];
    const float* fc2_w  = (const float*)d_in[24];
    const float* fc2_b  = (const float*)d_in[25];

    cudaFuncSetAttribute((const void*)gemm_hc<128, 128, 64, 2, 4, true, 256, 2>,
                         cudaFuncAttributeMaxDynamicSharedMemorySize, HSMEM_BIG);
    cudaFuncSetAttribute((const void*)gemm_hc<128, 128, 64, 2, 4, false, 256, 2>,
                         cudaFuncAttributeMaxDynamicSharedMemorySize, HSMEM_BIG);
    cudaFuncSetAttribute((const void*)gemm_hc<64, 64, 64, 2, 2, false, 128, 4>,
                         cudaFuncAttributeMaxDynamicSharedMemorySize, HSMEM_SML);
    cudaFuncSetAttribute(ppeg_t_k, cudaFuncAttributeMaxDynamicSharedMemorySize, PPEG_SMEM);

    float* base = nullptr;
    cudaGetSymbolAddress((void**)&base, g_scratch);
    __half* hb = nullptr;
    cudaGetSymbolAddress((void**)&hb, g_hscr);

    float* hA = base + OFF_HA;
    float* h2 = base + OFF_H2;

    // convert input + weights to fp16 (weights transposed to [N][K])
    cvt_k<<<8388608 / 256, 256>>>(hb + HOFF_X, x, 8388608);
    cvtT_k<<<(524288 + 255) / 256, 256>>>(hb + HOFF_WF, fc1_w, 1024, 512);
    cvtT_k<<<(786432 + 255) / 256, 256>>>(hb + HOFF_WQ1, qkv1_w, 512, 1536);
    cvtT_k<<<(786432 + 255) / 256, 256>>>(hb + HOFF_WQ2, qkv2_w, 512, 1536);
    cvtT_k<<<(262144 + 255) / 256, 256>>>(hb + HOFF_WO1, out1_w, 512, 512);
    cvtT_k<<<(262144 + 255) / 256, 256>>>(hb + HOFF_WO2, out2_w, 512, 512);

    // fc1 + relu into rows 1..8192 of hA (fp32 residual stream)
    launch_hbig(hb + HOFF_X, hb + HOFF_WF, hA + DIM, false,
                8192, DIM, 1024, 1024, 1024, DIM,
                0, 0, 0, 1, 1.f, fc1_b, nullptr, 0, 0, F_RELU);
    seed_k<<<(90 * DIM) / 256, 256>>>(hA, cls);

    run_attn_layer(base, hb, hA, ln1_g, ln1_b, hb + HOFF_WQ1, hb + HOFF_WO1,
                   out1_b, conv1w);

    ppeg_t_k<<<dim3(3, 12, 16), 256, PPEG_SMEM>>>(hA, h2, pg7_w, pg7_b, pg5_w, pg5_b, pg3_w, pg3_b);
    copy_row0_k<<<1, DIM>>>(h2, hA);

    run_attn_layer(base, hb, h2, ln2_g, ln2_b, hb + HOFF_WQ2, hb + HOFF_WO2,
                   out2_b, conv2w);

    final_k<<<1, DIM>>>(h2, norm_g, norm_b, fc2_w, fc2_b, (float*)d_out, out_size);
}

// round 8
// speedup vs baseline: 9.0891x; 1.0462x over previous
#include <cuda_runtime.h>
#include <cuda_fp16.h>
#include <cstdint>

// ----------------------------------------------------------------------------
// TransMIL forward pass. fp16 tensor-core GEMMs + fp16 flash attention +
// tf32 persistent pinv, with fork-join stream overlap of independent branches.
// ----------------------------------------------------------------------------

#define NP      8448
#define NTOK    8282
#define NPIX    8281
#define HSIZE   91
#define PADR    166
#define DIM     512
#define HEADS   8
#define DH      64
#define MLM     256
#define SCALE_Q 0.125f
#define EPSLN   1e-5f
#define NSL     11
#define KPS     768

#define F_RELU  1

// ---------------- fp32 scratch ---------------------------------------------
constexpr long long SZ_H    = (long long)NTOK * DIM;
constexpr long long SZ_S    = (long long)HEADS * NP * MLM;
constexpr long long SZ_A2   = (long long)MLM * MLM * HEADS;
constexpr long long SZ_LM   = (long long)HEADS * MLM * DH;

constexpr long long OFF_HA   = 0;
constexpr long long OFF_H2   = OFF_HA  + SZ_H;
constexpr long long OFF_S1   = OFF_H2  + SZ_H;     // flash O partials
constexpr long long OFF_S3   = OFF_S1  + SZ_S;     // flash m/l partials
constexpr long long OFF_A2   = OFF_S3  + SZ_S;
constexpr long long OFF_Z    = OFF_A2  + SZ_A2;
constexpr long long OFF_XZ   = OFF_Z   + SZ_A2;
constexpr long long OFF_T    = OFF_XZ  + SZ_A2;
constexpr long long OFF_T4   = OFF_T   + SZ_A2;
constexpr long long OFF_P    = OFF_T4  + SZ_A2;
constexpr long long OFF_A3V  = OFF_P   + SZ_A2;
constexpr long long OFF_W2   = OFF_A3V + SZ_LM;
constexpr long long SCRATCH_TOTAL = OFF_W2 + SZ_LM;

__device__ float g_scratch[SCRATCH_TOTAL];
__device__ unsigned g_bar_cnt;

// ---------------- fp16 scratch ---------------------------------------------
constexpr long long HOFF_X    = 0;
constexpr long long HOFF_WF   = HOFF_X    + 8388608;
constexpr long long HOFF_WQ1  = HOFF_WF   + 524288;
constexpr long long HOFF_WQ2  = HOFF_WQ1  + 786432;
constexpr long long HOFF_WO1  = HOFF_WQ2  + 786432;
constexpr long long HOFF_WO2  = HOFF_WO1  + 262144;
constexpr long long HOFF_XLN  = HOFF_WO2  + 262144;
constexpr long long HOFF_QKV  = HOFF_XLN  + SZ_H;
constexpr long long HOFF_QL   = HOFF_QKV  + (long long)NP * 1536;
constexpr long long HOFF_KL   = HOFF_QL   + SZ_LM;
constexpr long long HOFF_W2   = HOFF_KL   + SZ_LM;
constexpr long long HOFF_ATTN = HOFF_W2   + SZ_LM;
constexpr long long HSCR_TOTAL = HOFF_ATTN + (long long)NP * DIM;

__device__ __half g_hscr[HSCR_TOTAL];

// ---------------- mma helpers ----------------------------------------------

__device__ __forceinline__ void cpa16(uint32_t dst, const void* src, int validBytes)
{
    asm volatile("cp.async.cg.shared.global [%0], [%1], 16, %2;\n"
                 :: "r"(dst), "l"(src), "r"(validBytes));
}

__device__ __forceinline__ void mma_tf32(float* d, const uint32_t* a, const uint32_t* b)
{
    asm volatile(
        "mma.sync.aligned.m16n8k8.row.col.f32.tf32.tf32.f32 "
        "{%0,%1,%2,%3}, {%4,%5,%6,%7}, {%8,%9}, {%0,%1,%2,%3};"
        : "+f"(d[0]), "+f"(d[1]), "+f"(d[2]), "+f"(d[3])
        : "r"(a[0]), "r"(a[1]), "r"(a[2]), "r"(a[3]), "r"(b[0]), "r"(b[1]));
}

__device__ __forceinline__ void mma_f16(float* d, const uint32_t* a, const uint32_t* b)
{
    asm volatile(
        "mma.sync.aligned.m16n8k16.row.col.f32.f16.f16.f32 "
        "{%0,%1,%2,%3}, {%4,%5,%6,%7}, {%8,%9}, {%0,%1,%2,%3};"
        : "+f"(d[0]), "+f"(d[1]), "+f"(d[2]), "+f"(d[3])
        : "r"(a[0]), "r"(a[1]), "r"(a[2]), "r"(a[3]), "r"(b[0]), "r"(b[1]));
}

// ---------------- fp16 tensor-core GEMM, 3-stage pipeline -------------------
template<int BM, int BN, int BK, int WM, int WN, bool OUT16, int THREADS, int MAXB>
__global__ void __launch_bounds__(THREADS, MAXB)
gemm_hc(const __half* __restrict__ A, const __half* __restrict__ B,
        void* __restrict__ Cv,
        int Mr, int K, int lda, int ldb, int ldc,
        long long sA, long long sB, long long sC,
        float alpha,
        const float* __restrict__ bias,
        const float* __restrict__ res, int ldres,
        int zrows, int flags)
{
    constexpr int MT = BM / (WM * 16);
    constexpr int NT = BN / (WN * 8);
    constexpr int SK  = BK + 8;
    constexpr int ASZ = BM * SK;
    constexpr int BSZ = BN * SK;
    constexpr int CA = BM * BK / (8 * THREADS);
    constexpr int CB = BN * BK / (8 * THREADS);
    static_assert(CA >= 1 && CB >= 1, "chunks");
    static_assert(WM * WN == THREADS / 32, "warps");

    extern __shared__ __half hsm[];
    __half* sAr = hsm;
    __half* sBr = hsm + 3 * ASZ;

    const int bz = blockIdx.z;
    A += bz * sA; B += bz * sB;
    __half* C16 = OUT16 ? ((__half*)Cv + bz * sC) : nullptr;
    float*  C32 = OUT16 ? nullptr : ((float*)Cv + bz * sC);

    const int tid = threadIdx.x;
    const int lane = tid & 31;
    const int w = tid >> 5;
    const int wm = w / WN, wn = w % WN;
    const int m0 = wm * MT * 16;
    const int n0 = wn * NT * 8;
    const int g = lane >> 2, c = lane & 3;
    const int rowBase = blockIdx.y * BM;
    const int colBase = blockIdx.x * BN;

    const uint32_t saA = (uint32_t)__cvta_generic_to_shared(sAr);
    const uint32_t saB = (uint32_t)__cvta_generic_to_shared(sBr);

    auto loadTiles = [&](int st, int k0) {
#pragma unroll
        for (int v = 0; v < CA; v++) {
            int idx = tid + v * THREADS;
            int m = idx / (BK / 8), kq = idx % (BK / 8);
            int gm = rowBase + m, am = gm - zrows;
            bool ok = (gm < Mr) && (am >= 0);
            const __half* src = A + (ok ? (long long)am * lda : 0) + k0 + kq * 8;
            cpa16(saA + (uint32_t)(st * ASZ + m * SK + kq * 8) * 2, src, ok ? 16 : 0);
        }
#pragma unroll
        for (int v = 0; v < CB; v++) {
            int idx = tid + v * THREADS;
            int n = idx / (BK / 8), kq = idx % (BK / 8);
            const __half* src = B + (long long)(colBase + n) * ldb + k0 + kq * 8;
            cpa16(saB + (uint32_t)(st * BSZ + n * SK + kq * 8) * 2, src, 16);
        }
    };

    float acc[MT][NT][4];
#pragma unroll
    for (int i = 0; i < MT; i++)
#pragma unroll
        for (int j = 0; j < NT; j++)
#pragma unroll
            for (int e = 0; e < 4; e++) acc[i][j][e] = 0.f;

    const int nk = K / BK;
    loadTiles(0, 0);
    asm volatile("cp.async.commit_group;");
    if (nk > 1) loadTiles(1, BK);
    asm volatile("cp.async.commit_group;");

    for (int t = 0; t < nk; t++) {
        if (t + 1 < nk) { asm volatile("cp.async.wait_group 1;"); }
        else            { asm volatile("cp.async.wait_group 0;"); }
        __syncthreads();
        if (t + 2 < nk) {
            loadTiles((t + 2) % 3, (t + 2) * BK);
            asm volatile("cp.async.commit_group;");
        }

        const int st = t % 3;
        const __half* pA = sAr + st * ASZ;
        const __half* pB = sBr + st * BSZ;
#pragma unroll
        for (int kk = 0; kk < BK; kk += 16) {
            uint32_t af[MT][4], bf[NT][2];
#pragma unroll
            for (int mt = 0; mt < MT; mt++) {
                int r = m0 + mt * 16 + g;
                af[mt][0] = *(const uint32_t*)&pA[r * SK + kk + 2 * c];
                af[mt][1] = *(const uint32_t*)&pA[(r + 8) * SK + kk + 2 * c];
                af[mt][2] = *(const uint32_t*)&pA[r * SK + kk + 8 + 2 * c];
                af[mt][3] = *(const uint32_t*)&pA[(r + 8) * SK + kk + 8 + 2 * c];
            }
#pragma unroll
            for (int nt = 0; nt < NT; nt++) {
                int col = n0 + nt * 8 + g;
                bf[nt][0] = *(const uint32_t*)&pB[col * SK + kk + 2 * c];
                bf[nt][1] = *(const uint32_t*)&pB[col * SK + kk + 8 + 2 * c];
            }
#pragma unroll
            for (int mt = 0; mt < MT; mt++)
#pragma unroll
                for (int nt = 0; nt < NT; nt++)
                    mma_f16(acc[mt][nt], af[mt], bf[nt]);
        }
    }

#pragma unroll
    for (int mt = 0; mt < MT; mt++) {
#pragma unroll
        for (int nt = 0; nt < NT; nt++) {
            int gn = colBase + n0 + nt * 8 + 2 * c;
#pragma unroll
            for (int half = 0; half < 2; half++) {
                int gm = rowBase + m0 + mt * 16 + g + half * 8;
                if (gm >= Mr) continue;
#pragma unroll
                for (int e = 0; e < 2; e++) {
                    float v = alpha * acc[mt][nt][half * 2 + e];
                    int gnn = gn + e;
                    if (OUT16) {
                        C16[(long long)gm * ldc + gnn] = __float2half(v);
                    } else {
                        if (bias) v += bias[gnn];
                        if (res)  v += res[(long long)gm * ldres + gnn];
                        if (flags & F_RELU) v = fmaxf(v, 0.f);
                        C32[(long long)gm * ldc + gnn] = v;
                    }
                }
            }
        }
    }
}

// ---------------- persistent fused pinv kernel (tf32, phases 0-23) ----------
__device__ __forceinline__ void grid_bar(int gen)
{
    __syncthreads();
    if (threadIdx.x == 0) {
        __threadfence();
        atomicAdd(&g_bar_cnt, 1u);
        unsigned target = (unsigned)(gen + 1) * 128u;
        while (*(volatile unsigned*)&g_bar_cnt < target) __nanosleep(32);
        __threadfence();
    }
    __syncthreads();
}

__global__ void __launch_bounds__(128, 1)
pinv_fused_k(float* __restrict__ base)
{
    __shared__ float sA2[2][64 * 36];
    __shared__ float sB2[2][32 * 72];

    const int bid = blockIdx.x;
    const int h = bid >> 4;
    const int t = bid & 15;
    const int rowBase = (t >> 2) * 64;
    const int colBase = (t & 3) * 64;

    const long long hA2 = (long long)h * (MLM * MLM);
    float* a2  = base + OFF_A2  + hA2;
    float* Zb  = base + OFF_Z   + hA2;
    float* XZ  = base + OFF_XZ  + hA2;
    float* Tb  = base + OFF_T   + hA2;
    float* T4  = base + OFF_T4  + hA2;
    float* Pb  = base + OFF_P   + hA2;

    const int tid = threadIdx.x;
    const int lane = tid & 31;
    const int w = tid >> 5;
    const int wm = w >> 1, wn = w & 1;
    const int m0 = wm * 32;
    const int n0 = wn * 32;
    const int g = lane >> 2, c = lane & 3;

    const uint32_t saA = (uint32_t)__cvta_generic_to_shared(&sA2[0][0]);
    const uint32_t saB = (uint32_t)__cvta_generic_to_shared(&sB2[0][0]);

    for (int ph = 0; ph < 24; ph++) {
        const float *Ao, *Bo;
        float* Co;
        float alpha = 1.f, dcoef = 0.f;
        bool diag = false;

        int it = ph >> 2, sub = ph & 3;
        float* Zc = (it & 1) ? Pb : Zb;
        float* Pc = (it & 1) ? Zb : Pb;
        switch (sub) {
            case 0: Ao = a2; Bo = Zc; Co = XZ; break;
            case 1: Ao = XZ; Bo = XZ; Co = Tb; diag = true; dcoef = 7.f; break;
            case 2: Ao = XZ; Bo = Tb; Co = T4; diag = true; dcoef = 15.f; break;
            default: Ao = Zc; Bo = T4; Co = Pc; diag = true; dcoef = 13.f; alpha = 0.25f; break;
        }

        auto loadT = [&](int st, int k0) {
#pragma unroll
            for (int v = 0; v < 4; v++) {
                int idx = tid + v * 128;
                int m = idx >> 3, kq = idx & 7;
                cpa16(saA + (uint32_t)(st * 2304 + m * 36 + kq * 4) * 4,
                      Ao + (long long)(rowBase + m) * 256 + k0 + kq * 4, 16);
            }
#pragma unroll
            for (int v = 0; v < 4; v++) {
                int idx = tid + v * 128;
                int kk = idx >> 4, nq = idx & 15;
                cpa16(saB + (uint32_t)(st * 2304 + kk * 72 + nq * 4) * 4,
                      Bo + (long long)(k0 + kk) * 256 + colBase + nq * 4, 16);
            }
        };

        float acc[2][4][4];
#pragma unroll
        for (int i = 0; i < 2; i++)
#pragma unroll
            for (int j = 0; j < 4; j++)
#pragma unroll
                for (int e = 0; e < 4; e++) acc[i][j][e] = 0.f;

        loadT(0, 0);
        asm volatile("cp.async.commit_group;");

        for (int kt = 0; kt < 8; kt++) {
            if (kt + 1 < 8) {
                loadT((kt + 1) & 1, (kt + 1) * 32);
                asm volatile("cp.async.commit_group;");
                asm volatile("cp.async.wait_group 1;");
            } else {
                asm volatile("cp.async.wait_group 0;");
            }
            __syncthreads();

            const float* pA = &sA2[kt & 1][0];
            const float* pB = &sB2[kt & 1][0];
#pragma unroll
            for (int kk = 0; kk < 32; kk += 8) {
                uint32_t af[2][4], bf[4][2];
#pragma unroll
                for (int mt = 0; mt < 2; mt++) {
                    int r = m0 + mt * 16 + g;
                    af[mt][0] = __float_as_uint(pA[r * 36 + kk + c]);
                    af[mt][1] = __float_as_uint(pA[(r + 8) * 36 + kk + c]);
                    af[mt][2] = __float_as_uint(pA[r * 36 + kk + 4 + c]);
                    af[mt][3] = __float_as_uint(pA[(r + 8) * 36 + kk + 4 + c]);
                }
#pragma unroll
                for (int nt = 0; nt < 4; nt++) {
                    int col = n0 + nt * 8 + g;
                    bf[nt][0] = __float_as_uint(pB[(kk + c) * 72 + col]);
                    bf[nt][1] = __float_as_uint(pB[(kk + 4 + c) * 72 + col]);
                }
#pragma unroll
                for (int mt = 0; mt < 2; mt++)
#pragma unroll
                    for (int nt = 0; nt < 4; nt++)
                        mma_tf32(acc[mt][nt], af[mt], bf[nt]);
            }
            __syncthreads();
        }

#pragma unroll
        for (int mt = 0; mt < 2; mt++) {
#pragma unroll
            for (int nt = 0; nt < 4; nt++) {
                int gn = colBase + n0 + nt * 8 + 2 * c;
#pragma unroll
                for (int half = 0; half < 2; half++) {
                    int gm = rowBase + m0 + mt * 16 + g + half * 8;
#pragma unroll
                    for (int e = 0; e < 2; e++) {
                        float v = acc[mt][nt][half * 2 + e];
                        int gnn = gn + e;
                        if (diag)
                            v = alpha * (dcoef * Ao[(long long)gm * 256 + gnn] - v);
                        else
                            v = alpha * v;
                        Co[(long long)gm * 256 + gnn] = v;
                    }
                }
            }
        }
        if (ph < 23) grid_bar(ph);
    }
}

// W2 = Z @ a3v (tf32). grid 32 = 8 heads x 4 row tiles of 64. K=256, N=64.
__global__ void __launch_bounds__(128)
w2_k(float* __restrict__ base)
{
    __shared__ float sA2[2][64 * 36];
    __shared__ float sB2[2][32 * 72];

    const int bid = blockIdx.x;
    const int h = bid >> 2;
    const int rowBase = (bid & 3) * 64;

    const float* Ao = base + OFF_Z + (long long)h * (MLM * MLM);
    const float* Bo = base + OFF_A3V + (long long)h * (MLM * DH);
    float* Co = base + OFF_W2 + (long long)h * (MLM * DH);

    const int tid = threadIdx.x;
    const int lane = tid & 31;
    const int w = tid >> 5;
    const int wm = w >> 1, wn = w & 1;
    const int m0 = wm * 32;
    const int n0 = wn * 32;
    const int g = lane >> 2, c = lane & 3;

    const uint32_t saA = (uint32_t)__cvta_generic_to_shared(&sA2[0][0]);
    const uint32_t saB = (uint32_t)__cvta_generic_to_shared(&sB2[0][0]);

    auto loadT = [&](int st, int k0) {
#pragma unroll
        for (int v = 0; v < 4; v++) {
            int idx = tid + v * 128;
            int m = idx >> 3, kq = idx & 7;
            cpa16(saA + (uint32_t)(st * 2304 + m * 36 + kq * 4) * 4,
                  Ao + (long long)(rowBase + m) * 256 + k0 + kq * 4, 16);
        }
#pragma unroll
        for (int v = 0; v < 4; v++) {
            int idx = tid + v * 128;
            int kk = idx >> 4, nq = idx & 15;
            cpa16(saB + (uint32_t)(st * 2304 + kk * 72 + nq * 4) * 4,
                  Bo + (long long)(k0 + kk) * 64 + nq * 4, 16);
        }
    };

    float acc[2][4][4];
#pragma unroll
    for (int i = 0; i < 2; i++)
#pragma unroll
        for (int j = 0; j < 4; j++)
#pragma unroll
            for (int e = 0; e < 4; e++) acc[i][j][e] = 0.f;

    loadT(0, 0);
    asm volatile("cp.async.commit_group;");

    for (int kt = 0; kt < 8; kt++) {
        if (kt + 1 < 8) {
            loadT((kt + 1) & 1, (kt + 1) * 32);
            asm volatile("cp.async.commit_group;");
            asm volatile("cp.async.wait_group 1;");
        } else {
            asm volatile("cp.async.wait_group 0;");
        }
        __syncthreads();

        const float* pA = &sA2[kt & 1][0];
        const float* pB = &sB2[kt & 1][0];
#pragma unroll
        for (int kk = 0; kk < 32; kk += 8) {
            uint32_t af[2][4], bf[4][2];
#pragma unroll
            for (int mt = 0; mt < 2; mt++) {
                int r = m0 + mt * 16 + g;
                af[mt][0] = __float_as_uint(pA[r * 36 + kk + c]);
                af[mt][1] = __float_as_uint(pA[(r + 8) * 36 + kk + c]);
                af[mt][2] = __float_as_uint(pA[r * 36 + kk + 4 + c]);
                af[mt][3] = __float_as_uint(pA[(r + 8) * 36 + kk + 4 + c]);
            }
#pragma unroll
            for (int nt = 0; nt < 4; nt++) {
                int col = n0 + nt * 8 + g;
                bf[nt][0] = __float_as_uint(pB[(kk + c) * 72 + col]);
                bf[nt][1] = __float_as_uint(pB[(kk + 4 + c) * 72 + col]);
            }
#pragma unroll
            for (int mt = 0; mt < 2; mt++)
#pragma unroll
                for (int nt = 0; nt < 4; nt++)
                    mma_tf32(acc[mt][nt], af[mt], bf[nt]);
        }
        __syncthreads();
    }

#pragma unroll
    for (int mt = 0; mt < 2; mt++) {
#pragma unroll
        for (int nt = 0; nt < 4; nt++) {
            int gn = n0 + nt * 8 + 2 * c;
#pragma unroll
            for (int half = 0; half < 2; half++) {
                int gm = rowBase + m0 + mt * 16 + g + half * 8;
#pragma unroll
                for (int e = 0; e < 2; e++)
                    Co[(long long)gm * 64 + gn + e] = acc[mt][nt][half * 2 + e];
            }
        }
    }
}

// ---------------- fp16 flash attention kernel -------------------------------
template<bool SPLIT>
__global__ void __launch_bounds__(128, 4)
flash_h(const __half* __restrict__ Qb, int ldq, long long sQh,
        const __half* __restrict__ Kb, int ldk, long long sKh,
        const __half* __restrict__ Vb, int ldv, long long sVh,
        int nchunks, int keys_per_slice,
        __half* __restrict__ out, int ldo, long long sOh,
        float* __restrict__ Op, float* __restrict__ mp, float* __restrict__ lp,
        int nslices, int nqt, int accum)
{
    __shared__ __half sQ[64 * 72];
    __shared__ __half sK[64 * 72];
    __shared__ __half sVt[64 * 72];
    __shared__ __half sP[64 * 72];

    const int h = blockIdx.z, qt = blockIdx.x;
    const int sl = SPLIT ? blockIdx.y : 0;
    const __half* Q = Qb + h * sQh + (long long)qt * 64 * ldq;
    const __half* K = Kb + h * sKh + (long long)sl * keys_per_slice * ldk;
    const __half* V = Vb + h * sVh + (long long)sl * keys_per_slice * ldv;

    const int tid = threadIdx.x, lane = tid & 31, w = tid >> 5;
    const int g = lane >> 2, c = lane & 3;
    const int wr = w * 16;

    for (int i = tid; i < 64 * 8; i += 128) {
        int r = i >> 3, q8 = (i & 7) * 8;
        *reinterpret_cast<float4*>(&sQ[r * 72 + q8]) =
            *reinterpret_cast<const float4*>(Q + (long long)r * ldq + q8);
    }

    float m0 = -1e30f, m1 = -1e30f, l0 = 0.f, l1 = 0.f;
    float Oacc[8][4];
#pragma unroll
    for (int nt = 0; nt < 8; nt++)
#pragma unroll
        for (int e = 0; e < 4; e++) Oacc[nt][e] = 0.f;

    for (int ch = 0; ch < nchunks; ch++) {
        __syncthreads();
        const __half* Kc = K + (long long)ch * 64 * ldk;
        const __half* Vc = V + (long long)ch * 64 * ldv;
        for (int i = tid; i < 64 * 8; i += 128) {
            int r = i >> 3, q8 = (i & 7) * 8;
            *reinterpret_cast<float4*>(&sK[r * 72 + q8]) =
                *reinterpret_cast<const float4*>(Kc + (long long)r * ldk + q8);
            float4 v4 = *reinterpret_cast<const float4*>(Vc + (long long)r * ldv + q8);
            const __half* vh = reinterpret_cast<const __half*>(&v4);
#pragma unroll
            for (int j = 0; j < 8; j++)
                sVt[(q8 + j) * 72 + r] = vh[j];
        }
        __syncthreads();

        float lacc[8][4];
#pragma unroll
        for (int nt = 0; nt < 8; nt++)
#pragma unroll
            for (int e = 0; e < 4; e++) lacc[nt][e] = 0.f;
#pragma unroll
        for (int kk = 0; kk < 64; kk += 16) {
            uint32_t a[4];
            a[0] = *(const uint32_t*)&sQ[(wr + g) * 72 + kk + 2 * c];
            a[1] = *(const uint32_t*)&sQ[(wr + g + 8) * 72 + kk + 2 * c];
            a[2] = *(const uint32_t*)&sQ[(wr + g) * 72 + kk + 8 + 2 * c];
            a[3] = *(const uint32_t*)&sQ[(wr + g + 8) * 72 + kk + 8 + 2 * c];
#pragma unroll
            for (int nt = 0; nt < 8; nt++) {
                uint32_t b[2];
                b[0] = *(const uint32_t*)&sK[(nt * 8 + g) * 72 + kk + 2 * c];
                b[1] = *(const uint32_t*)&sK[(nt * 8 + g) * 72 + kk + 8 + 2 * c];
                mma_f16(lacc[nt], a, b);
            }
        }

        float cm0 = -1e30f, cm1 = -1e30f;
#pragma unroll
        for (int nt = 0; nt < 8; nt++) {
            lacc[nt][0] *= SCALE_Q; lacc[nt][1] *= SCALE_Q;
            lacc[nt][2] *= SCALE_Q; lacc[nt][3] *= SCALE_Q;
            cm0 = fmaxf(cm0, fmaxf(lacc[nt][0], lacc[nt][1]));
            cm1 = fmaxf(cm1, fmaxf(lacc[nt][2], lacc[nt][3]));
        }
        cm0 = fmaxf(cm0, __shfl_xor_sync(0xffffffffu, cm0, 1));
        cm0 = fmaxf(cm0, __shfl_xor_sync(0xffffffffu, cm0, 2));
        cm1 = fmaxf(cm1, __shfl_xor_sync(0xffffffffu, cm1, 1));
        cm1 = fmaxf(cm1, __shfl_xor_sync(0xffffffffu, cm1, 2));
        float nm0 = fmaxf(m0, cm0), nm1 = fmaxf(m1, cm1);
        float f0 = __expf(m0 - nm0), f1 = __expf(m1 - nm1);
        float rs0 = 0.f, rs1 = 0.f;
#pragma unroll
        for (int nt = 0; nt < 8; nt++) {
            float p0 = __expf(lacc[nt][0] - nm0);
            float p1 = __expf(lacc[nt][1] - nm0);
            float p2 = __expf(lacc[nt][2] - nm1);
            float p3 = __expf(lacc[nt][3] - nm1);
            rs0 += p0 + p1; rs1 += p2 + p3;
            *reinterpret_cast<__half2*>(&sP[(wr + g) * 72 + nt * 8 + 2 * c]) =
                __floats2half2_rn(p0, p1);
            *reinterpret_cast<__half2*>(&sP[(wr + g + 8) * 72 + nt * 8 + 2 * c]) =
                __floats2half2_rn(p2, p3);
        }
        rs0 += __shfl_xor_sync(0xffffffffu, rs0, 1);
        rs0 += __shfl_xor_sync(0xffffffffu, rs0, 2);
        rs1 += __shfl_xor_sync(0xffffffffu, rs1, 1);
        rs1 += __shfl_xor_sync(0xffffffffu, rs1, 2);
        l0 = l0 * f0 + rs0; l1 = l1 * f1 + rs1;
        m0 = nm0; m1 = nm1;
#pragma unroll
        for (int nt = 0; nt < 8; nt++) {
            Oacc[nt][0] *= f0; Oacc[nt][1] *= f0;
            Oacc[nt][2] *= f1; Oacc[nt][3] *= f1;
        }
        __syncwarp();

#pragma unroll
        for (int kk = 0; kk < 64; kk += 16) {
            uint32_t a[4];
            a[0] = *(const uint32_t*)&sP[(wr + g) * 72 + kk + 2 * c];
            a[1] = *(const uint32_t*)&sP[(wr + g + 8) * 72 + kk + 2 * c];
            a[2] = *(const uint32_t*)&sP[(wr + g) * 72 + kk + 8 + 2 * c];
            a[3] = *(const uint32_t*)&sP[(wr + g + 8) * 72 + kk + 8 + 2 * c];
#pragma unroll
            for (int nt = 0; nt < 8; nt++) {
                uint32_t b[2];
                b[0] = *(const uint32_t*)&sVt[(nt * 8 + g) * 72 + kk + 2 * c];
                b[1] = *(const uint32_t*)&sVt[(nt * 8 + g) * 72 + kk + 8 + 2 * c];
                mma_f16(Oacc[nt], a, b);
            }
        }
    }

    if (SPLIT) {
        long long pb = ((long long)(h * nqt + qt) * nslices + sl) * 64;
#pragma unroll
        for (int nt = 0; nt < 8; nt++) {
            Op[(pb + wr + g) * 64 + nt * 8 + 2 * c]     = Oacc[nt][0];
            Op[(pb + wr + g) * 64 + nt * 8 + 2 * c + 1] = Oacc[nt][1];
            Op[(pb + wr + g + 8) * 64 + nt * 8 + 2 * c]     = Oacc[nt][2];
            Op[(pb + wr + g + 8) * 64 + nt * 8 + 2 * c + 1] = Oacc[nt][3];
        }
        if (c == 0) {
            mp[pb + wr + g] = m0; lp[pb + wr + g] = l0;
            mp[pb + wr + g + 8] = m1; lp[pb + wr + g + 8] = l1;
        }
    } else {
        float inv0 = 1.f / l0, inv1 = 1.f / l1;
        __half* o0 = out + h * sOh + (long long)(qt * 64 + wr + g) * ldo;
        __half* o1 = out + h * sOh + (long long)(qt * 64 + wr + g + 8) * ldo;
#pragma unroll
        for (int nt = 0; nt < 8; nt++) {
#pragma unroll
            for (int e = 0; e < 2; e++) {
                int idx = nt * 8 + 2 * c + e;
                float v0 = Oacc[nt][e] * inv0;
                float v1 = Oacc[nt][2 + e] * inv1;
                if (accum) {
                    v0 += __half2float(o0[idx]);
                    v1 += __half2float(o1[idx]);
                }
                o0[idx] = __float2half(v0);
                o1[idx] = __float2half(v1);
            }
        }
    }
}

__global__ void fcomb_k(const float* __restrict__ Op, const float* __restrict__ mp,
                        const float* __restrict__ lp, float* __restrict__ a3v)
{
    int idx = blockIdx.x * 256 + threadIdx.x;
    int col = idx & 63, r = (idx >> 6) & 255, h = idx >> 14;
    int qt = r >> 6, rr = r & 63;
    long long hq = (long long)(h * 4 + qt) * NSL;
    float mx = -1e30f;
#pragma unroll
    for (int s = 0; s < NSL; s++) mx = fmaxf(mx, mp[(hq + s) * 64 + rr]);
    float num = 0.f, den = 0.f;
#pragma unroll
    for (int s = 0; s < NSL; s++) {
        float wgt = __expf(mp[(hq + s) * 64 + rr] - mx);
        den += wgt * lp[(hq + s) * 64 + rr];
        num += wgt * Op[((hq + s) * 64 + rr) * 64 + col];
    }
    a3v[idx] = num / den;
}

// ---------------- conversion + small kernels --------------------------------

__global__ void cvt_k(__half* __restrict__ dst, const float* __restrict__ src, int n)
{
    int idx = blockIdx.x * 256 + threadIdx.x;
    if (idx < n) dst[idx] = __float2half(src[idx]);
}

__global__ void cvtT_k(__half* __restrict__ dst, const float* __restrict__ src,
                       int K, int N)
{
    int idx = blockIdx.x * 256 + threadIdx.x;
    if (idx >= N * K) return;
    int n = idx / K, k = idx % K;
    dst[idx] = __float2half(src[(long long)k * N + n]);
}

__global__ void softmax256_k(float* __restrict__ S)
{
    long long row = (long long)blockIdx.x * 8 + (threadIdx.x >> 5);
    int lane = threadIdx.x & 31;
    float* p = S + row * 256 + lane * 8;
    float4 a = *reinterpret_cast<float4*>(p);
    float4 b = *reinterpret_cast<float4*>(p + 4);
    float m = fmaxf(fmaxf(fmaxf(a.x, a.y), fmaxf(a.z, a.w)),
                    fmaxf(fmaxf(b.x, b.y), fmaxf(b.z, b.w)));
#pragma unroll
    for (int o = 16; o; o >>= 1) m = fmaxf(m, __shfl_xor_sync(0xffffffffu, m, o));
    a.x = __expf(a.x - m); a.y = __expf(a.y - m); a.z = __expf(a.z - m); a.w = __expf(a.w - m);
    b.x = __expf(b.x - m); b.y = __expf(b.y - m); b.z = __expf(b.z - m); b.w = __expf(b.w - m);
    float s = a.x + a.y + a.z + a.w + b.x + b.y + b.z + b.w;
#pragma unroll
    for (int o = 16; o; o >>= 1) s += __shfl_xor_sync(0xffffffffu, s, o);
    float inv = 1.f / s;
    a.x *= inv; a.y *= inv; a.z *= inv; a.w *= inv;
    b.x *= inv; b.y *= inv; b.z *= inv; b.w *= inv;
    *reinterpret_cast<float4*>(p) = a;
    *reinterpret_cast<float4*>(p + 4) = b;
}

__global__ void ln_k(const float* __restrict__ x, __half* __restrict__ y,
                     const float* __restrict__ g, const float* __restrict__ b)
{
    long long row = blockIdx.x;
    const float* xr = x + row * DIM;
    __half* yr = y + row * DIM;
    int t = threadIdx.x;
    float v0 = xr[t], v1 = xr[t + 256];
    __shared__ float sm[256];
    sm[t] = v0 + v1; __syncthreads();
    for (int s = 128; s > 0; s >>= 1) { if (t < s) sm[t] += sm[t + s]; __syncthreads(); }
    float mu = sm[0] * (1.f / DIM); __syncthreads();
    float d0 = v0 - mu, d1 = v1 - mu;
    sm[t] = d0 * d0 + d1 * d1; __syncthreads();
    for (int s = 128; s > 0; s >>= 1) { if (t < s) sm[t] += sm[t + s]; __syncthreads(); }
    float rs = rsqrtf(sm[0] * (1.f / DIM) + EPSLN); __syncthreads();
    yr[t]       = __float2half(d0 * rs * g[t]       + b[t]);
    yr[t + 256] = __float2half(d1 * rs * g[t + 256] + b[t + 256]);
}

__global__ void landmark_k(const __half* __restrict__ qkv,
                           __half* __restrict__ ql, __half* __restrict__ kl)
{
    int idx = blockIdx.x * 256 + threadIdx.x;
    int d = idx & 63, m = (idx >> 6) & 255, h = idx >> 14;
    int off = (blockIdx.y == 0) ? 0 : DIM;
    float s = 0.f;
    const __half* src = qkv + off + h * DH + d;
#pragma unroll
    for (int j = 0; j < 33; j++)
        s += __half2float(src[(long long)(m * 33 + j) * 1536]);
    __half* dst = (blockIdx.y == 0) ? ql : kl;
    dst[h * (MLM * DH) + m * DH + d] = __float2half(s * (1.f / 33.f));
}

__global__ void pinv_init_k(const float* __restrict__ A2, float* __restrict__ Z)
{
    if (blockIdx.x == 0 && threadIdx.x == 0) g_bar_cnt = 0;
    int h = blockIdx.x;
    const float* A = A2 + (long long)h * MLM * MLM;
    float* Zh = Z + (long long)h * MLM * MLM;
    int t = threadIdx.x;
    float rs = 0.f, cs = 0.f;
    for (int j = 0; j < MLM; j++) {
        rs += fabsf(A[t * MLM + j]);
        cs += fabsf(A[j * MLM + t]);
    }
    __shared__ float s1[256], s2[256];
    s1[t] = rs; s2[t] = cs; __syncthreads();
    for (int s = 128; s > 0; s >>= 1) {
        if (t < s) { s1[t] = fmaxf(s1[t], s1[t + s]); s2[t] = fmaxf(s2[t], s2[t + s]); }
        __syncthreads();
    }
    float scale = 1.f / (s1[0] * s2[0]);
    __syncthreads();
    for (int j = 0; j < MLM; j++)
        Zh[t * MLM + j] = A[j * MLM + t] * scale;
}

// tiled depthwise seq-conv; WRITES (=) the attn buffer
__global__ void __launch_bounds__(256)
conv1d_t_k(__half* __restrict__ attn, const __half* __restrict__ qkv,
           const float* __restrict__ w)
{
    __shared__ float sv[160 * 64];
    __shared__ float sw[33];
    const int t0 = blockIdx.x * 128;
    const int h = blockIdx.y;
    const int tid = threadIdx.x;
    if (tid < 33) sw[tid] = w[h * 33 + tid];
    for (int i = tid; i < 160 * 64; i += 256) {
        int chL = i & 63, p = i >> 6;
        int tok = t0 + p - 16;
        float v = 0.f;
        if (tok >= 0 && tok < NP)
            v = __half2float(qkv[(long long)tok * 1536 + 1024 + h * 64 + chL]);
        sv[p * 64 + chL] = v;
    }
    __syncthreads();
    const int chL = tid & 63, lane = tid >> 6;
    for (int p = lane; p < 128; p += 4) {
        float acc = 0.f;
#pragma unroll
        for (int t = 0; t < 33; t++)
            acc += sw[t] * sv[(p + t) * 64 + chL];
        attn[(long long)(t0 + p) * DIM + h * 64 + chL] = __float2half(acc);
    }
}

__global__ void seed_k(float* __restrict__ hA, const float* __restrict__ cls)
{
    int idx = blockIdx.x * 256 + threadIdx.x;
    if (idx < DIM) hA[idx] = cls[idx];
    int j = idx - DIM;
    if (j >= 0 && j < 89 * DIM) {
        int r = j >> 9, c = j & 511;
        hA[(long long)(1 + 8192 + r) * DIM + c] = hA[(long long)(1 + r) * DIM + c];
    }
}

// tiled PPEG (fp32)
__global__ void __launch_bounds__(256)
ppeg_t_k(const float* __restrict__ hA, float* __restrict__ h2,
         const float* __restrict__ w7, const float* __restrict__ b7,
         const float* __restrict__ w5, const float* __restrict__ b5,
         const float* __restrict__ w3, const float* __restrict__ b3)
{
    extern __shared__ float psm[];
    float* sf = psm;
    float* wc = psm + 14 * 38 * 32;
    float* bs = wc + 49 * 32;

    const int c0 = blockIdx.x * 32;
    const int r0 = blockIdx.y * 8;
    const int ch0 = blockIdx.z * 32;
    const int tid = threadIdx.x;

    for (int i = tid; i < 49 * 32; i += 256) {
        int tap = i >> 5, chL = i & 31;
        int u = tap / 7 - 3, v = tap % 7 - 3;
        int ch = ch0 + chL;
        float wv = w7[ch * 49 + tap];
        if (u >= -2 && u <= 2 && v >= -2 && v <= 2) wv += w5[ch * 25 + (u + 2) * 5 + (v + 2)];
        if (u >= -1 && u <= 1 && v >= -1 && v <= 1) wv += w3[ch * 9 + (u + 1) * 3 + (v + 1)];
        wc[tap * 32 + chL] = wv;
    }
    if (tid < 32) bs[tid] = b7[ch0 + tid] + b5[ch0 + tid] + b3[ch0 + tid];

    for (int i = tid; i < 14 * 38 * 32; i += 256) {
        int chL = i & 31;
        int p = i >> 5;
        int pc = p % 38, pr = p / 38;
        int rr = r0 + pr - 3, cc = c0 + pc - 3;
        float v = 0.f;
        if (rr >= 0 && rr < HSIZE && cc >= 0 && cc < HSIZE)
            v = hA[(long long)(1 + rr * HSIZE + cc) * DIM + ch0 + chL];
        sf[p * 32 + chL] = v;
    }
    __syncthreads();

    const int chL = tid & 31, lane = tid >> 5;
    for (int p = lane; p < 8 * 32; p += 8) {
        int pr = p >> 5, pc = p & 31;
        int rr = r0 + pr, cc = c0 + pc;
        if (rr >= HSIZE || cc >= HSIZE) continue;
        float acc = sf[((pr + 3) * 38 + pc + 3) * 32 + chL] + bs[chL];
#pragma unroll
        for (int u = 0; u < 7; u++)
#pragma unroll
            for (int v = 0; v < 7; v++)
                acc += wc[(u * 7 + v) * 32 + chL] * sf[((pr + u) * 38 + pc + v) * 32 + chL];
        h2[(long long)(1 + rr * HSIZE + cc) * DIM + ch0 + chL] = acc;
    }
}

__global__ void copy_row0_k(float* __restrict__ h2, const float* __restrict__ hA)
{
    h2[threadIdx.x] = hA[threadIdx.x];
}

__global__ void final_k(const float* __restrict__ h, const float* __restrict__ g,
                        const float* __restrict__ b, const float* __restrict__ w,
                        const float* __restrict__ bias, float* __restrict__ out,
                        int out_size)
{
    int t = threadIdx.x;
    __shared__ float sm[512];
    float v = h[t];
    sm[t] = v; __syncthreads();
    for (int s = 256; s > 0; s >>= 1) { if (t < s) sm[t] += sm[t + s]; __syncthreads(); }
    float mu = sm[0] * (1.f / DIM); __syncthreads();
    float d = v - mu;
    sm[t] = d * d; __syncthreads();
    for (int s = 256; s > 0; s >>= 1) { if (t < s) sm[t] += sm[t + s]; __syncthreads(); }
    float rs = rsqrtf(sm[0] * (1.f / DIM) + EPSLN); __syncthreads();
    float e = d * rs * g[t] + b[t];
    if (5 + t < out_size) out[5 + t] = e;
    sm[t] = e * w[t * 2]; __syncthreads();
    for (int s = 256; s > 0; s >>= 1) { if (t < s) sm[t] += sm[t + s]; __syncthreads(); }
    float l0 = sm[0] + bias[0]; __syncthreads();
    sm[t] = e * w[t * 2 + 1]; __syncthreads();
    for (int s = 256; s > 0; s >>= 1) { if (t < s) sm[t] += sm[t + s]; __syncthreads(); }
    float l1 = sm[0] + bias[1]; __syncthreads();
    if (t == 0 && out_size >= 5) {
        out[0] = l0; out[1] = l1;
        float mx = fmaxf(l0, l1);
        float e0 = expf(l0 - mx), e1 = expf(l1 - mx);
        float s = e0 + e1;
        out[2] = e0 / s; out[3] = e1 / s;
        out[4] = (l1 > l0) ? 1.f : 0.f;
    }
}

// ---------------- host orchestration ---------------------------------------

constexpr int HSMEM_BIG = 3 * (128 * 72 + 128 * 72) * 2;
constexpr int HSMEM_SML = 3 * (64 * 72 + 64 * 72) * 2;
constexpr int PPEG_SMEM = (14 * 38 * 32 + 49 * 32 + 32) * 4;

static void launch_hbig(const __half* A, const __half* B, void* C, bool out16,
                        int M, int N, int K, int lda, int ldb, int ldc,
                        long long sA, long long sB, long long sC, int batch,
                        float alpha, const float* bias, const float* res, int ldres,
                        int zrows, int flags)
{
    dim3 grid(N / 128, (M + 127) / 128, batch);
    if (out16)
        gemm_hc<128, 128, 64, 2, 4, true, 256, 2><<<grid, 256, HSMEM_BIG>>>(
            A, B, C, M, K, lda, ldb, ldc, sA, sB, sC, alpha, bias, res, ldres, zrows, flags);
    else
        gemm_hc<128, 128, 64, 2, 4, false, 256, 2><<<grid, 256, HSMEM_BIG>>>(
            A, B, C, M, K, lda, ldb, ldc, sA, sB, sC, alpha, bias, res, ldres, zrows, flags);
}

static void run_attn_layer(float* base, __half* hb, float* hbuf,
                           const float* lng, const float* lnb,
                           const __half* wqkvT, const __half* woutT,
                           const float* outb, const float* convw,
                           cudaStream_t s2, cudaEvent_t eFork,
                           cudaEvent_t eA3v, cudaEvent_t eConv)
{
    __half* xln16  = hb + HOFF_XLN;
    __half* qkv16  = hb + HOFF_QKV;
    __half* ql16   = hb + HOFF_QL;
    __half* kl16   = hb + HOFF_KL;
    __half* W216   = hb + HOFF_W2;
    __half* attn16 = hb + HOFF_ATTN;

    float* Opar = base + OFF_S1;
    float* mpar = base + OFF_S3;
    float* lpar = base + OFF_S3 + 32768;
    float* a2   = base + OFF_A2;
    float* Zb   = base + OFF_Z;
    float* a3v  = base + OFF_A3V;
    float* W2   = base + OFF_W2;

    const long long sA2 = (long long)MLM * MLM;
    const long long sLM = (long long)MLM * DH;

    ln_k<<<NTOK, 256>>>(hbuf, xln16, lng, lnb);

    launch_hbig(xln16, wqkvT, qkv16, true, NP, 1536, DIM, DIM, DIM, 1536,
                0, 0, 0, 1, 1.f, nullptr, nullptr, 0, PADR, 0);

    landmark_k<<<dim3(512, 2), 256>>>(qkv16, ql16, kl16);

    // fork: side stream handles flash_split + fcomb + conv1d
    cudaEventRecord(eFork, 0);
    cudaStreamWaitEvent(s2, eFork, 0);

    flash_h<true><<<dim3(4, NSL, HEADS), 128, 0, s2>>>(
        ql16, DH, sLM,
        qkv16 + DIM, 1536, DH,
        qkv16 + 2 * DIM, 1536, DH,
        KPS / 64, KPS,
        nullptr, 0, 0,
        Opar, mpar, lpar, NSL, 4, 0);
    fcomb_k<<<(HEADS * (int)sLM) / 256, 256, 0, s2>>>(Opar, mpar, lpar, a3v);
    cudaEventRecord(eA3v, s2);

    conv1d_t_k<<<dim3(NP / 128, HEADS), 256, 0, s2>>>(attn16, qkv16, convw);
    cudaEventRecord(eConv, s2);

    // main stream: a2 -> softmax -> pinv chain (independent of side branch)
    {
        dim3 grid(MLM / 64, MLM / 64, HEADS);
        gemm_hc<64, 64, 64, 2, 2, false, 128, 4><<<grid, 128, HSMEM_SML>>>(
            ql16, kl16, a2, MLM, DH, DH, DH, MLM,
            sLM, sLM, sA2, SCALE_Q, nullptr, nullptr, 0, 0, 0);
    }
    softmax256_k<<<(HEADS * MLM) / 8, 256>>>(a2);
    pinv_init_k<<<HEADS, 256>>>(a2, Zb);
    pinv_fused_k<<<128, 128>>>(base);

    // join: W2 needs a3v
    cudaStreamWaitEvent(0, eA3v, 0);
    w2_k<<<32, 128>>>(base);
    cvt_k<<<(HEADS * (int)sLM) / 256, 256>>>(W216, W2, HEADS * (int)sLM);

    // join: flash_ns accumulates onto conv output
    cudaStreamWaitEvent(0, eConv, 0);
    flash_h<false><<<dim3(NP / 64, 1, HEADS), 128>>>(
        qkv16, 1536, DH,
        kl16, DH, sLM,
        W216, DH, sLM,
        MLM / 64, MLM,
        attn16, DIM, DH,
        nullptr, nullptr, nullptr, 1, NP / 64, 1);

    launch_hbig(attn16 + (long long)PADR * DIM, woutT, hbuf, false,
                NTOK, DIM, DIM, DIM, DIM, DIM,
                0, 0, 0, 1, 1.f, outb, hbuf, DIM, 0, 0);
}

extern "C" void kernel_launch(void* const* d_in, const int* in_sizes, int n_in,
                              void* d_out, int out_size)
{
    const float* x      = (const float*)d_in[0];
    const float* fc1_w  = (const float*)d_in[1];
    const float* fc1_b  = (const float*)d_in[2];
    const float* cls    = (const float*)d_in[3];
    const float* ln1_g  = (const float*)d_in[4];
    const float* ln1_b  = (const float*)d_in[5];
    const float* qkv1_w = (const float*)d_in[6];
    const float* out1_w = (const float*)d_in[7];
    const float* out1_b = (const float*)d_in[8];
    const float* conv1w = (const float*)d_in[9];
    const float* ln2_g  = (const float*)d_in[10];
    const float* ln2_b  = (const float*)d_in[11];
    const float* qkv2_w = (const float*)d_in[12];
    const float* out2_w = (const float*)d_in[13];
    const float* out2_b = (const float*)d_in[14];
    const float* conv2w = (const float*)d_in[15];
    const float* pg7_w  = (const float*)d_in[16];
    const float* pg7_b  = (const float*)d_in[17];
    const float* pg5_w  = (const float*)d_in[18];
    const float* pg5_b  = (const float*)d_in[19];
    const float* pg3_w  = (const float*)d_in[20];
    const float* pg3_b  = (const float*)d_in[21];
    const float* norm_g = (const float*)d_in[22];
    const float* norm_b = (const float*)d_in[23];
    const float* fc2_w  = (const float*)d_in[24];
    const float* fc2_b  = (const float*)d_in[25];

    cudaFuncSetAttribute((const void*)gemm_hc<128, 128, 64, 2, 4, true, 256, 2>,
                         cudaFuncAttributeMaxDynamicSharedMemorySize, HSMEM_BIG);
    cudaFuncSetAttribute((const void*)gemm_hc<128, 128, 64, 2, 4, false, 256, 2>,
                         cudaFuncAttributeMaxDynamicSharedMemorySize, HSMEM_BIG);
    cudaFuncSetAttribute((const void*)gemm_hc<64, 64, 64, 2, 2, false, 128, 4>,
                         cudaFuncAttributeMaxDynamicSharedMemorySize, HSMEM_SML);
    cudaFuncSetAttribute(ppeg_t_k, cudaFuncAttributeMaxDynamicSharedMemorySize, PPEG_SMEM);

    // fork-join resources (host objects only; created per call, joined before return)
    cudaStream_t s2;
    cudaStreamCreateWithFlags(&s2, cudaStreamNonBlocking);
    cudaEvent_t ev[6];
    for (int i = 0; i < 6; i++) cudaEventCreateWithFlags(&ev[i], cudaEventDisableTiming);

    float* base = nullptr;
    cudaGetSymbolAddress((void**)&base, g_scratch);
    __half* hb = nullptr;
    cudaGetSymbolAddress((void**)&hb, g_hscr);

    float* hA = base + OFF_HA;
    float* h2 = base + OFF_H2;

    cvt_k<<<8388608 / 256, 256>>>(hb + HOFF_X, x, 8388608);
    cvtT_k<<<(524288 + 255) / 256, 256>>>(hb + HOFF_WF, fc1_w, 1024, 512);
    cvtT_k<<<(786432 + 255) / 256, 256>>>(hb + HOFF_WQ1, qkv1_w, 512, 1536);
    cvtT_k<<<(786432 + 255) / 256, 256>>>(hb + HOFF_WQ2, qkv2_w, 512, 1536);
    cvtT_k<<<(262144 + 255) / 256, 256>>>(hb + HOFF_WO1, out1_w, 512, 512);
    cvtT_k<<<(262144 + 255) / 256, 256>>>(hb + HOFF_WO2, out2_w, 512, 512);

    launch_hbig(hb + HOFF_X, hb + HOFF_WF, hA + DIM, false,
                8192, DIM, 1024, 1024, 1024, DIM,
                0, 0, 0, 1, 1.f, fc1_b, nullptr, 0, 0, F_RELU);
    seed_k<<<(90 * DIM) / 256, 256>>>(hA, cls);

    run_attn_layer(base, hb, hA, ln1_g, ln1_b, hb + HOFF_WQ1, hb + HOFF_WO1,
                   out1_b, conv1w, s2, ev[0], ev[1], ev[2]);

    ppeg_t_k<<<dim3(3, 12, 16), 256, PPEG_SMEM>>>(hA, h2, pg7_w, pg7_b, pg5_w, pg5_b, pg3_w, pg3_b);
    copy_row0_k<<<1, DIM>>>(h2, hA);

    run_attn_layer(base, hb, h2, ln2_g, ln2_b, hb + HOFF_WQ2, hb + HOFF_WO2,
                   out2_b, conv2w, s2, ev[3], ev[4], ev[5]);

    final_k<<<1, DIM>>>(h2, norm_g, norm_b, fc2_w, fc2_b, (float*)d_out, out_size);
}